// round 3
// baseline (speedup 1.0000x reference)
#include <cuda_runtime.h>
#include <math.h>

// ---------------------------------------------------------------------------
// Problem constants
// ---------------------------------------------------------------------------
#define BB    2
#define SS    2048
#define DM    1024
#define HH    16
#define DHD   64
#define MTOK  (BB*SS)          // 4096 token rows
#define DFF   4096
#define NEGBIG (-1000000000.0f)

// ---------------------------------------------------------------------------
// Scratch (static device globals; no allocations allowed)
// ---------------------------------------------------------------------------
__device__ float g_X  [MTOK*DM];   // LN outputs (reused 3x)
__device__ float g_Q  [MTOK*DM];
__device__ float g_K  [MTOK*DM];
__device__ float g_V  [MTOK*DM];
__device__ float g_ATT[MTOK*DM];   // attention context
__device__ float g_H  [MTOK*DM];   // residual stream
__device__ float g_HID[MTOK*DFF];  // MLP hidden (64 MB)

// ---------------------------------------------------------------------------
// Block reduction for (sum, sumsq), blockDim.x == 256
// ---------------------------------------------------------------------------
__device__ __forceinline__ void block_reduce_2(float& s, float& q) {
    __shared__ float sh_s[8], sh_q[8];
    int lane = threadIdx.x & 31, w = threadIdx.x >> 5;
#pragma unroll
    for (int o = 16; o > 0; o >>= 1) {
        s += __shfl_down_sync(0xffffffffu, s, o);
        q += __shfl_down_sync(0xffffffffu, q, o);
    }
    if (lane == 0) { sh_s[w] = s; sh_q[w] = q; }
    __syncthreads();
    if (w == 0) {
        s = (lane < 8) ? sh_s[lane] : 0.f;
        q = (lane < 8) ? sh_q[lane] : 0.f;
#pragma unroll
        for (int o = 4; o > 0; o >>= 1) {
            s += __shfl_down_sync(0xffffffffu, s, o);
            q += __shfl_down_sync(0xffffffffu, q, o);
        }
        if (lane == 0) { sh_s[0] = s; sh_q[0] = q; }
    }
    __syncthreads();
    s = sh_s[0]; q = sh_q[0];
}

// ---------------------------------------------------------------------------
// Embedding gather + positional + LayerNorm (one block per token row)
// ---------------------------------------------------------------------------
__global__ void embed_ln_kernel(const int* __restrict__ tgt_ids,
                                const float* __restrict__ tok_emb,
                                const float* __restrict__ pos_emb,
                                const float* __restrict__ gam,
                                const float* __restrict__ bet,
                                float* __restrict__ out) {
    int row = blockIdx.x;
    int s   = row & (SS - 1);
    int tok = tgt_ids[row];
    const float* te = tok_emb + (size_t)tok * DM;
    const float* pe = pos_emb + (size_t)s   * DM;
    float v[4]; float sum = 0.f, sq = 0.f;
#pragma unroll
    for (int i = 0; i < 4; i++) {
        int c = threadIdx.x + i * 256;
        float x = te[c] + pe[c];
        v[i] = x; sum += x; sq += x * x;
    }
    block_reduce_2(sum, sq);
    float mu  = sum * (1.f / DM);
    float var = sq * (1.f / DM) - mu * mu;
    float rs  = rsqrtf(var + 1e-5f);
    float* o = out + (size_t)row * DM;
#pragma unroll
    for (int i = 0; i < 4; i++) {
        int c = threadIdx.x + i * 256;
        o[c] = (v[i] - mu) * rs * gam[c] + bet[c];
    }
}

// ---------------------------------------------------------------------------
// LayerNorm (one block per row)
// ---------------------------------------------------------------------------
__global__ void ln_kernel(const float* __restrict__ in,
                          const float* __restrict__ gam,
                          const float* __restrict__ bet,
                          float* __restrict__ out) {
    int row = blockIdx.x;
    const float* ip = in + (size_t)row * DM;
    float v[4]; float sum = 0.f, sq = 0.f;
#pragma unroll
    for (int i = 0; i < 4; i++) {
        int c = threadIdx.x + i * 256;
        float x = ip[c];
        v[i] = x; sum += x; sq += x * x;
    }
    block_reduce_2(sum, sq);
    float mu  = sum * (1.f / DM);
    float var = sq * (1.f / DM) - mu * mu;
    float rs  = rsqrtf(var + 1e-5f);
    float* o = out + (size_t)row * DM;
#pragma unroll
    for (int i = 0; i < 4; i++) {
        int c = threadIdx.x + i * 256;
        o[c] = (v[i] - mu) * rs * gam[c] + bet[c];
    }
}

// ---------------------------------------------------------------------------
// SGEMM: C[M,N] = A[M,K] @ W[K,N] + bias (+ res) (GELU optional)
// 128x128 block tile, BK=8, 256 threads, 8x8 micro tile. Exact fp32.
// ---------------------------------------------------------------------------
__global__ __launch_bounds__(256) void gemm_kernel(
    const float* __restrict__ A, const float* __restrict__ W,
    const float* __restrict__ bias, const float* __restrict__ res,
    float* __restrict__ C, int M, int N, int K, int gelu) {
    __shared__ float As[8][128];
    __shared__ float Bs[8][128];
    int tid = threadIdx.x;
    int bm = blockIdx.y * 128, bn = blockIdx.x * 128;
    int tx = tid & 15, ty = tid >> 4;

    float acc[8][8];
#pragma unroll
    for (int i = 0; i < 8; i++)
#pragma unroll
        for (int j = 0; j < 8; j++) acc[i][j] = 0.f;

    int am  = tid >> 1;          // 0..127  (row within tile)
    int ak  = (tid & 1) * 4;     // 0 or 4  (k within tile)
    int bk  = tid >> 5;          // 0..7
    int bn4 = (tid & 31) * 4;    // 0..124

    const float* Aptr = A + (size_t)(bm + am) * K + ak;
    const float* Wptr = W + (size_t)bk * N + bn + bn4;

    for (int k0 = 0; k0 < K; k0 += 8) {
        float4 av = *(const float4*)(Aptr + k0);
        float4 bv = *(const float4*)(Wptr + (size_t)k0 * N);
        As[ak + 0][am] = av.x;
        As[ak + 1][am] = av.y;
        As[ak + 2][am] = av.z;
        As[ak + 3][am] = av.w;
        *(float4*)&Bs[bk][bn4] = bv;
        __syncthreads();
#pragma unroll
        for (int kk = 0; kk < 8; kk++) {
            float a[8], b[8];
            *(float4*)&a[0] = *(const float4*)&As[kk][ty * 8];
            *(float4*)&a[4] = *(const float4*)&As[kk][ty * 8 + 4];
            *(float4*)&b[0] = *(const float4*)&Bs[kk][tx * 8];
            *(float4*)&b[4] = *(const float4*)&Bs[kk][tx * 8 + 4];
#pragma unroll
            for (int i = 0; i < 8; i++)
#pragma unroll
                for (int j = 0; j < 8; j++) acc[i][j] += a[i] * b[j];
        }
        __syncthreads();
    }

#pragma unroll
    for (int i = 0; i < 8; i++) {
        int row = bm + ty * 8 + i;
#pragma unroll
        for (int j = 0; j < 8; j++) {
            int col = bn + tx * 8 + j;
            float v = acc[i][j] + bias[col];
            if (res) v += res[(size_t)row * N + col];
            if (gelu) v = 0.5f * v * (1.0f + erff(v * 0.70710678118654752f));
            C[(size_t)row * N + col] = v;
        }
    }
}

// ---------------------------------------------------------------------------
// Flash-style attention, fp32. One thread per query row.
// grid = (S/128, B*H), block = 128 threads.
// Q,K,V layouts: [B*S, H*DH] row-major, head h at columns h*DH..
// ---------------------------------------------------------------------------
__global__ __launch_bounds__(128) void attn_kernel(
    const float* __restrict__ Q, const float* __restrict__ Kb,
    const float* __restrict__ Vb, const int* __restrict__ ids,
    float* __restrict__ O, int causal) {
    __shared__ float Ks[64][68];
    __shared__ float Vs[64][68];
    __shared__ float pm[64];

    int b  = blockIdx.y >> 4;   // / HH
    int h  = blockIdx.y & 15;
    int q0 = blockIdx.x * 128;
    int tid = threadIdx.x;
    int qi = q0 + tid;

    const float* qp = Q + ((size_t)(b * SS + qi)) * DM + h * DHD;
    float q[64];
#pragma unroll
    for (int d4 = 0; d4 < 16; d4++) {
        float4 t = *(const float4*)(qp + d4 * 4);
        q[d4 * 4 + 0] = t.x; q[d4 * 4 + 1] = t.y;
        q[d4 * 4 + 2] = t.z; q[d4 * 4 + 3] = t.w;
    }

    float m = -1e30f, l = 0.f;
    float o[64];
#pragma unroll
    for (int d = 0; d < 64; d++) o[d] = 0.f;

    int ntiles = causal ? (2 * blockIdx.x + 2) : (SS / 64);
    for (int t0 = 0; t0 < ntiles; t0++) {
        int kbase = t0 * 64;
#pragma unroll
        for (int i = 0; i < 8; i++) {
            int e = tid + i * 128;
            int r = e >> 4, c = (e & 15) * 4;
            size_t goff = ((size_t)(b * SS + kbase + r)) * DM + h * DHD + c;
            *(float4*)&Ks[r][c] = *(const float4*)(Kb + goff);
            *(float4*)&Vs[r][c] = *(const float4*)(Vb + goff);
        }
        if (tid < 64)
            pm[tid] = (ids[b * SS + kbase + tid] == 0) ? NEGBIG : 0.f;
        __syncthreads();

        int kmax = 64;
        if (causal) {
            int rel = qi - kbase + 1;
            kmax = rel < 0 ? 0 : (rel < 64 ? rel : 64);
        }
        for (int k = 0; k < kmax; k++) {
            float s0 = 0.f, s1 = 0.f, s2 = 0.f, s3 = 0.f;
#pragma unroll
            for (int d = 0; d < 64; d += 4) {
                s0 += q[d + 0] * Ks[k][d + 0];
                s1 += q[d + 1] * Ks[k][d + 1];
                s2 += q[d + 2] * Ks[k][d + 2];
                s3 += q[d + 3] * Ks[k][d + 3];
            }
            float lg = ((s0 + s1) + (s2 + s3)) * 0.125f + pm[k];
            float p;
            if (lg <= m) {
                p = __expf(lg - m);
            } else {
                float r = __expf(m - lg);
                l *= r;
#pragma unroll
                for (int d = 0; d < 64; d++) o[d] *= r;
                m = lg; p = 1.f;
            }
            l += p;
#pragma unroll
            for (int d = 0; d < 64; d++) o[d] += p * Vs[k][d];
        }
        __syncthreads();
    }

    float inv = 1.f / l;
    float* op = O + ((size_t)(b * SS + qi)) * DM + h * DHD;
#pragma unroll
    for (int d = 0; d < 64; d += 4) {
        float4 t;
        t.x = o[d + 0] * inv; t.y = o[d + 1] * inv;
        t.z = o[d + 2] * inv; t.w = o[d + 3] * inv;
        *(float4*)(op + d) = t;
    }
}

// ---------------------------------------------------------------------------
// Launch
// ---------------------------------------------------------------------------
extern "C" void kernel_launch(void* const* d_in, const int* in_sizes, int n_in,
                              void* d_out, int out_size) {
    const float* input_embedding = (const float*)d_in[0];
    const int*   input_ids       = (const int*)d_in[1];
    const int*   target_ids      = (const int*)d_in[2];
    const float* tok_emb = (const float*)d_in[3];
    const float* pos_emb = (const float*)d_in[4];
    const float* ln1_g = (const float*)d_in[5];
    const float* ln1_b = (const float*)d_in[6];
    const float* q1_w = (const float*)d_in[7];
    const float* q1_b = (const float*)d_in[8];
    const float* k1_w = (const float*)d_in[9];
    const float* k1_b = (const float*)d_in[10];
    const float* v1_w = (const float*)d_in[11];
    const float* v1_b = (const float*)d_in[12];
    const float* out1_w = (const float*)d_in[13];
    const float* out1_b = (const float*)d_in[14];
    const float* ln2_g = (const float*)d_in[15];
    const float* ln2_b = (const float*)d_in[16];
    const float* q2_w = (const float*)d_in[17];
    const float* q2_b = (const float*)d_in[18];
    const float* k2_w = (const float*)d_in[19];
    const float* k2_b = (const float*)d_in[20];
    const float* v2_w = (const float*)d_in[21];
    const float* v2_b = (const float*)d_in[22];
    const float* out2_w = (const float*)d_in[23];
    const float* out2_b = (const float*)d_in[24];
    const float* ln3_g = (const float*)d_in[25];
    const float* ln3_b = (const float*)d_in[26];
    const float* mlp_w1 = (const float*)d_in[27];
    const float* mlp_b1 = (const float*)d_in[28];
    const float* mlp_w2 = (const float*)d_in[29];
    const float* mlp_b2 = (const float*)d_in[30];
    float* out = (float*)d_out;

    static float *X = nullptr, *Qb = nullptr, *Kb = nullptr, *Vb = nullptr,
                 *ATT = nullptr, *H = nullptr, *HID = nullptr;
    if (!X) {
        cudaGetSymbolAddress((void**)&X,   g_X);
        cudaGetSymbolAddress((void**)&Qb,  g_Q);
        cudaGetSymbolAddress((void**)&Kb,  g_K);
        cudaGetSymbolAddress((void**)&Vb,  g_V);
        cudaGetSymbolAddress((void**)&ATT, g_ATT);
        cudaGetSymbolAddress((void**)&H,   g_H);
        cudaGetSymbolAddress((void**)&HID, g_HID);
    }

    dim3 gProj(DM / 128, MTOK / 128);     // (8, 32)
    dim3 gMlp1(DFF / 128, MTOK / 128);    // (32, 32)
    dim3 gAttn(SS / 128, BB * HH);        // (16, 32)

    // 1. embedding + LN1 -> X   (X = ln1 output = "x" in reference)
    embed_ln_kernel<<<MTOK, 256>>>(target_ids, tok_emb, pos_emb, ln1_g, ln1_b, X);
    // 2. self-attn QKV projections (from X)
    gemm_kernel<<<gProj, 256>>>(X, q1_w, q1_b, nullptr, Qb, MTOK, DM, DM, 0);
    gemm_kernel<<<gProj, 256>>>(X, k1_w, k1_b, nullptr, Kb, MTOK, DM, DM, 0);
    gemm_kernel<<<gProj, 256>>>(X, v1_w, v1_b, nullptr, Vb, MTOK, DM, DM, 0);
    // 3. causal self-attention (pad mask from target_ids)
    attn_kernel<<<gAttn, 128>>>(Qb, Kb, Vb, target_ids, ATT, 1);
    // 4. out projection + residual (X = ln1 out) -> H  (pre-LN2 "h")
    gemm_kernel<<<gProj, 256>>>(ATT, out1_w, out1_b, X, H, MTOK, DM, DM, 0);
    // 5. LN2 -> X   (X = ln2 output = reassigned "h" in reference)
    ln_kernel<<<MTOK, 256>>>(H, ln2_g, ln2_b, X);
    // 6. cross-attn projections (Q from LN2 out; K,V from raw encoder states)
    gemm_kernel<<<gProj, 256>>>(X, q2_w, q2_b, nullptr, Qb, MTOK, DM, DM, 0);
    gemm_kernel<<<gProj, 256>>>(input_embedding, k2_w, k2_b, nullptr, Kb, MTOK, DM, DM, 0);
    gemm_kernel<<<gProj, 256>>>(input_embedding, v2_w, v2_b, nullptr, Vb, MTOK, DM, DM, 0);
    // 7. cross-attention (no causal, pad mask from input_ids)
    attn_kernel<<<gAttn, 128>>>(Qb, Kb, Vb, input_ids, ATT, 0);
    // 8. out projection + residual (X = LN2 OUTPUT, per reference!) -> H ("r")
    gemm_kernel<<<gProj, 256>>>(ATT, out2_w, out2_b, X, H, MTOK, DM, DM, 0);
    // 9. LN3 -> X  ("z")
    ln_kernel<<<MTOK, 256>>>(H, ln3_g, ln3_b, X);
    // 10. MLP up + GELU -> HID
    gemm_kernel<<<gMlp1, 256>>>(X, mlp_w1, mlp_b1, nullptr, HID, MTOK, DFF, DM, 1);
    // 11. MLP down + bias + residual (H = "r") -> out
    gemm_kernel<<<gProj, 256>>>(HID, mlp_w2, mlp_b2, H, out, MTOK, DM, DFF, 0);
}

// round 5
// speedup vs baseline: 1.3804x; 1.3804x over previous
#include <cuda_runtime.h>
#include <math.h>
#include <stdint.h>

// ---------------------------------------------------------------------------
// Problem constants
// ---------------------------------------------------------------------------
#define BB    2
#define SS    2048
#define DM    1024
#define HH    16
#define DHD   64
#define MTOK  (BB*SS)          // 4096 token rows
#define DFF   4096
#define NEGBIG (-1000000000.0f)

// ---------------------------------------------------------------------------
// Scratch (static device globals; no allocations allowed)
// ---------------------------------------------------------------------------
__device__ float g_X  [MTOK*DM];
__device__ float g_Q  [MTOK*DM];
__device__ float g_K  [MTOK*DM];
__device__ float g_V  [MTOK*DM];
__device__ float g_ATT[MTOK*DM];
__device__ float g_H  [MTOK*DM];
__device__ float g_HID[(size_t)MTOK*DFF];
__device__ float g_WT [16*1024*1024];   // transposed weights, K-major [N,K]

// ---------------------------------------------------------------------------
// Helpers
// ---------------------------------------------------------------------------
__device__ __forceinline__ float tf32r(float x) {
    float y;
    asm("cvt.rna.tf32.f32 %0, %1;" : "=f"(y) : "f"(x));
    return y;
}

__device__ __forceinline__ void mma_tf32(float* d, const uint32_t* a,
                                         const uint32_t* b) {
    asm volatile(
        "mma.sync.aligned.m16n8k8.row.col.f32.tf32.tf32.f32 "
        "{%0,%1,%2,%3}, {%4,%5,%6,%7}, {%8,%9}, {%0,%1,%2,%3};"
        : "+f"(d[0]), "+f"(d[1]), "+f"(d[2]), "+f"(d[3])
        : "r"(a[0]), "r"(a[1]), "r"(a[2]), "r"(a[3]), "r"(b[0]), "r"(b[1]));
}

// ---------------------------------------------------------------------------
// Block reduction for (sum, sumsq), blockDim.x == 256
// ---------------------------------------------------------------------------
__device__ __forceinline__ void block_reduce_2(float& s, float& q) {
    __shared__ float sh_s[8], sh_q[8];
    int lane = threadIdx.x & 31, w = threadIdx.x >> 5;
#pragma unroll
    for (int o = 16; o > 0; o >>= 1) {
        s += __shfl_down_sync(0xffffffffu, s, o);
        q += __shfl_down_sync(0xffffffffu, q, o);
    }
    if (lane == 0) { sh_s[w] = s; sh_q[w] = q; }
    __syncthreads();
    if (w == 0) {
        s = (lane < 8) ? sh_s[lane] : 0.f;
        q = (lane < 8) ? sh_q[lane] : 0.f;
#pragma unroll
        for (int o = 4; o > 0; o >>= 1) {
            s += __shfl_down_sync(0xffffffffu, s, o);
            q += __shfl_down_sync(0xffffffffu, q, o);
        }
        if (lane == 0) { sh_s[0] = s; sh_q[0] = q; }
    }
    __syncthreads();
    s = sh_s[0]; q = sh_q[0];
}

// ---------------------------------------------------------------------------
// Embedding gather + positional + LayerNorm (one block per token row)
// ---------------------------------------------------------------------------
__global__ void embed_ln_kernel(const int* __restrict__ tgt_ids,
                                const float* __restrict__ tok_emb,
                                const float* __restrict__ pos_emb,
                                const float* __restrict__ gam,
                                const float* __restrict__ bet,
                                float* __restrict__ out) {
    int row = blockIdx.x;
    int s   = row & (SS - 1);
    int tok = tgt_ids[row];
    const float* te = tok_emb + (size_t)tok * DM;
    const float* pe = pos_emb + (size_t)s   * DM;
    float v[4]; float sum = 0.f, sq = 0.f;
#pragma unroll
    for (int i = 0; i < 4; i++) {
        int c = threadIdx.x + i * 256;
        float x = te[c] + pe[c];
        v[i] = x; sum += x; sq += x * x;
    }
    block_reduce_2(sum, sq);
    float mu  = sum * (1.f / DM);
    float var = sq * (1.f / DM) - mu * mu;
    float rs  = rsqrtf(var + 1e-5f);
    float* o = out + (size_t)row * DM;
#pragma unroll
    for (int i = 0; i < 4; i++) {
        int c = threadIdx.x + i * 256;
        o[c] = (v[i] - mu) * rs * gam[c] + bet[c];
    }
}

// ---------------------------------------------------------------------------
// LayerNorm (one block per row)
// ---------------------------------------------------------------------------
__global__ void ln_kernel(const float* __restrict__ in,
                          const float* __restrict__ gam,
                          const float* __restrict__ bet,
                          float* __restrict__ out) {
    int row = blockIdx.x;
    const float* ip = in + (size_t)row * DM;
    float v[4]; float sum = 0.f, sq = 0.f;
#pragma unroll
    for (int i = 0; i < 4; i++) {
        int c = threadIdx.x + i * 256;
        float x = ip[c];
        v[i] = x; sum += x; sq += x * x;
    }
    block_reduce_2(sum, sq);
    float mu  = sum * (1.f / DM);
    float var = sq * (1.f / DM) - mu * mu;
    float rs  = rsqrtf(var + 1e-5f);
    float* o = out + (size_t)row * DM;
#pragma unroll
    for (int i = 0; i < 4; i++) {
        int c = threadIdx.x + i * 256;
        o[c] = (v[i] - mu) * rs * gam[c] + bet[c];
    }
}

// ---------------------------------------------------------------------------
// Transpose: out[C,R] = in[R,C]^T  (32x32 tiles, block 32x8)
// ---------------------------------------------------------------------------
__global__ void transpose_kernel(const float* __restrict__ in,
                                 float* __restrict__ out, int R, int C) {
    __shared__ float tile[32][33];
    int cx = blockIdx.x * 32, ry = blockIdx.y * 32;
    int tx = threadIdx.x, ty = threadIdx.y;
#pragma unroll
    for (int i = 0; i < 32; i += 8)
        tile[ty + i][tx] = in[(size_t)(ry + ty + i) * C + cx + tx];
    __syncthreads();
#pragma unroll
    for (int i = 0; i < 32; i += 8)
        out[(size_t)(cx + ty + i) * R + ry + tx] = tile[tx][ty + i];
}

// ---------------------------------------------------------------------------
// TF32 mma.sync GEMM: C[M,N] = A[M,K] @ BT[N,K]^T + bias (+res) (gelu opt)
// 128x128 block tile, BK=32, 256 threads (8 warps as 2m x 4n; warp = 64x32).
// Double-buffered dynamic smem, register-staged global prefetch.
// ---------------------------------------------------------------------------
#define BKT 32
#define SPAD 36
#define TILE_F (128 * SPAD)                   // floats per operand buffer
#define GEMM_SMEM_BYTES (4 * TILE_F * 4)      // 2 bufs x 2 operands

__global__ __launch_bounds__(256) void gemm_mma(
    const float* __restrict__ A, const float* __restrict__ BT,
    const float* __restrict__ bias, const float* __restrict__ res,
    float* __restrict__ C, int M, int N, int K, int gelu) {
    extern __shared__ float sm[];
    // layout: [buf][operand][128][SPAD]
    float* As[2] = { sm,              sm + 2 * TILE_F };
    float* Bs[2] = { sm + TILE_F,     sm + 3 * TILE_F };

    int tid  = threadIdx.x;
    int wid  = tid >> 5, lane = tid & 31;
    int gid  = lane >> 2, tig = lane & 3;
    int m_off = (wid >> 2) * 64;      // 2 warp rows
    int n_off = (wid & 3) * 32;       // 4 warp cols
    int bm = blockIdx.y * 128, bn = blockIdx.x * 128;

    float acc[4][4][4];
#pragma unroll
    for (int i = 0; i < 4; i++)
#pragma unroll
        for (int j = 0; j < 4; j++)
#pragma unroll
            for (int k = 0; k < 4; k++) acc[i][j][k] = 0.f;

    int lr  = tid >> 3;          // 0..31? -> tid>>3 in 0..31 for 256 threads... use idx loop
    (void)lr;

    float4 ar[4], br[4];
    const int T = K / BKT;

    // prefetch tile 0
#pragma unroll
    for (int i = 0; i < 4; i++) {
        int idx = tid + i * 256;
        int r = idx >> 3, c4 = idx & 7;
        ar[i] = *(const float4*)(A  + (size_t)(bm + r) * K + c4 * 4);
        br[i] = *(const float4*)(BT + (size_t)(bn + r) * K + c4 * 4);
    }
#pragma unroll
    for (int i = 0; i < 4; i++) {
        int idx = tid + i * 256;
        int r = idx >> 3, c4 = idx & 7;
        float* ap = As[0] + r * SPAD + c4 * 4;
        float* bp = Bs[0] + r * SPAD + c4 * 4;
        ap[0] = tf32r(ar[i].x); ap[1] = tf32r(ar[i].y);
        ap[2] = tf32r(ar[i].z); ap[3] = tf32r(ar[i].w);
        bp[0] = tf32r(br[i].x); bp[1] = tf32r(br[i].y);
        bp[2] = tf32r(br[i].z); bp[3] = tf32r(br[i].w);
    }
    __syncthreads();

    for (int t = 0; t < T; t++) {
        int cur = t & 1, nxt = cur ^ 1;
        if (t + 1 < T) {
            int k0 = (t + 1) * BKT;
#pragma unroll
            for (int i = 0; i < 4; i++) {
                int idx = tid + i * 256;
                int r = idx >> 3, c4 = idx & 7;
                ar[i] = *(const float4*)(A  + (size_t)(bm + r) * K + k0 + c4 * 4);
                br[i] = *(const float4*)(BT + (size_t)(bn + r) * K + k0 + c4 * 4);
            }
        }
        const float* Ac = As[cur];
        const float* Bc = Bs[cur];
#pragma unroll
        for (int ks = 0; ks < 4; ks++) {
            int k = ks * 8;
            uint32_t a[4][4], b[4][2];
#pragma unroll
            for (int mf = 0; mf < 4; mf++) {
                const float* p = Ac + (m_off + mf * 16 + gid) * SPAD + k + tig;
                a[mf][0] = __float_as_uint(p[0]);
                a[mf][1] = __float_as_uint(p[8 * SPAD]);
                a[mf][2] = __float_as_uint(p[4]);
                a[mf][3] = __float_as_uint(p[8 * SPAD + 4]);
            }
#pragma unroll
            for (int nf = 0; nf < 4; nf++) {
                const float* p = Bc + (n_off + nf * 8 + gid) * SPAD + k + tig;
                b[nf][0] = __float_as_uint(p[0]);
                b[nf][1] = __float_as_uint(p[4]);
            }
#pragma unroll
            for (int mf = 0; mf < 4; mf++)
#pragma unroll
                for (int nf = 0; nf < 4; nf++)
                    mma_tf32(acc[mf][nf], a[mf], b[nf]);
        }
        if (t + 1 < T) {
#pragma unroll
            for (int i = 0; i < 4; i++) {
                int idx = tid + i * 256;
                int r = idx >> 3, c4 = idx & 7;
                float* ap = As[nxt] + r * SPAD + c4 * 4;
                float* bp = Bs[nxt] + r * SPAD + c4 * 4;
                ap[0] = tf32r(ar[i].x); ap[1] = tf32r(ar[i].y);
                ap[2] = tf32r(ar[i].z); ap[3] = tf32r(ar[i].w);
                bp[0] = tf32r(br[i].x); bp[1] = tf32r(br[i].y);
                bp[2] = tf32r(br[i].z); bp[3] = tf32r(br[i].w);
            }
        }
        __syncthreads();
    }

    // epilogue: C fragment layout c0=[gid][2t], c1=[gid][2t+1], c2=[gid+8][..]
#pragma unroll
    for (int mf = 0; mf < 4; mf++) {
        int row0 = bm + m_off + mf * 16 + gid;
        int row1 = row0 + 8;
#pragma unroll
        for (int nf = 0; nf < 4; nf++) {
            int col = bn + n_off + nf * 8 + 2 * tig;
            float b0 = bias[col], b1 = bias[col + 1];
            float v0 = acc[mf][nf][0] + b0;
            float v1 = acc[mf][nf][1] + b1;
            float v2 = acc[mf][nf][2] + b0;
            float v3 = acc[mf][nf][3] + b1;
            if (res) {
                v0 += res[(size_t)row0 * N + col];
                v1 += res[(size_t)row0 * N + col + 1];
                v2 += res[(size_t)row1 * N + col];
                v3 += res[(size_t)row1 * N + col + 1];
            }
            if (gelu) {
                v0 = 0.5f * v0 * (1.0f + erff(v0 * 0.70710678118654752f));
                v1 = 0.5f * v1 * (1.0f + erff(v1 * 0.70710678118654752f));
                v2 = 0.5f * v2 * (1.0f + erff(v2 * 0.70710678118654752f));
                v3 = 0.5f * v3 * (1.0f + erff(v3 * 0.70710678118654752f));
            }
            float2 w0 = make_float2(v0, v1), w1 = make_float2(v2, v3);
            *(float2*)(C + (size_t)row0 * N + col) = w0;
            *(float2*)(C + (size_t)row1 * N + col) = w1;
        }
    }
}

// ---------------------------------------------------------------------------
// Flash-style attention, fp32. One thread per query row.
// grid = (S/128, B*H), block = 128 threads.
// ---------------------------------------------------------------------------
__global__ __launch_bounds__(128) void attn_kernel(
    const float* __restrict__ Q, const float* __restrict__ Kb,
    const float* __restrict__ Vb, const int* __restrict__ ids,
    float* __restrict__ O, int causal) {
    __shared__ float Ks[64][68];
    __shared__ float Vs[64][68];
    __shared__ float pm[64];

    int b  = blockIdx.y >> 4;
    int h  = blockIdx.y & 15;
    int q0 = blockIdx.x * 128;
    int tid = threadIdx.x;
    int qi = q0 + tid;

    const float* qp = Q + ((size_t)(b * SS + qi)) * DM + h * DHD;
    float q[64];
#pragma unroll
    for (int d4 = 0; d4 < 16; d4++) {
        float4 t = *(const float4*)(qp + d4 * 4);
        q[d4 * 4 + 0] = t.x; q[d4 * 4 + 1] = t.y;
        q[d4 * 4 + 2] = t.z; q[d4 * 4 + 3] = t.w;
    }

    float m = -1e30f, l = 0.f;
    float o[64];
#pragma unroll
    for (int d = 0; d < 64; d++) o[d] = 0.f;

    int ntiles = causal ? (2 * blockIdx.x + 2) : (SS / 64);
    for (int t0 = 0; t0 < ntiles; t0++) {
        int kbase = t0 * 64;
#pragma unroll
        for (int i = 0; i < 8; i++) {
            int e = tid + i * 128;
            int r = e >> 4, c = (e & 15) * 4;
            size_t goff = ((size_t)(b * SS + kbase + r)) * DM + h * DHD + c;
            *(float4*)&Ks[r][c] = *(const float4*)(Kb + goff);
            *(float4*)&Vs[r][c] = *(const float4*)(Vb + goff);
        }
        if (tid < 64)
            pm[tid] = (ids[b * SS + kbase + tid] == 0) ? NEGBIG : 0.f;
        __syncthreads();

        int kmax = 64;
        if (causal) {
            int rel = qi - kbase + 1;
            kmax = rel < 0 ? 0 : (rel < 64 ? rel : 64);
        }
        for (int k = 0; k < kmax; k++) {
            float s0 = 0.f, s1 = 0.f, s2 = 0.f, s3 = 0.f;
#pragma unroll
            for (int d = 0; d < 64; d += 4) {
                s0 += q[d + 0] * Ks[k][d + 0];
                s1 += q[d + 1] * Ks[k][d + 1];
                s2 += q[d + 2] * Ks[k][d + 2];
                s3 += q[d + 3] * Ks[k][d + 3];
            }
            float lg = ((s0 + s1) + (s2 + s3)) * 0.125f + pm[k];
            float p;
            if (lg <= m) {
                p = __expf(lg - m);
            } else {
                float r = __expf(m - lg);
                l *= r;
#pragma unroll
                for (int d = 0; d < 64; d++) o[d] *= r;
                m = lg; p = 1.f;
            }
            l += p;
#pragma unroll
            for (int d = 0; d < 64; d++) o[d] += p * Vs[k][d];
        }
        __syncthreads();
    }

    float inv = 1.f / l;
    float* op = O + ((size_t)(b * SS + qi)) * DM + h * DHD;
#pragma unroll
    for (int d = 0; d < 64; d += 4) {
        float4 t;
        t.x = o[d + 0] * inv; t.y = o[d + 1] * inv;
        t.z = o[d + 2] * inv; t.w = o[d + 3] * inv;
        *(float4*)(op + d) = t;
    }
}

// ---------------------------------------------------------------------------
// Launch
// ---------------------------------------------------------------------------
extern "C" void kernel_launch(void* const* d_in, const int* in_sizes, int n_in,
                              void* d_out, int out_size) {
    const float* input_embedding = (const float*)d_in[0];
    const int*   input_ids       = (const int*)d_in[1];
    const int*   target_ids      = (const int*)d_in[2];
    const float* tok_emb = (const float*)d_in[3];
    const float* pos_emb = (const float*)d_in[4];
    const float* ln1_g = (const float*)d_in[5];
    const float* ln1_b = (const float*)d_in[6];
    const float* q1_w = (const float*)d_in[7];
    const float* q1_b = (const float*)d_in[8];
    const float* k1_w = (const float*)d_in[9];
    const float* k1_b = (const float*)d_in[10];
    const float* v1_w = (const float*)d_in[11];
    const float* v1_b = (const float*)d_in[12];
    const float* out1_w = (const float*)d_in[13];
    const float* out1_b = (const float*)d_in[14];
    const float* ln2_g = (const float*)d_in[15];
    const float* ln2_b = (const float*)d_in[16];
    const float* q2_w = (const float*)d_in[17];
    const float* q2_b = (const float*)d_in[18];
    const float* k2_w = (const float*)d_in[19];
    const float* k2_b = (const float*)d_in[20];
    const float* v2_w = (const float*)d_in[21];
    const float* v2_b = (const float*)d_in[22];
    const float* out2_w = (const float*)d_in[23];
    const float* out2_b = (const float*)d_in[24];
    const float* ln3_g = (const float*)d_in[25];
    const float* ln3_b = (const float*)d_in[26];
    const float* mlp_w1 = (const float*)d_in[27];
    const float* mlp_b1 = (const float*)d_in[28];
    const float* mlp_w2 = (const float*)d_in[29];
    const float* mlp_b2 = (const float*)d_in[30];
    float* out = (float*)d_out;

    static float *X = nullptr, *Qb = nullptr, *Kb = nullptr, *Vb = nullptr,
                 *ATT = nullptr, *H = nullptr, *HID = nullptr, *WT = nullptr;
    static bool attr_done = false;
    if (!X) {
        cudaGetSymbolAddress((void**)&X,   g_X);
        cudaGetSymbolAddress((void**)&Qb,  g_Q);
        cudaGetSymbolAddress((void**)&Kb,  g_K);
        cudaGetSymbolAddress((void**)&Vb,  g_V);
        cudaGetSymbolAddress((void**)&ATT, g_ATT);
        cudaGetSymbolAddress((void**)&H,   g_H);
        cudaGetSymbolAddress((void**)&HID, g_HID);
        cudaGetSymbolAddress((void**)&WT,  g_WT);
    }
    if (!attr_done) {
        cudaFuncSetAttribute(gemm_mma, cudaFuncAttributeMaxDynamicSharedMemorySize,
                             GEMM_SMEM_BYTES);
        attr_done = true;
    }

    const size_t MW = 1024 * 1024;
    float* wt_q1 = WT + 0 * MW;
    float* wt_k1 = WT + 1 * MW;
    float* wt_v1 = WT + 2 * MW;
    float* wt_o1 = WT + 3 * MW;
    float* wt_q2 = WT + 4 * MW;
    float* wt_k2 = WT + 5 * MW;
    float* wt_v2 = WT + 6 * MW;
    float* wt_o2 = WT + 7 * MW;
    float* wt_m1 = WT + 8 * MW;    // [DFF, DM]
    float* wt_m2 = WT + 12 * MW;   // [DM, DFF]

    dim3 tb(32, 8);
    dim3 tg1(DM / 32, DM / 32);
    transpose_kernel<<<tg1, tb>>>(q1_w, wt_q1, DM, DM);
    transpose_kernel<<<tg1, tb>>>(k1_w, wt_k1, DM, DM);
    transpose_kernel<<<tg1, tb>>>(v1_w, wt_v1, DM, DM);
    transpose_kernel<<<tg1, tb>>>(out1_w, wt_o1, DM, DM);
    transpose_kernel<<<tg1, tb>>>(q2_w, wt_q2, DM, DM);
    transpose_kernel<<<tg1, tb>>>(k2_w, wt_k2, DM, DM);
    transpose_kernel<<<tg1, tb>>>(v2_w, wt_v2, DM, DM);
    transpose_kernel<<<tg1, tb>>>(out2_w, wt_o2, DM, DM);
    dim3 tgm1(DFF / 32, DM / 32);
    transpose_kernel<<<tgm1, tb>>>(mlp_w1, wt_m1, DM, DFF);
    dim3 tgm2(DM / 32, DFF / 32);
    transpose_kernel<<<tgm2, tb>>>(mlp_w2, wt_m2, DFF, DM);

    dim3 gProj(DM / 128, MTOK / 128);   // (8, 32)
    dim3 gMlp1(DFF / 128, MTOK / 128);  // (32, 32)
    dim3 gAttn(SS / 128, BB * HH);      // (16, 32)
    const int SB = GEMM_SMEM_BYTES;

    // 1. embedding + LN1 -> X
    embed_ln_kernel<<<MTOK, 256>>>(target_ids, tok_emb, pos_emb, ln1_g, ln1_b, X);
    // 2. self-attn QKV projections
    gemm_mma<<<gProj, 256, SB>>>(X, wt_q1, q1_b, nullptr, Qb, MTOK, DM, DM, 0);
    gemm_mma<<<gProj, 256, SB>>>(X, wt_k1, k1_b, nullptr, Kb, MTOK, DM, DM, 0);
    gemm_mma<<<gProj, 256, SB>>>(X, wt_v1, v1_b, nullptr, Vb, MTOK, DM, DM, 0);
    // 3. causal self-attention
    attn_kernel<<<gAttn, 128>>>(Qb, Kb, Vb, target_ids, ATT, 1);
    // 4. out projection + residual (X = LN1 out) -> H
    gemm_mma<<<gProj, 256, SB>>>(ATT, wt_o1, out1_b, X, H, MTOK, DM, DM, 0);
    // 5. LN2 -> X
    ln_kernel<<<MTOK, 256>>>(H, ln2_g, ln2_b, X);
    // 6. cross-attn projections
    gemm_mma<<<gProj, 256, SB>>>(X, wt_q2, q2_b, nullptr, Qb, MTOK, DM, DM, 0);
    gemm_mma<<<gProj, 256, SB>>>(input_embedding, wt_k2, k2_b, nullptr, Kb, MTOK, DM, DM, 0);
    gemm_mma<<<gProj, 256, SB>>>(input_embedding, wt_v2, v2_b, nullptr, Vb, MTOK, DM, DM, 0);
    // 7. cross-attention
    attn_kernel<<<gAttn, 128>>>(Qb, Kb, Vb, input_ids, ATT, 0);
    // 8. out projection + residual (X = LN2 out) -> H  ("r")
    gemm_mma<<<gProj, 256, SB>>>(ATT, wt_o2, out2_b, X, H, MTOK, DM, DM, 0);
    // 9. LN3 -> X
    ln_kernel<<<MTOK, 256>>>(H, ln3_g, ln3_b, X);
    // 10. MLP up + GELU -> HID
    gemm_mma<<<gMlp1, 256, SB>>>(X, wt_m1, mlp_b1, nullptr, HID, MTOK, DFF, DM, 1);
    // 11. MLP down + bias + residual (H) -> out
    gemm_mma<<<gProj, 256, SB>>>(HID, wt_m2, mlp_b2, H, out, MTOK, DM, DFF, 0);
}

// round 6
// speedup vs baseline: 2.2231x; 1.6105x over previous
#include <cuda_runtime.h>
#include <math.h>
#include <stdint.h>

// ---------------------------------------------------------------------------
// Problem constants
// ---------------------------------------------------------------------------
#define BB    2
#define SS    2048
#define DM    1024
#define HH    16
#define DHD   64
#define MTOK  (BB*SS)          // 4096 token rows
#define DFF   4096
#define NEGBIG (-1000000000.0f)

// ---------------------------------------------------------------------------
// Scratch (static device globals; no allocations allowed)
// ---------------------------------------------------------------------------
__device__ float g_X  [MTOK*DM];
__device__ float g_Q  [MTOK*DM];
__device__ float g_K  [MTOK*DM];
__device__ float g_V  [MTOK*DM];
__device__ float g_ATT[MTOK*DM];
__device__ float g_H  [MTOK*DM];
__device__ float g_HID[(size_t)MTOK*DFF];
__device__ float g_WT [16*1024*1024];   // transposed weights, K-major [N,K]

// ---------------------------------------------------------------------------
// Helpers
// ---------------------------------------------------------------------------
__device__ __forceinline__ float tf32r(float x) {
    float y;
    asm("cvt.rna.tf32.f32 %0, %1;" : "=f"(y) : "f"(x));
    return y;
}

__device__ __forceinline__ void mma_tf32(float* d, const uint32_t* a,
                                         const uint32_t* b) {
    asm volatile(
        "mma.sync.aligned.m16n8k8.row.col.f32.tf32.tf32.f32 "
        "{%0,%1,%2,%3}, {%4,%5,%6,%7}, {%8,%9}, {%0,%1,%2,%3};"
        : "+f"(d[0]), "+f"(d[1]), "+f"(d[2]), "+f"(d[3])
        : "r"(a[0]), "r"(a[1]), "r"(a[2]), "r"(a[3]), "r"(b[0]), "r"(b[1]));
}

// ---------------------------------------------------------------------------
// Block reduction for (sum, sumsq), blockDim.x == 256
// ---------------------------------------------------------------------------
__device__ __forceinline__ void block_reduce_2(float& s, float& q) {
    __shared__ float sh_s[8], sh_q[8];
    int lane = threadIdx.x & 31, w = threadIdx.x >> 5;
#pragma unroll
    for (int o = 16; o > 0; o >>= 1) {
        s += __shfl_down_sync(0xffffffffu, s, o);
        q += __shfl_down_sync(0xffffffffu, q, o);
    }
    if (lane == 0) { sh_s[w] = s; sh_q[w] = q; }
    __syncthreads();
    if (w == 0) {
        s = (lane < 8) ? sh_s[lane] : 0.f;
        q = (lane < 8) ? sh_q[lane] : 0.f;
#pragma unroll
        for (int o = 4; o > 0; o >>= 1) {
            s += __shfl_down_sync(0xffffffffu, s, o);
            q += __shfl_down_sync(0xffffffffu, q, o);
        }
        if (lane == 0) { sh_s[0] = s; sh_q[0] = q; }
    }
    __syncthreads();
    s = sh_s[0]; q = sh_q[0];
}

// ---------------------------------------------------------------------------
// Embedding gather + positional + LayerNorm (one block per token row)
// ---------------------------------------------------------------------------
__global__ void embed_ln_kernel(const int* __restrict__ tgt_ids,
                                const float* __restrict__ tok_emb,
                                const float* __restrict__ pos_emb,
                                const float* __restrict__ gam,
                                const float* __restrict__ bet,
                                float* __restrict__ out) {
    int row = blockIdx.x;
    int s   = row & (SS - 1);
    int tok = tgt_ids[row];
    const float* te = tok_emb + (size_t)tok * DM;
    const float* pe = pos_emb + (size_t)s   * DM;
    float v[4]; float sum = 0.f, sq = 0.f;
#pragma unroll
    for (int i = 0; i < 4; i++) {
        int c = threadIdx.x + i * 256;
        float x = te[c] + pe[c];
        v[i] = x; sum += x; sq += x * x;
    }
    block_reduce_2(sum, sq);
    float mu  = sum * (1.f / DM);
    float var = sq * (1.f / DM) - mu * mu;
    float rs  = rsqrtf(var + 1e-5f);
    float* o = out + (size_t)row * DM;
#pragma unroll
    for (int i = 0; i < 4; i++) {
        int c = threadIdx.x + i * 256;
        o[c] = (v[i] - mu) * rs * gam[c] + bet[c];
    }
}

// ---------------------------------------------------------------------------
// LayerNorm (one block per row)
// ---------------------------------------------------------------------------
__global__ void ln_kernel(const float* __restrict__ in,
                          const float* __restrict__ gam,
                          const float* __restrict__ bet,
                          float* __restrict__ out) {
    int row = blockIdx.x;
    const float* ip = in + (size_t)row * DM;
    float v[4]; float sum = 0.f, sq = 0.f;
#pragma unroll
    for (int i = 0; i < 4; i++) {
        int c = threadIdx.x + i * 256;
        float x = ip[c];
        v[i] = x; sum += x; sq += x * x;
    }
    block_reduce_2(sum, sq);
    float mu  = sum * (1.f / DM);
    float var = sq * (1.f / DM) - mu * mu;
    float rs  = rsqrtf(var + 1e-5f);
    float* o = out + (size_t)row * DM;
#pragma unroll
    for (int i = 0; i < 4; i++) {
        int c = threadIdx.x + i * 256;
        o[c] = (v[i] - mu) * rs * gam[c] + bet[c];
    }
}

// ---------------------------------------------------------------------------
// Transpose: out[C,R] = in[R,C]^T  (32x32 tiles, block 32x8)
// ---------------------------------------------------------------------------
__global__ void transpose_kernel(const float* __restrict__ in,
                                 float* __restrict__ out, int R, int C) {
    __shared__ float tile[32][33];
    int cx = blockIdx.x * 32, ry = blockIdx.y * 32;
    int tx = threadIdx.x, ty = threadIdx.y;
#pragma unroll
    for (int i = 0; i < 32; i += 8)
        tile[ty + i][tx] = in[(size_t)(ry + ty + i) * C + cx + tx];
    __syncthreads();
#pragma unroll
    for (int i = 0; i < 32; i += 8)
        out[(size_t)(cx + ty + i) * R + ry + tx] = tile[tx][ty + i];
}

// ---------------------------------------------------------------------------
// TF32 mma.sync GEMM: C[M,N] = A[M,K] @ BT[N,K]^T + bias (+res) (gelu opt)
// 128x128 block tile, BK=32, 256 threads (8 warps as 2m x 4n; warp = 64x32).
// ---------------------------------------------------------------------------
#define BKT 32
#define SPAD 36
#define TILE_F (128 * SPAD)
#define GEMM_SMEM_BYTES (4 * TILE_F * 4)

__global__ __launch_bounds__(256) void gemm_mma(
    const float* __restrict__ A, const float* __restrict__ BT,
    const float* __restrict__ bias, const float* __restrict__ res,
    float* __restrict__ C, int M, int N, int K, int gelu) {
    extern __shared__ float sm[];
    float* As[2] = { sm,              sm + 2 * TILE_F };
    float* Bs[2] = { sm + TILE_F,     sm + 3 * TILE_F };

    int tid  = threadIdx.x;
    int wid  = tid >> 5, lane = tid & 31;
    int gid  = lane >> 2, tig = lane & 3;
    int m_off = (wid >> 2) * 64;
    int n_off = (wid & 3) * 32;
    int bm = blockIdx.y * 128, bn = blockIdx.x * 128;

    float acc[4][4][4];
#pragma unroll
    for (int i = 0; i < 4; i++)
#pragma unroll
        for (int j = 0; j < 4; j++)
#pragma unroll
            for (int k = 0; k < 4; k++) acc[i][j][k] = 0.f;

    float4 ar[4], br[4];
    const int T = K / BKT;

#pragma unroll
    for (int i = 0; i < 4; i++) {
        int idx = tid + i * 256;
        int r = idx >> 3, c4 = idx & 7;
        ar[i] = *(const float4*)(A  + (size_t)(bm + r) * K + c4 * 4);
        br[i] = *(const float4*)(BT + (size_t)(bn + r) * K + c4 * 4);
    }
#pragma unroll
    for (int i = 0; i < 4; i++) {
        int idx = tid + i * 256;
        int r = idx >> 3, c4 = idx & 7;
        float* ap = As[0] + r * SPAD + c4 * 4;
        float* bp = Bs[0] + r * SPAD + c4 * 4;
        ap[0] = tf32r(ar[i].x); ap[1] = tf32r(ar[i].y);
        ap[2] = tf32r(ar[i].z); ap[3] = tf32r(ar[i].w);
        bp[0] = tf32r(br[i].x); bp[1] = tf32r(br[i].y);
        bp[2] = tf32r(br[i].z); bp[3] = tf32r(br[i].w);
    }
    __syncthreads();

    for (int t = 0; t < T; t++) {
        int cur = t & 1, nxt = cur ^ 1;
        if (t + 1 < T) {
            int k0 = (t + 1) * BKT;
#pragma unroll
            for (int i = 0; i < 4; i++) {
                int idx = tid + i * 256;
                int r = idx >> 3, c4 = idx & 7;
                ar[i] = *(const float4*)(A  + (size_t)(bm + r) * K + k0 + c4 * 4);
                br[i] = *(const float4*)(BT + (size_t)(bn + r) * K + k0 + c4 * 4);
            }
        }
        const float* Ac = As[cur];
        const float* Bc = Bs[cur];
#pragma unroll
        for (int ks = 0; ks < 4; ks++) {
            int k = ks * 8;
            uint32_t a[4][4], b[4][2];
#pragma unroll
            for (int mf = 0; mf < 4; mf++) {
                const float* p = Ac + (m_off + mf * 16 + gid) * SPAD + k + tig;
                a[mf][0] = __float_as_uint(p[0]);
                a[mf][1] = __float_as_uint(p[8 * SPAD]);
                a[mf][2] = __float_as_uint(p[4]);
                a[mf][3] = __float_as_uint(p[8 * SPAD + 4]);
            }
#pragma unroll
            for (int nf = 0; nf < 4; nf++) {
                const float* p = Bc + (n_off + nf * 8 + gid) * SPAD + k + tig;
                b[nf][0] = __float_as_uint(p[0]);
                b[nf][1] = __float_as_uint(p[4]);
            }
#pragma unroll
            for (int mf = 0; mf < 4; mf++)
#pragma unroll
                for (int nf = 0; nf < 4; nf++)
                    mma_tf32(acc[mf][nf], a[mf], b[nf]);
        }
        if (t + 1 < T) {
#pragma unroll
            for (int i = 0; i < 4; i++) {
                int idx = tid + i * 256;
                int r = idx >> 3, c4 = idx & 7;
                float* ap = As[nxt] + r * SPAD + c4 * 4;
                float* bp = Bs[nxt] + r * SPAD + c4 * 4;
                ap[0] = tf32r(ar[i].x); ap[1] = tf32r(ar[i].y);
                ap[2] = tf32r(ar[i].z); ap[3] = tf32r(ar[i].w);
                bp[0] = tf32r(br[i].x); bp[1] = tf32r(br[i].y);
                bp[2] = tf32r(br[i].z); bp[3] = tf32r(br[i].w);
            }
        }
        __syncthreads();
    }

#pragma unroll
    for (int mf = 0; mf < 4; mf++) {
        int row0 = bm + m_off + mf * 16 + gid;
        int row1 = row0 + 8;
#pragma unroll
        for (int nf = 0; nf < 4; nf++) {
            int col = bn + n_off + nf * 8 + 2 * tig;
            float b0 = bias[col], b1 = bias[col + 1];
            float v0 = acc[mf][nf][0] + b0;
            float v1 = acc[mf][nf][1] + b1;
            float v2 = acc[mf][nf][2] + b0;
            float v3 = acc[mf][nf][3] + b1;
            if (res) {
                v0 += res[(size_t)row0 * N + col];
                v1 += res[(size_t)row0 * N + col + 1];
                v2 += res[(size_t)row1 * N + col];
                v3 += res[(size_t)row1 * N + col + 1];
            }
            if (gelu) {
                v0 = 0.5f * v0 * (1.0f + erff(v0 * 0.70710678118654752f));
                v1 = 0.5f * v1 * (1.0f + erff(v1 * 0.70710678118654752f));
                v2 = 0.5f * v2 * (1.0f + erff(v2 * 0.70710678118654752f));
                v3 = 0.5f * v3 * (1.0f + erff(v3 * 0.70710678118654752f));
            }
            float2 w0 = make_float2(v0, v1), w1 = make_float2(v2, v3);
            *(float2*)(C + (size_t)row0 * N + col) = w0;
            *(float2*)(C + (size_t)row1 * N + col) = w1;
        }
    }
}

// ---------------------------------------------------------------------------
// Tensor-core flash attention (tf32 mma.sync).
// Block = 128 threads (4 warps), 64 query rows per block, warp owns 16 rows.
// grid = (S/64, B*H). Q,K,V: [B*S, H*DH] row-major.
// Dynamic smem: Ks[64][68] + Vt[64][68] + Ps[64][68] + pm[64]
// ---------------------------------------------------------------------------
#define APAD 68
#define ATTN_SMEM_BYTES ((3 * 64 * APAD + 64) * 4)

__global__ __launch_bounds__(128) void attn_tc(
    const float* __restrict__ Q, const float* __restrict__ Kb,
    const float* __restrict__ Vb, const int* __restrict__ ids,
    float* __restrict__ O, int causal) {
    extern __shared__ float sm[];
    float* Ks = sm;                 // [64][APAD]  keys K-major (key, dh)
    float* Vt = sm + 64 * APAD;     // [64][APAD]  V transposed (dh, key)
    float* Ps = sm + 2 * 64 * APAD; // [64][APAD]  probs (q, key)
    float* pm = sm + 3 * 64 * APAD; // [64]

    int b   = blockIdx.y >> 4;
    int h   = blockIdx.y & 15;
    int q0  = blockIdx.x * 64;
    int tid = threadIdx.x;
    int wid = tid >> 5, lane = tid & 31;
    int gid = lane >> 2, tig = lane & 3;
    int lrow = wid * 16 + gid;       // local q row (row0); row1 = +8
    int grow = q0 + lrow;            // global q row

    // Q fragments (A operand, row-major [q][dh])
    float qf[8][4];
    const float* qb0 = Q + ((size_t)(b * SS + grow)) * DM + h * DHD;
    const float* qb8 = qb0 + 8 * DM;
#pragma unroll
    for (int ks = 0; ks < 8; ks++) {
        qf[ks][0] = tf32r(qb0[ks * 8 + tig]);
        qf[ks][1] = tf32r(qb8[ks * 8 + tig]);
        qf[ks][2] = tf32r(qb0[ks * 8 + tig + 4]);
        qf[ks][3] = tf32r(qb8[ks * 8 + tig + 4]);
    }

    float of[8][4];
#pragma unroll
    for (int i = 0; i < 8; i++)
#pragma unroll
        for (int j = 0; j < 4; j++) of[i][j] = 0.f;
    float m0 = -1e30f, m1 = -1e30f, l0 = 0.f, l1 = 0.f;

    int ntiles = causal ? (blockIdx.x + 1) : (SS / 64);
    for (int t = 0; t < ntiles; t++) {
        int kbase = t * 64;
        // cooperative loads: K rows into Ks, V rows transposed into Vt
#pragma unroll
        for (int i = 0; i < 8; i++) {
            int e  = tid + i * 128;
            int r  = e >> 4, c4 = (e & 15) * 4;
            size_t goff = ((size_t)(b * SS + kbase + r)) * DM + h * DHD + c4;
            float4 kv = *(const float4*)(Kb + goff);
            float4 vv = *(const float4*)(Vb + goff);
            float* kp = Ks + r * APAD + c4;
            kp[0] = tf32r(kv.x); kp[1] = tf32r(kv.y);
            kp[2] = tf32r(kv.z); kp[3] = tf32r(kv.w);
            Vt[(c4 + 0) * APAD + r] = tf32r(vv.x);
            Vt[(c4 + 1) * APAD + r] = tf32r(vv.y);
            Vt[(c4 + 2) * APAD + r] = tf32r(vv.z);
            Vt[(c4 + 3) * APAD + r] = tf32r(vv.w);
        }
        if (tid < 64)
            pm[tid] = (ids[b * SS + kbase + tid] == 0) ? NEGBIG : 0.f;
        __syncthreads();

        // S = Q @ K^T  (scaled) + masks
        float sf[8][4];
#pragma unroll
        for (int nf = 0; nf < 8; nf++) {
            sf[nf][0] = 0.f; sf[nf][1] = 0.f; sf[nf][2] = 0.f; sf[nf][3] = 0.f;
#pragma unroll
            for (int ks = 0; ks < 8; ks++) {
                uint32_t bf[2];
                const float* p = Ks + (nf * 8 + gid) * APAD + ks * 8 + tig;
                bf[0] = __float_as_uint(p[0]);
                bf[1] = __float_as_uint(p[4]);
                mma_tf32(sf[nf], (const uint32_t*)qf[ks], bf);
            }
        }

        float tmax0 = -1e30f, tmax1 = -1e30f;
#pragma unroll
        for (int nf = 0; nf < 8; nf++) {
            int lc0 = nf * 8 + 2 * tig, lc1 = lc0 + 1;
            float s0 = sf[nf][0] * 0.125f + pm[lc0];
            float s1 = sf[nf][1] * 0.125f + pm[lc1];
            float s2 = sf[nf][2] * 0.125f + pm[lc0];
            float s3 = sf[nf][3] * 0.125f + pm[lc1];
            if (causal) {
                int g0 = kbase + lc0, g1 = kbase + lc1;
                if (g0 > grow)     s0 = -1e30f;
                if (g1 > grow)     s1 = -1e30f;
                if (g0 > grow + 8) s2 = -1e30f;
                if (g1 > grow + 8) s3 = -1e30f;
            }
            sf[nf][0] = s0; sf[nf][1] = s1; sf[nf][2] = s2; sf[nf][3] = s3;
            tmax0 = fmaxf(tmax0, fmaxf(s0, s1));
            tmax1 = fmaxf(tmax1, fmaxf(s2, s3));
        }
        tmax0 = fmaxf(tmax0, __shfl_xor_sync(0xffffffffu, tmax0, 1));
        tmax0 = fmaxf(tmax0, __shfl_xor_sync(0xffffffffu, tmax0, 2));
        tmax1 = fmaxf(tmax1, __shfl_xor_sync(0xffffffffu, tmax1, 1));
        tmax1 = fmaxf(tmax1, __shfl_xor_sync(0xffffffffu, tmax1, 2));

        float nm0 = fmaxf(m0, tmax0), nm1 = fmaxf(m1, tmax1);
        float sc0 = __expf(m0 - nm0), sc1 = __expf(m1 - nm1);
        m0 = nm0; m1 = nm1;

        float ts0 = 0.f, ts1 = 0.f;
        float* pr0 = Ps + lrow * APAD;
        float* pr1 = Ps + (lrow + 8) * APAD;
#pragma unroll
        for (int nf = 0; nf < 8; nf++) {
            int lc0 = nf * 8 + 2 * tig;
            float p0 = __expf(sf[nf][0] - nm0);
            float p1 = __expf(sf[nf][1] - nm0);
            float p2 = __expf(sf[nf][2] - nm1);
            float p3 = __expf(sf[nf][3] - nm1);
            ts0 += p0 + p1; ts1 += p2 + p3;
            pr0[lc0]     = tf32r(p0);
            pr0[lc0 + 1] = tf32r(p1);
            pr1[lc0]     = tf32r(p2);
            pr1[lc0 + 1] = tf32r(p3);
            of[nf][0] *= sc0; of[nf][1] *= sc0;
            of[nf][2] *= sc1; of[nf][3] *= sc1;
        }
        ts0 += __shfl_xor_sync(0xffffffffu, ts0, 1);
        ts0 += __shfl_xor_sync(0xffffffffu, ts0, 2);
        ts1 += __shfl_xor_sync(0xffffffffu, ts1, 1);
        ts1 += __shfl_xor_sync(0xffffffffu, ts1, 2);
        l0 = l0 * sc0 + ts0;
        l1 = l1 * sc1 + ts1;
        __syncwarp();

        // O += P @ V   (A from Ps warp-private rows, B from Vt)
#pragma unroll
        for (int ks = 0; ks < 8; ks++) {
            uint32_t af[4];
            af[0] = __float_as_uint(pr0[ks * 8 + tig]);
            af[1] = __float_as_uint(pr1[ks * 8 + tig]);
            af[2] = __float_as_uint(pr0[ks * 8 + tig + 4]);
            af[3] = __float_as_uint(pr1[ks * 8 + tig + 4]);
#pragma unroll
            for (int nf = 0; nf < 8; nf++) {
                uint32_t bf[2];
                const float* p = Vt + (nf * 8 + gid) * APAD + ks * 8 + tig;
                bf[0] = __float_as_uint(p[0]);
                bf[1] = __float_as_uint(p[4]);
                mma_tf32(of[nf], af, bf);
            }
        }
        __syncthreads();
    }

    float inv0 = 1.f / l0, inv1 = 1.f / l1;
    float* ob0 = O + ((size_t)(b * SS + grow)) * DM + h * DHD;
    float* ob8 = ob0 + 8 * DM;
#pragma unroll
    for (int nf = 0; nf < 8; nf++) {
        int col = nf * 8 + 2 * tig;
        *(float2*)(ob0 + col) = make_float2(of[nf][0] * inv0, of[nf][1] * inv0);
        *(float2*)(ob8 + col) = make_float2(of[nf][2] * inv1, of[nf][3] * inv1);
    }
}

// ---------------------------------------------------------------------------
// Launch
// ---------------------------------------------------------------------------
extern "C" void kernel_launch(void* const* d_in, const int* in_sizes, int n_in,
                              void* d_out, int out_size) {
    const float* input_embedding = (const float*)d_in[0];
    const int*   input_ids       = (const int*)d_in[1];
    const int*   target_ids      = (const int*)d_in[2];
    const float* tok_emb = (const float*)d_in[3];
    const float* pos_emb = (const float*)d_in[4];
    const float* ln1_g = (const float*)d_in[5];
    const float* ln1_b = (const float*)d_in[6];
    const float* q1_w = (const float*)d_in[7];
    const float* q1_b = (const float*)d_in[8];
    const float* k1_w = (const float*)d_in[9];
    const float* k1_b = (const float*)d_in[10];
    const float* v1_w = (const float*)d_in[11];
    const float* v1_b = (const float*)d_in[12];
    const float* out1_w = (const float*)d_in[13];
    const float* out1_b = (const float*)d_in[14];
    const float* ln2_g = (const float*)d_in[15];
    const float* ln2_b = (const float*)d_in[16];
    const float* q2_w = (const float*)d_in[17];
    const float* q2_b = (const float*)d_in[18];
    const float* k2_w = (const float*)d_in[19];
    const float* k2_b = (const float*)d_in[20];
    const float* v2_w = (const float*)d_in[21];
    const float* v2_b = (const float*)d_in[22];
    const float* out2_w = (const float*)d_in[23];
    const float* out2_b = (const float*)d_in[24];
    const float* ln3_g = (const float*)d_in[25];
    const float* ln3_b = (const float*)d_in[26];
    const float* mlp_w1 = (const float*)d_in[27];
    const float* mlp_b1 = (const float*)d_in[28];
    const float* mlp_w2 = (const float*)d_in[29];
    const float* mlp_b2 = (const float*)d_in[30];
    float* out = (float*)d_out;

    static float *X = nullptr, *Qb = nullptr, *Kb = nullptr, *Vb = nullptr,
                 *ATT = nullptr, *H = nullptr, *HID = nullptr, *WT = nullptr;
    static bool attr_done = false;
    if (!X) {
        cudaGetSymbolAddress((void**)&X,   g_X);
        cudaGetSymbolAddress((void**)&Qb,  g_Q);
        cudaGetSymbolAddress((void**)&Kb,  g_K);
        cudaGetSymbolAddress((void**)&Vb,  g_V);
        cudaGetSymbolAddress((void**)&ATT, g_ATT);
        cudaGetSymbolAddress((void**)&H,   g_H);
        cudaGetSymbolAddress((void**)&HID, g_HID);
        cudaGetSymbolAddress((void**)&WT,  g_WT);
    }
    if (!attr_done) {
        cudaFuncSetAttribute(gemm_mma, cudaFuncAttributeMaxDynamicSharedMemorySize,
                             GEMM_SMEM_BYTES);
        cudaFuncSetAttribute(attn_tc, cudaFuncAttributeMaxDynamicSharedMemorySize,
                             ATTN_SMEM_BYTES);
        attr_done = true;
    }

    const size_t MW = 1024 * 1024;
    float* wt_q1 = WT + 0 * MW;
    float* wt_k1 = WT + 1 * MW;
    float* wt_v1 = WT + 2 * MW;
    float* wt_o1 = WT + 3 * MW;
    float* wt_q2 = WT + 4 * MW;
    float* wt_k2 = WT + 5 * MW;
    float* wt_v2 = WT + 6 * MW;
    float* wt_o2 = WT + 7 * MW;
    float* wt_m1 = WT + 8 * MW;
    float* wt_m2 = WT + 12 * MW;

    dim3 tb(32, 8);
    dim3 tg1(DM / 32, DM / 32);
    transpose_kernel<<<tg1, tb>>>(q1_w, wt_q1, DM, DM);
    transpose_kernel<<<tg1, tb>>>(k1_w, wt_k1, DM, DM);
    transpose_kernel<<<tg1, tb>>>(v1_w, wt_v1, DM, DM);
    transpose_kernel<<<tg1, tb>>>(out1_w, wt_o1, DM, DM);
    transpose_kernel<<<tg1, tb>>>(q2_w, wt_q2, DM, DM);
    transpose_kernel<<<tg1, tb>>>(k2_w, wt_k2, DM, DM);
    transpose_kernel<<<tg1, tb>>>(v2_w, wt_v2, DM, DM);
    transpose_kernel<<<tg1, tb>>>(out2_w, wt_o2, DM, DM);
    dim3 tgm1(DFF / 32, DM / 32);
    transpose_kernel<<<tgm1, tb>>>(mlp_w1, wt_m1, DM, DFF);
    dim3 tgm2(DM / 32, DFF / 32);
    transpose_kernel<<<tgm2, tb>>>(mlp_w2, wt_m2, DFF, DM);

    dim3 gProj(DM / 128, MTOK / 128);   // (8, 32)
    dim3 gMlp1(DFF / 128, MTOK / 128);  // (32, 32)
    dim3 gAttn(SS / 64, BB * HH);       // (32, 32)
    const int SB = GEMM_SMEM_BYTES;
    const int AB = ATTN_SMEM_BYTES;

    // 1. embedding + LN1 -> X
    embed_ln_kernel<<<MTOK, 256>>>(target_ids, tok_emb, pos_emb, ln1_g, ln1_b, X);
    // 2. self-attn QKV projections
    gemm_mma<<<gProj, 256, SB>>>(X, wt_q1, q1_b, nullptr, Qb, MTOK, DM, DM, 0);
    gemm_mma<<<gProj, 256, SB>>>(X, wt_k1, k1_b, nullptr, Kb, MTOK, DM, DM, 0);
    gemm_mma<<<gProj, 256, SB>>>(X, wt_v1, v1_b, nullptr, Vb, MTOK, DM, DM, 0);
    // 3. causal self-attention
    attn_tc<<<gAttn, 128, AB>>>(Qb, Kb, Vb, target_ids, ATT, 1);
    // 4. out projection + residual (X = LN1 out) -> H
    gemm_mma<<<gProj, 256, SB>>>(ATT, wt_o1, out1_b, X, H, MTOK, DM, DM, 0);
    // 5. LN2 -> X
    ln_kernel<<<MTOK, 256>>>(H, ln2_g, ln2_b, X);
    // 6. cross-attn projections
    gemm_mma<<<gProj, 256, SB>>>(X, wt_q2, q2_b, nullptr, Qb, MTOK, DM, DM, 0);
    gemm_mma<<<gProj, 256, SB>>>(input_embedding, wt_k2, k2_b, nullptr, Kb, MTOK, DM, DM, 0);
    gemm_mma<<<gProj, 256, SB>>>(input_embedding, wt_v2, v2_b, nullptr, Vb, MTOK, DM, DM, 0);
    // 7. cross-attention
    attn_tc<<<gAttn, 128, AB>>>(Qb, Kb, Vb, input_ids, ATT, 0);
    // 8. out projection + residual (X = LN2 out) -> H  ("r")
    gemm_mma<<<gProj, 256, SB>>>(ATT, wt_o2, out2_b, X, H, MTOK, DM, DM, 0);
    // 9. LN3 -> X
    ln_kernel<<<MTOK, 256>>>(H, ln3_g, ln3_b, X);
    // 10. MLP up + GELU -> HID
    gemm_mma<<<gMlp1, 256, SB>>>(X, wt_m1, mlp_b1, nullptr, HID, MTOK, DFF, DM, 1);
    // 11. MLP down + bias + residual (H) -> out
    gemm_mma<<<gProj, 256, SB>>>(HID, wt_m2, mlp_b2, H, out, MTOK, DM, DFF, 0);
}

// round 7
// speedup vs baseline: 2.9066x; 1.3074x over previous
#include <cuda_runtime.h>
#include <math.h>
#include <stdint.h>

// ---------------------------------------------------------------------------
// Problem constants
// ---------------------------------------------------------------------------
#define BB    2
#define SS    2048
#define DM    1024
#define HH    16
#define DHD   64
#define MTOK  (BB*SS)          // 4096 token rows
#define DFF   4096
#define NEGBIG (-1000000000.0f)

// ---------------------------------------------------------------------------
// Scratch (static device globals; no allocations allowed)
// ---------------------------------------------------------------------------
__device__ float g_X  [MTOK*DM];
__device__ float g_Q  [MTOK*DM];
__device__ float g_K  [MTOK*DM];
__device__ float g_V  [MTOK*DM];
__device__ float g_ATT[MTOK*DM];
__device__ float g_H  [MTOK*DM];
__device__ float g_HID[(size_t)MTOK*DFF];

// ---------------------------------------------------------------------------
// Helpers
// ---------------------------------------------------------------------------
__device__ __forceinline__ float tf32r(float x) {
    float y;
    asm("cvt.rna.tf32.f32 %0, %1;" : "=f"(y) : "f"(x));
    return y;
}
__device__ __forceinline__ uint32_t tf32u(float x) {
    return __float_as_uint(tf32r(x));
}

__device__ __forceinline__ void mma_tf32(float* d, const uint32_t* a,
                                         const uint32_t* b) {
    asm volatile(
        "mma.sync.aligned.m16n8k8.row.col.f32.tf32.tf32.f32 "
        "{%0,%1,%2,%3}, {%4,%5,%6,%7}, {%8,%9}, {%0,%1,%2,%3};"
        : "+f"(d[0]), "+f"(d[1]), "+f"(d[2]), "+f"(d[3])
        : "r"(a[0]), "r"(a[1]), "r"(a[2]), "r"(a[3]), "r"(b[0]), "r"(b[1]));
}

__device__ __forceinline__ uint32_t smem_u32(const void* p) {
    uint32_t a;
    asm("{ .reg .u64 t; cvta.to.shared.u64 t, %1; cvt.u32.u64 %0, t; }"
        : "=r"(a) : "l"(p));
    return a;
}
__device__ __forceinline__ void cp16(uint32_t dst, const void* src) {
    asm volatile("cp.async.cg.shared.global [%0], [%1], 16;"
                 :: "r"(dst), "l"(src));
}
#define CP_COMMIT() asm volatile("cp.async.commit_group;" ::: "memory")
#define CP_WAIT(n)  asm volatile("cp.async.wait_group %0;" :: "n"(n) : "memory")

// ---------------------------------------------------------------------------
// Block reduction for (sum, sumsq), blockDim.x == 256
// ---------------------------------------------------------------------------
__device__ __forceinline__ void block_reduce_2(float& s, float& q) {
    __shared__ float sh_s[8], sh_q[8];
    int lane = threadIdx.x & 31, w = threadIdx.x >> 5;
#pragma unroll
    for (int o = 16; o > 0; o >>= 1) {
        s += __shfl_down_sync(0xffffffffu, s, o);
        q += __shfl_down_sync(0xffffffffu, q, o);
    }
    if (lane == 0) { sh_s[w] = s; sh_q[w] = q; }
    __syncthreads();
    if (w == 0) {
        s = (lane < 8) ? sh_s[lane] : 0.f;
        q = (lane < 8) ? sh_q[lane] : 0.f;
#pragma unroll
        for (int o = 4; o > 0; o >>= 1) {
            s += __shfl_down_sync(0xffffffffu, s, o);
            q += __shfl_down_sync(0xffffffffu, q, o);
        }
        if (lane == 0) { sh_s[0] = s; sh_q[0] = q; }
    }
    __syncthreads();
    s = sh_s[0]; q = sh_q[0];
}

// ---------------------------------------------------------------------------
// Embedding gather + positional + LayerNorm (one block per token row)
// ---------------------------------------------------------------------------
__global__ void embed_ln_kernel(const int* __restrict__ tgt_ids,
                                const float* __restrict__ tok_emb,
                                const float* __restrict__ pos_emb,
                                const float* __restrict__ gam,
                                const float* __restrict__ bet,
                                float* __restrict__ out) {
    int row = blockIdx.x;
    int s   = row & (SS - 1);
    int tok = tgt_ids[row];
    const float* te = tok_emb + (size_t)tok * DM;
    const float* pe = pos_emb + (size_t)s   * DM;
    float v[4]; float sum = 0.f, sq = 0.f;
#pragma unroll
    for (int i = 0; i < 4; i++) {
        int c = threadIdx.x + i * 256;
        float x = te[c] + pe[c];
        v[i] = x; sum += x; sq += x * x;
    }
    block_reduce_2(sum, sq);
    float mu  = sum * (1.f / DM);
    float var = sq * (1.f / DM) - mu * mu;
    float rs  = rsqrtf(var + 1e-5f);
    float* o = out + (size_t)row * DM;
#pragma unroll
    for (int i = 0; i < 4; i++) {
        int c = threadIdx.x + i * 256;
        o[c] = (v[i] - mu) * rs * gam[c] + bet[c];
    }
}

// ---------------------------------------------------------------------------
// LayerNorm (one block per row)
// ---------------------------------------------------------------------------
__global__ void ln_kernel(const float* __restrict__ in,
                          const float* __restrict__ gam,
                          const float* __restrict__ bet,
                          float* __restrict__ out) {
    int row = blockIdx.x;
    const float* ip = in + (size_t)row * DM;
    float v[4]; float sum = 0.f, sq = 0.f;
#pragma unroll
    for (int i = 0; i < 4; i++) {
        int c = threadIdx.x + i * 256;
        float x = ip[c];
        v[i] = x; sum += x; sq += x * x;
    }
    block_reduce_2(sum, sq);
    float mu  = sum * (1.f / DM);
    float var = sq * (1.f / DM) - mu * mu;
    float rs  = rsqrtf(var + 1e-5f);
    float* o = out + (size_t)row * DM;
#pragma unroll
    for (int i = 0; i < 4; i++) {
        int c = threadIdx.x + i * 256;
        o[c] = (v[i] - mu) * rs * gam[c] + bet[c];
    }
}

// ---------------------------------------------------------------------------
// TF32 mma.sync GEMM v2: C[M,N] = A[M,K] @ W[K,N] + bias (+res) (gelu opt)
// Natural-layout W (no pre-transpose). 128x128 tile, BK=32, 256 threads,
// 8 warps (2m x 4n; warp = 64x32). 2-stage cp.async pipeline.
// A smem: [128][ASPAD] row-major slab; W smem: [32][BSPAD].
// ---------------------------------------------------------------------------
#define BKT    32
#define ASPAD  36
#define BSPAD  132
#define A_STAGE (128 * ASPAD)               // floats
#define B_STAGE (BKT * BSPAD)               // floats
#define STAGE_F (A_STAGE + B_STAGE)
#define GEMM_SMEM_BYTES (2 * STAGE_F * 4)   // ~70.7 KB

__global__ __launch_bounds__(256) void gemm_mma(
    const float* __restrict__ A, const float* __restrict__ W,
    const float* __restrict__ bias, const float* __restrict__ res,
    float* __restrict__ C, int M, int N, int K, int gelu) {
    extern __shared__ float sm[];
    float* Af[2] = { sm,                     sm + STAGE_F };
    float* Bf[2] = { sm + A_STAGE,           sm + STAGE_F + A_STAGE };
    uint32_t aU[2] = { smem_u32(Af[0]), smem_u32(Af[1]) };
    uint32_t bU[2] = { smem_u32(Bf[0]), smem_u32(Bf[1]) };

    int tid  = threadIdx.x;
    int wid  = tid >> 5, lane = tid & 31;
    int gid  = lane >> 2, tig = lane & 3;
    int m_off = (wid >> 2) * 64;
    int n_off = (wid & 3) * 32;
    int bm = blockIdx.y * 128, bn = blockIdx.x * 128;

    float acc[4][4][4];
#pragma unroll
    for (int i = 0; i < 4; i++)
#pragma unroll
        for (int j = 0; j < 4; j++)
#pragma unroll
            for (int k = 0; k < 4; k++) acc[i][j][k] = 0.f;

    const int T = K / BKT;

    // ---- prefetch tile 0 into stage 0
    {
#pragma unroll
        for (int i = 0; i < 4; i++) {
            int idx = tid + i * 256;
            int r = idx >> 3, c4 = idx & 7;
            cp16(aU[0] + (uint32_t)(r * ASPAD + c4 * 4) * 4,
                 A + (size_t)(bm + r) * K + c4 * 4);
        }
#pragma unroll
        for (int i = 0; i < 4; i++) {
            int idx = tid + i * 256;
            int r = idx >> 5, c4 = idx & 31;
            cp16(bU[0] + (uint32_t)(r * BSPAD + c4 * 4) * 4,
                 W + (size_t)r * N + bn + c4 * 4);
        }
        CP_COMMIT();
    }

    for (int t = 0; t < T; t++) {
        int cur = t & 1;
        if (t + 1 < T) {
            int nxt = cur ^ 1;
            int k0 = (t + 1) * BKT;
#pragma unroll
            for (int i = 0; i < 4; i++) {
                int idx = tid + i * 256;
                int r = idx >> 3, c4 = idx & 7;
                cp16(aU[nxt] + (uint32_t)(r * ASPAD + c4 * 4) * 4,
                     A + (size_t)(bm + r) * K + k0 + c4 * 4);
            }
#pragma unroll
            for (int i = 0; i < 4; i++) {
                int idx = tid + i * 256;
                int r = idx >> 5, c4 = idx & 31;
                cp16(bU[nxt] + (uint32_t)(r * BSPAD + c4 * 4) * 4,
                     W + (size_t)(k0 + r) * N + bn + c4 * 4);
            }
            CP_COMMIT();
            CP_WAIT(1);
        } else {
            CP_WAIT(0);
        }
        __syncthreads();

        const float* Ac = Af[cur];
        const float* Bc = Bf[cur];
#pragma unroll
        for (int ks = 0; ks < 4; ks++) {
            int k = ks * 8;
            uint32_t a[4][4], b[4][2];
#pragma unroll
            for (int mf = 0; mf < 4; mf++) {
                const float* p = Ac + (m_off + mf * 16 + gid) * ASPAD + k + tig;
                a[mf][0] = tf32u(p[0]);
                a[mf][1] = tf32u(p[8 * ASPAD]);
                a[mf][2] = tf32u(p[4]);
                a[mf][3] = tf32u(p[8 * ASPAD + 4]);
            }
#pragma unroll
            for (int nf = 0; nf < 4; nf++) {
                const float* p = Bc + (k + tig) * BSPAD + n_off + nf * 8 + gid;
                b[nf][0] = tf32u(p[0]);
                b[nf][1] = tf32u(p[4 * BSPAD]);
            }
#pragma unroll
            for (int mf = 0; mf < 4; mf++)
#pragma unroll
                for (int nf = 0; nf < 4; nf++)
                    mma_tf32(acc[mf][nf], a[mf], b[nf]);
        }
        __syncthreads();
    }

    // epilogue
#pragma unroll
    for (int mf = 0; mf < 4; mf++) {
        int row0 = bm + m_off + mf * 16 + gid;
        int row1 = row0 + 8;
#pragma unroll
        for (int nf = 0; nf < 4; nf++) {
            int col = bn + n_off + nf * 8 + 2 * tig;
            float b0 = bias[col], b1 = bias[col + 1];
            float v0 = acc[mf][nf][0] + b0;
            float v1 = acc[mf][nf][1] + b1;
            float v2 = acc[mf][nf][2] + b0;
            float v3 = acc[mf][nf][3] + b1;
            if (res) {
                v0 += res[(size_t)row0 * N + col];
                v1 += res[(size_t)row0 * N + col + 1];
                v2 += res[(size_t)row1 * N + col];
                v3 += res[(size_t)row1 * N + col + 1];
            }
            if (gelu) {
                v0 = 0.5f * v0 * (1.0f + erff(v0 * 0.70710678118654752f));
                v1 = 0.5f * v1 * (1.0f + erff(v1 * 0.70710678118654752f));
                v2 = 0.5f * v2 * (1.0f + erff(v2 * 0.70710678118654752f));
                v3 = 0.5f * v3 * (1.0f + erff(v3 * 0.70710678118654752f));
            }
            *(float2*)(C + (size_t)row0 * N + col) = make_float2(v0, v1);
            *(float2*)(C + (size_t)row1 * N + col) = make_float2(v2, v3);
        }
    }
}

// ---------------------------------------------------------------------------
// Tensor-core flash attention (tf32 mma.sync).
// Block = 128 threads (4 warps), 64 query rows per block, warp owns 16 rows.
// grid = (S/64, B*H). Q,K,V: [B*S, H*DH] row-major.
// ---------------------------------------------------------------------------
#define APAD 68
#define ATTN_SMEM_BYTES ((3 * 64 * APAD + 64) * 4)

__global__ __launch_bounds__(128) void attn_tc(
    const float* __restrict__ Q, const float* __restrict__ Kb,
    const float* __restrict__ Vb, const int* __restrict__ ids,
    float* __restrict__ O, int causal) {
    extern __shared__ float sm[];
    float* Ks = sm;                 // [64][APAD]
    float* Vt = sm + 64 * APAD;     // [64][APAD]  V transposed (dh, key)
    float* Ps = sm + 2 * 64 * APAD; // [64][APAD]
    float* pm = sm + 3 * 64 * APAD; // [64]

    int b   = blockIdx.y >> 4;
    int h   = blockIdx.y & 15;
    int q0  = blockIdx.x * 64;
    int tid = threadIdx.x;
    int wid = tid >> 5, lane = tid & 31;
    int gid = lane >> 2, tig = lane & 3;
    int lrow = wid * 16 + gid;
    int grow = q0 + lrow;

    float qf[8][4];
    const float* qb0 = Q + ((size_t)(b * SS + grow)) * DM + h * DHD;
    const float* qb8 = qb0 + 8 * DM;
#pragma unroll
    for (int ks = 0; ks < 8; ks++) {
        qf[ks][0] = tf32r(qb0[ks * 8 + tig]);
        qf[ks][1] = tf32r(qb8[ks * 8 + tig]);
        qf[ks][2] = tf32r(qb0[ks * 8 + tig + 4]);
        qf[ks][3] = tf32r(qb8[ks * 8 + tig + 4]);
    }

    float of[8][4];
#pragma unroll
    for (int i = 0; i < 8; i++)
#pragma unroll
        for (int j = 0; j < 4; j++) of[i][j] = 0.f;
    float m0 = -1e30f, m1 = -1e30f, l0 = 0.f, l1 = 0.f;

    int ntiles = causal ? (blockIdx.x + 1) : (SS / 64);
    for (int t = 0; t < ntiles; t++) {
        int kbase = t * 64;
#pragma unroll
        for (int i = 0; i < 8; i++) {
            int e  = tid + i * 128;
            int r  = e >> 4, c4 = (e & 15) * 4;
            size_t goff = ((size_t)(b * SS + kbase + r)) * DM + h * DHD + c4;
            float4 kv = *(const float4*)(Kb + goff);
            float4 vv = *(const float4*)(Vb + goff);
            float* kp = Ks + r * APAD + c4;
            kp[0] = tf32r(kv.x); kp[1] = tf32r(kv.y);
            kp[2] = tf32r(kv.z); kp[3] = tf32r(kv.w);
            Vt[(c4 + 0) * APAD + r] = tf32r(vv.x);
            Vt[(c4 + 1) * APAD + r] = tf32r(vv.y);
            Vt[(c4 + 2) * APAD + r] = tf32r(vv.z);
            Vt[(c4 + 3) * APAD + r] = tf32r(vv.w);
        }
        if (tid < 64)
            pm[tid] = (ids[b * SS + kbase + tid] == 0) ? NEGBIG : 0.f;
        __syncthreads();

        float sf[8][4];
#pragma unroll
        for (int nf = 0; nf < 8; nf++) {
            sf[nf][0] = 0.f; sf[nf][1] = 0.f; sf[nf][2] = 0.f; sf[nf][3] = 0.f;
#pragma unroll
            for (int ks = 0; ks < 8; ks++) {
                uint32_t bf[2];
                const float* p = Ks + (nf * 8 + gid) * APAD + ks * 8 + tig;
                bf[0] = __float_as_uint(p[0]);
                bf[1] = __float_as_uint(p[4]);
                mma_tf32(sf[nf], (const uint32_t*)qf[ks], bf);
            }
        }

        float tmax0 = -1e30f, tmax1 = -1e30f;
#pragma unroll
        for (int nf = 0; nf < 8; nf++) {
            int lc0 = nf * 8 + 2 * tig, lc1 = lc0 + 1;
            float s0 = sf[nf][0] * 0.125f + pm[lc0];
            float s1 = sf[nf][1] * 0.125f + pm[lc1];
            float s2 = sf[nf][2] * 0.125f + pm[lc0];
            float s3 = sf[nf][3] * 0.125f + pm[lc1];
            if (causal) {
                int g0 = kbase + lc0, g1 = kbase + lc1;
                if (g0 > grow)     s0 = -1e30f;
                if (g1 > grow)     s1 = -1e30f;
                if (g0 > grow + 8) s2 = -1e30f;
                if (g1 > grow + 8) s3 = -1e30f;
            }
            sf[nf][0] = s0; sf[nf][1] = s1; sf[nf][2] = s2; sf[nf][3] = s3;
            tmax0 = fmaxf(tmax0, fmaxf(s0, s1));
            tmax1 = fmaxf(tmax1, fmaxf(s2, s3));
        }
        tmax0 = fmaxf(tmax0, __shfl_xor_sync(0xffffffffu, tmax0, 1));
        tmax0 = fmaxf(tmax0, __shfl_xor_sync(0xffffffffu, tmax0, 2));
        tmax1 = fmaxf(tmax1, __shfl_xor_sync(0xffffffffu, tmax1, 1));
        tmax1 = fmaxf(tmax1, __shfl_xor_sync(0xffffffffu, tmax1, 2));

        float nm0 = fmaxf(m0, tmax0), nm1 = fmaxf(m1, tmax1);
        float sc0 = __expf(m0 - nm0), sc1 = __expf(m1 - nm1);
        m0 = nm0; m1 = nm1;

        float ts0 = 0.f, ts1 = 0.f;
        float* pr0 = Ps + lrow * APAD;
        float* pr1 = Ps + (lrow + 8) * APAD;
#pragma unroll
        for (int nf = 0; nf < 8; nf++) {
            int lc0 = nf * 8 + 2 * tig;
            float p0 = __expf(sf[nf][0] - nm0);
            float p1 = __expf(sf[nf][1] - nm0);
            float p2 = __expf(sf[nf][2] - nm1);
            float p3 = __expf(sf[nf][3] - nm1);
            ts0 += p0 + p1; ts1 += p2 + p3;
            pr0[lc0]     = tf32r(p0);
            pr0[lc0 + 1] = tf32r(p1);
            pr1[lc0]     = tf32r(p2);
            pr1[lc0 + 1] = tf32r(p3);
            of[nf][0] *= sc0; of[nf][1] *= sc0;
            of[nf][2] *= sc1; of[nf][3] *= sc1;
        }
        ts0 += __shfl_xor_sync(0xffffffffu, ts0, 1);
        ts0 += __shfl_xor_sync(0xffffffffu, ts0, 2);
        ts1 += __shfl_xor_sync(0xffffffffu, ts1, 1);
        ts1 += __shfl_xor_sync(0xffffffffu, ts1, 2);
        l0 = l0 * sc0 + ts0;
        l1 = l1 * sc1 + ts1;
        __syncwarp();

#pragma unroll
        for (int ks = 0; ks < 8; ks++) {
            uint32_t af[4];
            af[0] = __float_as_uint(pr0[ks * 8 + tig]);
            af[1] = __float_as_uint(pr1[ks * 8 + tig]);
            af[2] = __float_as_uint(pr0[ks * 8 + tig + 4]);
            af[3] = __float_as_uint(pr1[ks * 8 + tig + 4]);
#pragma unroll
            for (int nf = 0; nf < 8; nf++) {
                uint32_t bf[2];
                const float* p = Vt + (nf * 8 + gid) * APAD + ks * 8 + tig;
                bf[0] = __float_as_uint(p[0]);
                bf[1] = __float_as_uint(p[4]);
                mma_tf32(of[nf], af, bf);
            }
        }
        __syncthreads();
    }

    float inv0 = 1.f / l0, inv1 = 1.f / l1;
    float* ob0 = O + ((size_t)(b * SS + grow)) * DM + h * DHD;
    float* ob8 = ob0 + 8 * DM;
#pragma unroll
    for (int nf = 0; nf < 8; nf++) {
        int col = nf * 8 + 2 * tig;
        *(float2*)(ob0 + col) = make_float2(of[nf][0] * inv0, of[nf][1] * inv0);
        *(float2*)(ob8 + col) = make_float2(of[nf][2] * inv1, of[nf][3] * inv1);
    }
}

// ---------------------------------------------------------------------------
// Launch
// ---------------------------------------------------------------------------
extern "C" void kernel_launch(void* const* d_in, const int* in_sizes, int n_in,
                              void* d_out, int out_size) {
    const float* input_embedding = (const float*)d_in[0];
    const int*   input_ids       = (const int*)d_in[1];
    const int*   target_ids      = (const int*)d_in[2];
    const float* tok_emb = (const float*)d_in[3];
    const float* pos_emb = (const float*)d_in[4];
    const float* ln1_g = (const float*)d_in[5];
    const float* ln1_b = (const float*)d_in[6];
    const float* q1_w = (const float*)d_in[7];
    const float* q1_b = (const float*)d_in[8];
    const float* k1_w = (const float*)d_in[9];
    const float* k1_b = (const float*)d_in[10];
    const float* v1_w = (const float*)d_in[11];
    const float* v1_b = (const float*)d_in[12];
    const float* out1_w = (const float*)d_in[13];
    const float* out1_b = (const float*)d_in[14];
    const float* ln2_g = (const float*)d_in[15];
    const float* ln2_b = (const float*)d_in[16];
    const float* q2_w = (const float*)d_in[17];
    const float* q2_b = (const float*)d_in[18];
    const float* k2_w = (const float*)d_in[19];
    const float* k2_b = (const float*)d_in[20];
    const float* v2_w = (const float*)d_in[21];
    const float* v2_b = (const float*)d_in[22];
    const float* out2_w = (const float*)d_in[23];
    const float* out2_b = (const float*)d_in[24];
    const float* ln3_g = (const float*)d_in[25];
    const float* ln3_b = (const float*)d_in[26];
    const float* mlp_w1 = (const float*)d_in[27];
    const float* mlp_b1 = (const float*)d_in[28];
    const float* mlp_w2 = (const float*)d_in[29];
    const float* mlp_b2 = (const float*)d_in[30];
    float* out = (float*)d_out;

    static float *X = nullptr, *Qb = nullptr, *Kb = nullptr, *Vb = nullptr,
                 *ATT = nullptr, *H = nullptr, *HID = nullptr;
    static bool attr_done = false;
    if (!X) {
        cudaGetSymbolAddress((void**)&X,   g_X);
        cudaGetSymbolAddress((void**)&Qb,  g_Q);
        cudaGetSymbolAddress((void**)&Kb,  g_K);
        cudaGetSymbolAddress((void**)&Vb,  g_V);
        cudaGetSymbolAddress((void**)&ATT, g_ATT);
        cudaGetSymbolAddress((void**)&H,   g_H);
        cudaGetSymbolAddress((void**)&HID, g_HID);
    }
    if (!attr_done) {
        cudaFuncSetAttribute(gemm_mma, cudaFuncAttributeMaxDynamicSharedMemorySize,
                             GEMM_SMEM_BYTES);
        cudaFuncSetAttribute(attn_tc, cudaFuncAttributeMaxDynamicSharedMemorySize,
                             ATTN_SMEM_BYTES);
        attr_done = true;
    }

    dim3 gProj(DM / 128, MTOK / 128);   // (8, 32)
    dim3 gMlp1(DFF / 128, MTOK / 128);  // (32, 32)
    dim3 gAttn(SS / 64, BB * HH);       // (32, 32)
    const int SB = GEMM_SMEM_BYTES;
    const int AB = ATTN_SMEM_BYTES;

    // 1. embedding + LN1 -> X
    embed_ln_kernel<<<MTOK, 256>>>(target_ids, tok_emb, pos_emb, ln1_g, ln1_b, X);
    // 2. self-attn QKV projections
    gemm_mma<<<gProj, 256, SB>>>(X, q1_w, q1_b, nullptr, Qb, MTOK, DM, DM, 0);
    gemm_mma<<<gProj, 256, SB>>>(X, k1_w, k1_b, nullptr, Kb, MTOK, DM, DM, 0);
    gemm_mma<<<gProj, 256, SB>>>(X, v1_w, v1_b, nullptr, Vb, MTOK, DM, DM, 0);
    // 3. causal self-attention
    attn_tc<<<gAttn, 128, AB>>>(Qb, Kb, Vb, target_ids, ATT, 1);
    // 4. out projection + residual (X = LN1 out) -> H
    gemm_mma<<<gProj, 256, SB>>>(ATT, out1_w, out1_b, X, H, MTOK, DM, DM, 0);
    // 5. LN2 -> X
    ln_kernel<<<MTOK, 256>>>(H, ln2_g, ln2_b, X);
    // 6. cross-attn projections
    gemm_mma<<<gProj, 256, SB>>>(X, q2_w, q2_b, nullptr, Qb, MTOK, DM, DM, 0);
    gemm_mma<<<gProj, 256, SB>>>(input_embedding, k2_w, k2_b, nullptr, Kb, MTOK, DM, DM, 0);
    gemm_mma<<<gProj, 256, SB>>>(input_embedding, v2_w, v2_b, nullptr, Vb, MTOK, DM, DM, 0);
    // 7. cross-attention
    attn_tc<<<gAttn, 128, AB>>>(Qb, Kb, Vb, input_ids, ATT, 0);
    // 8. out projection + residual (X = LN2 out) -> H  ("r")
    gemm_mma<<<gProj, 256, SB>>>(ATT, out2_w, out2_b, X, H, MTOK, DM, DM, 0);
    // 9. LN3 -> X
    ln_kernel<<<MTOK, 256>>>(H, ln3_g, ln3_b, X);
    // 10. MLP up + GELU -> HID
    gemm_mma<<<gMlp1, 256, SB>>>(X, mlp_w1, mlp_b1, nullptr, HID, MTOK, DFF, DM, 1);
    // 11. MLP down + bias + residual (H) -> out
    gemm_mma<<<gProj, 256, SB>>>(HID, mlp_w2, mlp_b2, H, out, MTOK, DM, DFF, 0);
}

// round 8
// speedup vs baseline: 3.1666x; 1.0895x over previous
#include <cuda_runtime.h>
#include <math.h>
#include <stdint.h>

// ---------------------------------------------------------------------------
// Problem constants
// ---------------------------------------------------------------------------
#define BB    2
#define SS    2048
#define DM    1024
#define HH    16
#define DHD   64
#define MTOK  (BB*SS)          // 4096 token rows
#define DFF   4096
#define NEGBIG (-1000000000.0f)

// ---------------------------------------------------------------------------
// Scratch (static device globals; no allocations allowed)
// ---------------------------------------------------------------------------
__device__ float g_X  [MTOK*DM];            // LN out, exact (residual use)
__device__ float g_XR [MTOK*DM];            // LN out, tf32-rounded (GEMM A)
__device__ float g_ER [MTOK*DM];            // input_embedding, rounded
__device__ float g_Q  [MTOK*DM];
__device__ float g_K  [MTOK*DM];
__device__ float g_V  [MTOK*DM];
__device__ float g_ATT[MTOK*DM];
__device__ float g_H  [MTOK*DM];
__device__ float g_HID[(size_t)MTOK*DFF];
__device__ float g_WT [16*1024*1024];       // tf32-rounded weights

// ---------------------------------------------------------------------------
// Helpers
// ---------------------------------------------------------------------------
__device__ __forceinline__ float tf32r(float x) {
    float y;
    asm("cvt.rna.tf32.f32 %0, %1;" : "=f"(y) : "f"(x));
    return y;
}

__device__ __forceinline__ void mma_tf32(float* d, const uint32_t* a,
                                         const uint32_t* b) {
    asm volatile(
        "mma.sync.aligned.m16n8k8.row.col.f32.tf32.tf32.f32 "
        "{%0,%1,%2,%3}, {%4,%5,%6,%7}, {%8,%9}, {%0,%1,%2,%3};"
        : "+f"(d[0]), "+f"(d[1]), "+f"(d[2]), "+f"(d[3])
        : "r"(a[0]), "r"(a[1]), "r"(a[2]), "r"(a[3]), "r"(b[0]), "r"(b[1]));
}

__device__ __forceinline__ uint32_t smem_u32(const void* p) {
    uint32_t a;
    asm("{ .reg .u64 t; cvta.to.shared.u64 t, %1; cvt.u32.u64 %0, t; }"
        : "=r"(a) : "l"(p));
    return a;
}
__device__ __forceinline__ void cp16(uint32_t dst, const void* src) {
    asm volatile("cp.async.cg.shared.global [%0], [%1], 16;"
                 :: "r"(dst), "l"(src));
}
#define CP_COMMIT() asm volatile("cp.async.commit_group;" ::: "memory")
#define CP_WAIT(n)  asm volatile("cp.async.wait_group %0;" :: "n"(n) : "memory")

// ---------------------------------------------------------------------------
// Elementwise tf32 rounding (float4 vectorized), n divisible by 1024
// ---------------------------------------------------------------------------
__global__ void round_kernel(const float* __restrict__ in,
                             float* __restrict__ out, int n4) {
    int i = blockIdx.x * 256 + threadIdx.x;
    if (i < n4) {
        float4 v = ((const float4*)in)[i];
        v.x = tf32r(v.x); v.y = tf32r(v.y);
        v.z = tf32r(v.z); v.w = tf32r(v.w);
        ((float4*)out)[i] = v;
    }
}

// ---------------------------------------------------------------------------
// Block reduction for (sum, sumsq), blockDim.x == 256
// ---------------------------------------------------------------------------
__device__ __forceinline__ void block_reduce_2(float& s, float& q) {
    __shared__ float sh_s[8], sh_q[8];
    int lane = threadIdx.x & 31, w = threadIdx.x >> 5;
#pragma unroll
    for (int o = 16; o > 0; o >>= 1) {
        s += __shfl_down_sync(0xffffffffu, s, o);
        q += __shfl_down_sync(0xffffffffu, q, o);
    }
    if (lane == 0) { sh_s[w] = s; sh_q[w] = q; }
    __syncthreads();
    if (w == 0) {
        s = (lane < 8) ? sh_s[lane] : 0.f;
        q = (lane < 8) ? sh_q[lane] : 0.f;
#pragma unroll
        for (int o = 4; o > 0; o >>= 1) {
            s += __shfl_down_sync(0xffffffffu, s, o);
            q += __shfl_down_sync(0xffffffffu, q, o);
        }
        if (lane == 0) { sh_s[0] = s; sh_q[0] = q; }
    }
    __syncthreads();
    s = sh_s[0]; q = sh_q[0];
}

// ---------------------------------------------------------------------------
// Embedding gather + positional + LayerNorm; writes exact + rounded copies
// ---------------------------------------------------------------------------
__global__ void embed_ln_kernel(const int* __restrict__ tgt_ids,
                                const float* __restrict__ tok_emb,
                                const float* __restrict__ pos_emb,
                                const float* __restrict__ gam,
                                const float* __restrict__ bet,
                                float* __restrict__ out,
                                float* __restrict__ out_r) {
    int row = blockIdx.x;
    int s   = row & (SS - 1);
    int tok = tgt_ids[row];
    const float* te = tok_emb + (size_t)tok * DM;
    const float* pe = pos_emb + (size_t)s   * DM;
    float v[4]; float sum = 0.f, sq = 0.f;
#pragma unroll
    for (int i = 0; i < 4; i++) {
        int c = threadIdx.x + i * 256;
        float x = te[c] + pe[c];
        v[i] = x; sum += x; sq += x * x;
    }
    block_reduce_2(sum, sq);
    float mu  = sum * (1.f / DM);
    float var = sq * (1.f / DM) - mu * mu;
    float rs  = rsqrtf(var + 1e-5f);
    float* o  = out   + (size_t)row * DM;
    float* orr = out_r + (size_t)row * DM;
#pragma unroll
    for (int i = 0; i < 4; i++) {
        int c = threadIdx.x + i * 256;
        float y = (v[i] - mu) * rs * gam[c] + bet[c];
        o[c] = y;
        orr[c] = tf32r(y);
    }
}

// ---------------------------------------------------------------------------
// LayerNorm; writes exact + rounded copies
// ---------------------------------------------------------------------------
__global__ void ln_kernel(const float* __restrict__ in,
                          const float* __restrict__ gam,
                          const float* __restrict__ bet,
                          float* __restrict__ out,
                          float* __restrict__ out_r) {
    int row = blockIdx.x;
    const float* ip = in + (size_t)row * DM;
    float v[4]; float sum = 0.f, sq = 0.f;
#pragma unroll
    for (int i = 0; i < 4; i++) {
        int c = threadIdx.x + i * 256;
        float x = ip[c];
        v[i] = x; sum += x; sq += x * x;
    }
    block_reduce_2(sum, sq);
    float mu  = sum * (1.f / DM);
    float var = sq * (1.f / DM) - mu * mu;
    float rs  = rsqrtf(var + 1e-5f);
    float* o  = out   + (size_t)row * DM;
    float* orr = out_r + (size_t)row * DM;
#pragma unroll
    for (int i = 0; i < 4; i++) {
        int c = threadIdx.x + i * 256;
        float y = (v[i] - mu) * rs * gam[c] + bet[c];
        o[c] = y;
        orr[c] = tf32r(y);
    }
}

// ---------------------------------------------------------------------------
// TF32 mma.sync GEMM v3: operands PRE-ROUNDED in gmem (no cvt in mainloop).
// C[M,N] = A[M,K] @ W[K,N] + bias (+res) (gelu opt) (round_out opt)
// 128x128 tile, BK=32, 256 threads, 8 warps (2m x 4n), 2-stage cp.async.
// ---------------------------------------------------------------------------
#define BKT    32
#define ASPAD  36
#define BSPAD  132
#define A_STAGE (128 * ASPAD)
#define B_STAGE (BKT * BSPAD)
#define STAGE_F (A_STAGE + B_STAGE)
#define GEMM_SMEM_BYTES (2 * STAGE_F * 4)

__global__ __launch_bounds__(256) void gemm_mma(
    const float* __restrict__ A, const float* __restrict__ W,
    const float* __restrict__ bias, const float* __restrict__ res,
    float* __restrict__ C, int M, int N, int K, int gelu, int round_out) {
    extern __shared__ float sm[];
    float* Af[2] = { sm,           sm + STAGE_F };
    float* Bf[2] = { sm + A_STAGE, sm + STAGE_F + A_STAGE };
    uint32_t aU[2] = { smem_u32(Af[0]), smem_u32(Af[1]) };
    uint32_t bU[2] = { smem_u32(Bf[0]), smem_u32(Bf[1]) };

    int tid  = threadIdx.x;
    int wid  = tid >> 5, lane = tid & 31;
    int gid  = lane >> 2, tig = lane & 3;
    int m_off = (wid >> 2) * 64;
    int n_off = (wid & 3) * 32;
    int bm = blockIdx.y * 128, bn = blockIdx.x * 128;

    float acc[4][4][4];
#pragma unroll
    for (int i = 0; i < 4; i++)
#pragma unroll
        for (int j = 0; j < 4; j++)
#pragma unroll
            for (int k = 0; k < 4; k++) acc[i][j][k] = 0.f;

    const int T = K / BKT;

    {
#pragma unroll
        for (int i = 0; i < 4; i++) {
            int idx = tid + i * 256;
            int r = idx >> 3, c4 = idx & 7;
            cp16(aU[0] + (uint32_t)(r * ASPAD + c4 * 4) * 4,
                 A + (size_t)(bm + r) * K + c4 * 4);
        }
#pragma unroll
        for (int i = 0; i < 4; i++) {
            int idx = tid + i * 256;
            int r = idx >> 5, c4 = idx & 31;
            cp16(bU[0] + (uint32_t)(r * BSPAD + c4 * 4) * 4,
                 W + (size_t)r * N + bn + c4 * 4);
        }
        CP_COMMIT();
    }

    for (int t = 0; t < T; t++) {
        int cur = t & 1;
        if (t + 1 < T) {
            int nxt = cur ^ 1;
            int k0 = (t + 1) * BKT;
#pragma unroll
            for (int i = 0; i < 4; i++) {
                int idx = tid + i * 256;
                int r = idx >> 3, c4 = idx & 7;
                cp16(aU[nxt] + (uint32_t)(r * ASPAD + c4 * 4) * 4,
                     A + (size_t)(bm + r) * K + k0 + c4 * 4);
            }
#pragma unroll
            for (int i = 0; i < 4; i++) {
                int idx = tid + i * 256;
                int r = idx >> 5, c4 = idx & 31;
                cp16(bU[nxt] + (uint32_t)(r * BSPAD + c4 * 4) * 4,
                     W + (size_t)(k0 + r) * N + bn + c4 * 4);
            }
            CP_COMMIT();
            CP_WAIT(1);
        } else {
            CP_WAIT(0);
        }
        __syncthreads();

        const uint32_t* Ac = (const uint32_t*)Af[cur];
        const uint32_t* Bc = (const uint32_t*)Bf[cur];
#pragma unroll
        for (int ks = 0; ks < 4; ks++) {
            int k = ks * 8;
            uint32_t a[4][4], b[4][2];
#pragma unroll
            for (int mf = 0; mf < 4; mf++) {
                const uint32_t* p = Ac + (m_off + mf * 16 + gid) * ASPAD + k + tig;
                a[mf][0] = p[0];
                a[mf][1] = p[8 * ASPAD];
                a[mf][2] = p[4];
                a[mf][3] = p[8 * ASPAD + 4];
            }
#pragma unroll
            for (int nf = 0; nf < 4; nf++) {
                const uint32_t* p = Bc + (k + tig) * BSPAD + n_off + nf * 8 + gid;
                b[nf][0] = p[0];
                b[nf][1] = p[4 * BSPAD];
            }
#pragma unroll
            for (int mf = 0; mf < 4; mf++)
#pragma unroll
                for (int nf = 0; nf < 4; nf++)
                    mma_tf32(acc[mf][nf], a[mf], b[nf]);
        }
        __syncthreads();
    }

#pragma unroll
    for (int mf = 0; mf < 4; mf++) {
        int row0 = bm + m_off + mf * 16 + gid;
        int row1 = row0 + 8;
#pragma unroll
        for (int nf = 0; nf < 4; nf++) {
            int col = bn + n_off + nf * 8 + 2 * tig;
            float b0 = bias[col], b1 = bias[col + 1];
            float v0 = acc[mf][nf][0] + b0;
            float v1 = acc[mf][nf][1] + b1;
            float v2 = acc[mf][nf][2] + b0;
            float v3 = acc[mf][nf][3] + b1;
            if (res) {
                v0 += res[(size_t)row0 * N + col];
                v1 += res[(size_t)row0 * N + col + 1];
                v2 += res[(size_t)row1 * N + col];
                v3 += res[(size_t)row1 * N + col + 1];
            }
            if (gelu) {
                v0 = 0.5f * v0 * (1.0f + erff(v0 * 0.70710678118654752f));
                v1 = 0.5f * v1 * (1.0f + erff(v1 * 0.70710678118654752f));
                v2 = 0.5f * v2 * (1.0f + erff(v2 * 0.70710678118654752f));
                v3 = 0.5f * v3 * (1.0f + erff(v3 * 0.70710678118654752f));
            }
            if (round_out) {
                v0 = tf32r(v0); v1 = tf32r(v1);
                v2 = tf32r(v2); v3 = tf32r(v3);
            }
            *(float2*)(C + (size_t)row0 * N + col) = make_float2(v0, v1);
            *(float2*)(C + (size_t)row1 * N + col) = make_float2(v2, v3);
        }
    }
}

// ---------------------------------------------------------------------------
// Tensor-core flash attention (tf32). Inputs Q/K/V pre-rounded.
// Block = 128 threads (4 warps), 64 query rows. Output written tf32-rounded
// (it feeds only the out-projection GEMM A operand).
// ---------------------------------------------------------------------------
#define APAD 68
#define ATTN_SMEM_BYTES ((3 * 64 * APAD + 64) * 4)

__global__ __launch_bounds__(128) void attn_tc(
    const float* __restrict__ Q, const float* __restrict__ Kb,
    const float* __restrict__ Vb, const int* __restrict__ ids,
    float* __restrict__ O, int causal) {
    extern __shared__ float sm[];
    float* Ks = sm;                 // [64][APAD]
    float* Vt = sm + 64 * APAD;     // [64][APAD]  V^T (dh, key)
    float* Ps = sm + 2 * 64 * APAD; // [64][APAD]
    float* pm = sm + 3 * 64 * APAD; // [64]

    int b   = blockIdx.y >> 4;
    int h   = blockIdx.y & 15;
    int q0  = blockIdx.x * 64;
    int tid = threadIdx.x;
    int wid = tid >> 5, lane = tid & 31;
    int gid = lane >> 2, tig = lane & 3;
    int lrow = wid * 16 + gid;
    int grow = q0 + lrow;

    float qf[8][4];
    const float* qb0 = Q + ((size_t)(b * SS + grow)) * DM + h * DHD;
    const float* qb8 = qb0 + 8 * DM;
#pragma unroll
    for (int ks = 0; ks < 8; ks++) {
        qf[ks][0] = qb0[ks * 8 + tig];
        qf[ks][1] = qb8[ks * 8 + tig];
        qf[ks][2] = qb0[ks * 8 + tig + 4];
        qf[ks][3] = qb8[ks * 8 + tig + 4];
    }

    float of[8][4];
#pragma unroll
    for (int i = 0; i < 8; i++)
#pragma unroll
        for (int j = 0; j < 4; j++) of[i][j] = 0.f;
    float m0 = -1e30f, m1 = -1e30f, l0 = 0.f, l1 = 0.f;

    int ntiles = causal ? (blockIdx.x + 1) : (SS / 64);
    for (int t = 0; t < ntiles; t++) {
        int kbase = t * 64;
#pragma unroll
        for (int i = 0; i < 8; i++) {
            int e  = tid + i * 128;
            int r  = e >> 4, c4 = (e & 15) * 4;
            size_t goff = ((size_t)(b * SS + kbase + r)) * DM + h * DHD + c4;
            float4 kv = *(const float4*)(Kb + goff);
            float4 vv = *(const float4*)(Vb + goff);
            *(float4*)(Ks + r * APAD + c4) = kv;
            Vt[(c4 + 0) * APAD + r] = vv.x;
            Vt[(c4 + 1) * APAD + r] = vv.y;
            Vt[(c4 + 2) * APAD + r] = vv.z;
            Vt[(c4 + 3) * APAD + r] = vv.w;
        }
        if (tid < 64)
            pm[tid] = (ids[b * SS + kbase + tid] == 0) ? NEGBIG : 0.f;
        __syncthreads();

        float sf[8][4];
#pragma unroll
        for (int nf = 0; nf < 8; nf++) {
            sf[nf][0] = 0.f; sf[nf][1] = 0.f; sf[nf][2] = 0.f; sf[nf][3] = 0.f;
#pragma unroll
            for (int ks = 0; ks < 8; ks++) {
                uint32_t bf[2];
                const float* p = Ks + (nf * 8 + gid) * APAD + ks * 8 + tig;
                bf[0] = __float_as_uint(p[0]);
                bf[1] = __float_as_uint(p[4]);
                mma_tf32(sf[nf], (const uint32_t*)qf[ks], bf);
            }
        }

        float tmax0 = -1e30f, tmax1 = -1e30f;
#pragma unroll
        for (int nf = 0; nf < 8; nf++) {
            int lc0 = nf * 8 + 2 * tig, lc1 = lc0 + 1;
            float s0 = sf[nf][0] * 0.125f + pm[lc0];
            float s1 = sf[nf][1] * 0.125f + pm[lc1];
            float s2 = sf[nf][2] * 0.125f + pm[lc0];
            float s3 = sf[nf][3] * 0.125f + pm[lc1];
            if (causal) {
                int g0 = kbase + lc0, g1 = kbase + lc1;
                if (g0 > grow)     s0 = -1e30f;
                if (g1 > grow)     s1 = -1e30f;
                if (g0 > grow + 8) s2 = -1e30f;
                if (g1 > grow + 8) s3 = -1e30f;
            }
            sf[nf][0] = s0; sf[nf][1] = s1; sf[nf][2] = s2; sf[nf][3] = s3;
            tmax0 = fmaxf(tmax0, fmaxf(s0, s1));
            tmax1 = fmaxf(tmax1, fmaxf(s2, s3));
        }
        tmax0 = fmaxf(tmax0, __shfl_xor_sync(0xffffffffu, tmax0, 1));
        tmax0 = fmaxf(tmax0, __shfl_xor_sync(0xffffffffu, tmax0, 2));
        tmax1 = fmaxf(tmax1, __shfl_xor_sync(0xffffffffu, tmax1, 1));
        tmax1 = fmaxf(tmax1, __shfl_xor_sync(0xffffffffu, tmax1, 2));

        float nm0 = fmaxf(m0, tmax0), nm1 = fmaxf(m1, tmax1);
        float sc0 = __expf(m0 - nm0), sc1 = __expf(m1 - nm1);
        m0 = nm0; m1 = nm1;

        float ts0 = 0.f, ts1 = 0.f;
        float* pr0 = Ps + lrow * APAD;
        float* pr1 = Ps + (lrow + 8) * APAD;
#pragma unroll
        for (int nf = 0; nf < 8; nf++) {
            int lc0 = nf * 8 + 2 * tig;
            float p0 = __expf(sf[nf][0] - nm0);
            float p1 = __expf(sf[nf][1] - nm0);
            float p2 = __expf(sf[nf][2] - nm1);
            float p3 = __expf(sf[nf][3] - nm1);
            ts0 += p0 + p1; ts1 += p2 + p3;
            pr0[lc0]     = tf32r(p0);
            pr0[lc0 + 1] = tf32r(p1);
            pr1[lc0]     = tf32r(p2);
            pr1[lc0 + 1] = tf32r(p3);
            of[nf][0] *= sc0; of[nf][1] *= sc0;
            of[nf][2] *= sc1; of[nf][3] *= sc1;
        }
        ts0 += __shfl_xor_sync(0xffffffffu, ts0, 1);
        ts0 += __shfl_xor_sync(0xffffffffu, ts0, 2);
        ts1 += __shfl_xor_sync(0xffffffffu, ts1, 1);
        ts1 += __shfl_xor_sync(0xffffffffu, ts1, 2);
        l0 = l0 * sc0 + ts0;
        l1 = l1 * sc1 + ts1;
        __syncwarp();

#pragma unroll
        for (int ks = 0; ks < 8; ks++) {
            uint32_t af[4];
            af[0] = __float_as_uint(pr0[ks * 8 + tig]);
            af[1] = __float_as_uint(pr1[ks * 8 + tig]);
            af[2] = __float_as_uint(pr0[ks * 8 + tig + 4]);
            af[3] = __float_as_uint(pr1[ks * 8 + tig + 4]);
#pragma unroll
            for (int nf = 0; nf < 8; nf++) {
                uint32_t bf[2];
                const float* p = Vt + (nf * 8 + gid) * APAD + ks * 8 + tig;
                bf[0] = __float_as_uint(p[0]);
                bf[1] = __float_as_uint(p[4]);
                mma_tf32(of[nf], af, bf);
            }
        }
        __syncthreads();
    }

    float inv0 = 1.f / l0, inv1 = 1.f / l1;
    float* ob0 = O + ((size_t)(b * SS + grow)) * DM + h * DHD;
    float* ob8 = ob0 + 8 * DM;
#pragma unroll
    for (int nf = 0; nf < 8; nf++) {
        int col = nf * 8 + 2 * tig;
        *(float2*)(ob0 + col) = make_float2(tf32r(of[nf][0] * inv0),
                                            tf32r(of[nf][1] * inv0));
        *(float2*)(ob8 + col) = make_float2(tf32r(of[nf][2] * inv1),
                                            tf32r(of[nf][3] * inv1));
    }
}

// ---------------------------------------------------------------------------
// Launch
// ---------------------------------------------------------------------------
extern "C" void kernel_launch(void* const* d_in, const int* in_sizes, int n_in,
                              void* d_out, int out_size) {
    const float* input_embedding = (const float*)d_in[0];
    const int*   input_ids       = (const int*)d_in[1];
    const int*   target_ids      = (const int*)d_in[2];
    const float* tok_emb = (const float*)d_in[3];
    const float* pos_emb = (const float*)d_in[4];
    const float* ln1_g = (const float*)d_in[5];
    const float* ln1_b = (const float*)d_in[6];
    const float* q1_w = (const float*)d_in[7];
    const float* q1_b = (const float*)d_in[8];
    const float* k1_w = (const float*)d_in[9];
    const float* k1_b = (const float*)d_in[10];
    const float* v1_w = (const float*)d_in[11];
    const float* v1_b = (const float*)d_in[12];
    const float* out1_w = (const float*)d_in[13];
    const float* out1_b = (const float*)d_in[14];
    const float* ln2_g = (const float*)d_in[15];
    const float* ln2_b = (const float*)d_in[16];
    const float* q2_w = (const float*)d_in[17];
    const float* q2_b = (const float*)d_in[18];
    const float* k2_w = (const float*)d_in[19];
    const float* k2_b = (const float*)d_in[20];
    const float* v2_w = (const float*)d_in[21];
    const float* v2_b = (const float*)d_in[22];
    const float* out2_w = (const float*)d_in[23];
    const float* out2_b = (const float*)d_in[24];
    const float* ln3_g = (const float*)d_in[25];
    const float* ln3_b = (const float*)d_in[26];
    const float* mlp_w1 = (const float*)d_in[27];
    const float* mlp_b1 = (const float*)d_in[28];
    const float* mlp_w2 = (const float*)d_in[29];
    const float* mlp_b2 = (const float*)d_in[30];
    float* out = (float*)d_out;

    static float *X = nullptr, *XR = nullptr, *ER = nullptr,
                 *Qb = nullptr, *Kb = nullptr, *Vb = nullptr,
                 *ATT = nullptr, *H = nullptr, *HID = nullptr, *WT = nullptr;
    static bool attr_done = false;
    if (!X) {
        cudaGetSymbolAddress((void**)&X,   g_X);
        cudaGetSymbolAddress((void**)&XR,  g_XR);
        cudaGetSymbolAddress((void**)&ER,  g_ER);
        cudaGetSymbolAddress((void**)&Qb,  g_Q);
        cudaGetSymbolAddress((void**)&Kb,  g_K);
        cudaGetSymbolAddress((void**)&Vb,  g_V);
        cudaGetSymbolAddress((void**)&ATT, g_ATT);
        cudaGetSymbolAddress((void**)&H,   g_H);
        cudaGetSymbolAddress((void**)&HID, g_HID);
        cudaGetSymbolAddress((void**)&WT,  g_WT);
    }
    if (!attr_done) {
        cudaFuncSetAttribute(gemm_mma, cudaFuncAttributeMaxDynamicSharedMemorySize,
                             GEMM_SMEM_BYTES);
        cudaFuncSetAttribute(attn_tc, cudaFuncAttributeMaxDynamicSharedMemorySize,
                             ATTN_SMEM_BYTES);
        attr_done = true;
    }

    const size_t MW = 1024 * 1024;
    float* wr_q1 = WT + 0 * MW;
    float* wr_k1 = WT + 1 * MW;
    float* wr_v1 = WT + 2 * MW;
    float* wr_o1 = WT + 3 * MW;
    float* wr_q2 = WT + 4 * MW;
    float* wr_k2 = WT + 5 * MW;
    float* wr_v2 = WT + 6 * MW;
    float* wr_o2 = WT + 7 * MW;
    float* wr_m1 = WT + 8 * MW;
    float* wr_m2 = WT + 12 * MW;

    // round weights + encoder states once per replay
    const int N4_1M = (int)(MW / 4);
    round_kernel<<<N4_1M / 256, 256>>>(q1_w,  wr_q1, N4_1M);
    round_kernel<<<N4_1M / 256, 256>>>(k1_w,  wr_k1, N4_1M);
    round_kernel<<<N4_1M / 256, 256>>>(v1_w,  wr_v1, N4_1M);
    round_kernel<<<N4_1M / 256, 256>>>(out1_w, wr_o1, N4_1M);
    round_kernel<<<N4_1M / 256, 256>>>(q2_w,  wr_q2, N4_1M);
    round_kernel<<<N4_1M / 256, 256>>>(k2_w,  wr_k2, N4_1M);
    round_kernel<<<N4_1M / 256, 256>>>(v2_w,  wr_v2, N4_1M);
    round_kernel<<<N4_1M / 256, 256>>>(out2_w, wr_o2, N4_1M);
    round_kernel<<<4 * N4_1M / 256, 256>>>(mlp_w1, wr_m1, 4 * N4_1M);
    round_kernel<<<4 * N4_1M / 256, 256>>>(mlp_w2, wr_m2, 4 * N4_1M);
    round_kernel<<<4 * N4_1M / 256, 256>>>(input_embedding, ER, 4 * N4_1M);

    dim3 gProj(DM / 128, MTOK / 128);   // (8, 32)
    dim3 gMlp1(DFF / 128, MTOK / 128);  // (32, 32)
    dim3 gAttn(SS / 64, BB * HH);       // (32, 32)
    const int SB = GEMM_SMEM_BYTES;
    const int AB = ATTN_SMEM_BYTES;

    // 1. embedding + LN1 -> X (exact), XR (rounded)
    embed_ln_kernel<<<MTOK, 256>>>(target_ids, tok_emb, pos_emb, ln1_g, ln1_b, X, XR);
    // 2. self-attn QKV projections (rounded outputs — feed attention only)
    gemm_mma<<<gProj, 256, SB>>>(XR, wr_q1, q1_b, nullptr, Qb, MTOK, DM, DM, 0, 1);
    gemm_mma<<<gProj, 256, SB>>>(XR, wr_k1, k1_b, nullptr, Kb, MTOK, DM, DM, 0, 1);
    gemm_mma<<<gProj, 256, SB>>>(XR, wr_v1, v1_b, nullptr, Vb, MTOK, DM, DM, 0, 1);
    // 3. causal self-attention -> ATT (rounded)
    attn_tc<<<gAttn, 128, AB>>>(Qb, Kb, Vb, target_ids, ATT, 1);
    // 4. out projection + residual (X exact) -> H (exact)
    gemm_mma<<<gProj, 256, SB>>>(ATT, wr_o1, out1_b, X, H, MTOK, DM, DM, 0, 0);
    // 5. LN2 -> X, XR
    ln_kernel<<<MTOK, 256>>>(H, ln2_g, ln2_b, X, XR);
    // 6. cross-attn projections
    gemm_mma<<<gProj, 256, SB>>>(XR, wr_q2, q2_b, nullptr, Qb, MTOK, DM, DM, 0, 1);
    gemm_mma<<<gProj, 256, SB>>>(ER, wr_k2, k2_b, nullptr, Kb, MTOK, DM, DM, 0, 1);
    gemm_mma<<<gProj, 256, SB>>>(ER, wr_v2, v2_b, nullptr, Vb, MTOK, DM, DM, 0, 1);
    // 7. cross-attention -> ATT (rounded)
    attn_tc<<<gAttn, 128, AB>>>(Qb, Kb, Vb, input_ids, ATT, 0);
    // 8. out projection + residual (X = LN2 out, exact) -> H ("r", exact)
    gemm_mma<<<gProj, 256, SB>>>(ATT, wr_o2, out2_b, X, H, MTOK, DM, DM, 0, 0);
    // 9. LN3 -> X, XR
    ln_kernel<<<MTOK, 256>>>(H, ln3_g, ln3_b, X, XR);
    // 10. MLP up + GELU -> HID (rounded — feeds MLP-down A only)
    gemm_mma<<<gMlp1, 256, SB>>>(XR, wr_m1, mlp_b1, nullptr, HID, MTOK, DFF, DM, 1, 1);
    // 11. MLP down + bias + residual (H exact) -> out (exact)
    gemm_mma<<<gProj, 256, SB>>>(HID, wr_m2, mlp_b2, H, out, MTOK, DM, DFF, 0, 0);
}

// round 9
// speedup vs baseline: 3.3413x; 1.0552x over previous
#include <cuda_runtime.h>
#include <math.h>
#include <stdint.h>

// ---------------------------------------------------------------------------
// Problem constants
// ---------------------------------------------------------------------------
#define BB    2
#define SS    2048
#define DM    1024
#define HH    16
#define DHD   64
#define MTOK  (BB*SS)          // 4096 token rows
#define DFF   4096
#define NEGBIG (-1000000000.0f)

// ---------------------------------------------------------------------------
// Scratch (static device globals; no allocations allowed)
// ---------------------------------------------------------------------------
__device__ float g_X  [MTOK*DM];            // LN out, exact
__device__ float g_XR [MTOK*DM];            // LN out, tf32-rounded
__device__ float g_ER [MTOK*DM];            // input_embedding, rounded
__device__ float g_QKV[(size_t)MTOK*3*DM];  // packed Q|K|V (self-attn)
__device__ float g_KV [(size_t)MTOK*2*DM];  // packed K|V (cross-attn)
__device__ float g_Q  [MTOK*DM];            // Q2
__device__ float g_ATT[MTOK*DM];
__device__ float g_H  [MTOK*DM];
__device__ float g_HID[(size_t)MTOK*DFF];
__device__ float g_WT [16*1024*1024];       // rounded weights (packed)
__device__ float g_BI [3*DM + 2*DM];        // concat biases qkv1, kv2

// ---------------------------------------------------------------------------
// Helpers
// ---------------------------------------------------------------------------
__device__ __forceinline__ float tf32r(float x) {
    float y;
    asm("cvt.rna.tf32.f32 %0, %1;" : "=f"(y) : "f"(x));
    return y;
}

__device__ __forceinline__ void mma_tf32(float* d, const uint32_t* a,
                                         const uint32_t* b) {
    asm volatile(
        "mma.sync.aligned.m16n8k8.row.col.f32.tf32.tf32.f32 "
        "{%0,%1,%2,%3}, {%4,%5,%6,%7}, {%8,%9}, {%0,%1,%2,%3};"
        : "+f"(d[0]), "+f"(d[1]), "+f"(d[2]), "+f"(d[3])
        : "r"(a[0]), "r"(a[1]), "r"(a[2]), "r"(a[3]), "r"(b[0]), "r"(b[1]));
}

__device__ __forceinline__ uint32_t smem_u32(const void* p) {
    uint32_t a;
    asm("{ .reg .u64 t; cvta.to.shared.u64 t, %1; cvt.u32.u64 %0, t; }"
        : "=r"(a) : "l"(p));
    return a;
}
__device__ __forceinline__ void cp16(uint32_t dst, const void* src) {
    asm volatile("cp.async.cg.shared.global [%0], [%1], 16;"
                 :: "r"(dst), "l"(src));
}
#define CP_COMMIT() asm volatile("cp.async.commit_group;" ::: "memory")
#define CP_WAIT(n)  asm volatile("cp.async.wait_group %0;" :: "n"(n) : "memory")

// ---------------------------------------------------------------------------
// tf32 rounding with optional column-concat relayout.
// in: [R][srcN] row-major; out[r][base + c] with row stride dstN.
// n4 = R*srcN/4 float4 elements.
// ---------------------------------------------------------------------------
__global__ void round_concat(const float* __restrict__ in,
                             float* __restrict__ out,
                             int n4, int srcN, int dstN, int base) {
    int i = blockIdx.x * 256 + threadIdx.x;
    if (i < n4) {
        float4 v = ((const float4*)in)[i];
        v.x = tf32r(v.x); v.y = tf32r(v.y);
        v.z = tf32r(v.z); v.w = tf32r(v.w);
        int e = i * 4;
        int r = e / srcN, c = e - r * srcN;
        *(float4*)(out + (size_t)r * dstN + base + c) = v;
    }
}

// concat biases: bqkv[0:3D) = q1_b|k1_b|v1_b ; bkv2 at offset 3D = k2_b|v2_b
__global__ void bias_concat(const float* q1b, const float* k1b, const float* v1b,
                            const float* k2b, const float* v2b, float* out) {
    int i = blockIdx.x * 256 + threadIdx.x;
    if (i < DM)            out[i]           = q1b[i];
    else if (i < 2 * DM)   out[i]           = k1b[i - DM];
    else if (i < 3 * DM)   out[i]           = v1b[i - 2 * DM];
    else if (i < 4 * DM)   out[i]           = k2b[i - 3 * DM];
    else if (i < 5 * DM)   out[i]           = v2b[i - 4 * DM];
}

// ---------------------------------------------------------------------------
// Block reduction for (sum, sumsq), blockDim.x == 256
// ---------------------------------------------------------------------------
__device__ __forceinline__ void block_reduce_2(float& s, float& q) {
    __shared__ float sh_s[8], sh_q[8];
    int lane = threadIdx.x & 31, w = threadIdx.x >> 5;
#pragma unroll
    for (int o = 16; o > 0; o >>= 1) {
        s += __shfl_down_sync(0xffffffffu, s, o);
        q += __shfl_down_sync(0xffffffffu, q, o);
    }
    if (lane == 0) { sh_s[w] = s; sh_q[w] = q; }
    __syncthreads();
    if (w == 0) {
        s = (lane < 8) ? sh_s[lane] : 0.f;
        q = (lane < 8) ? sh_q[lane] : 0.f;
#pragma unroll
        for (int o = 4; o > 0; o >>= 1) {
            s += __shfl_down_sync(0xffffffffu, s, o);
            q += __shfl_down_sync(0xffffffffu, q, o);
        }
        if (lane == 0) { sh_s[0] = s; sh_q[0] = q; }
    }
    __syncthreads();
    s = sh_s[0]; q = sh_q[0];
}

// ---------------------------------------------------------------------------
// Embedding gather + positional + LayerNorm; exact + rounded outputs
// ---------------------------------------------------------------------------
__global__ void embed_ln_kernel(const int* __restrict__ tgt_ids,
                                const float* __restrict__ tok_emb,
                                const float* __restrict__ pos_emb,
                                const float* __restrict__ gam,
                                const float* __restrict__ bet,
                                float* __restrict__ out,
                                float* __restrict__ out_r) {
    int row = blockIdx.x;
    int s   = row & (SS - 1);
    int tok = tgt_ids[row];
    const float* te = tok_emb + (size_t)tok * DM;
    const float* pe = pos_emb + (size_t)s   * DM;
    float v[4]; float sum = 0.f, sq = 0.f;
#pragma unroll
    for (int i = 0; i < 4; i++) {
        int c = threadIdx.x + i * 256;
        float x = te[c] + pe[c];
        v[i] = x; sum += x; sq += x * x;
    }
    block_reduce_2(sum, sq);
    float mu  = sum * (1.f / DM);
    float var = sq * (1.f / DM) - mu * mu;
    float rs  = rsqrtf(var + 1e-5f);
    float* o   = out   + (size_t)row * DM;
    float* orr = out_r + (size_t)row * DM;
#pragma unroll
    for (int i = 0; i < 4; i++) {
        int c = threadIdx.x + i * 256;
        float y = (v[i] - mu) * rs * gam[c] + bet[c];
        o[c] = y;
        orr[c] = tf32r(y);
    }
}

// ---------------------------------------------------------------------------
// LayerNorm; exact + rounded outputs
// ---------------------------------------------------------------------------
__global__ void ln_kernel(const float* __restrict__ in,
                          const float* __restrict__ gam,
                          const float* __restrict__ bet,
                          float* __restrict__ out,
                          float* __restrict__ out_r) {
    int row = blockIdx.x;
    const float* ip = in + (size_t)row * DM;
    float v[4]; float sum = 0.f, sq = 0.f;
#pragma unroll
    for (int i = 0; i < 4; i++) {
        int c = threadIdx.x + i * 256;
        float x = ip[c];
        v[i] = x; sum += x; sq += x * x;
    }
    block_reduce_2(sum, sq);
    float mu  = sum * (1.f / DM);
    float var = sq * (1.f / DM) - mu * mu;
    float rs  = rsqrtf(var + 1e-5f);
    float* o   = out   + (size_t)row * DM;
    float* orr = out_r + (size_t)row * DM;
#pragma unroll
    for (int i = 0; i < 4; i++) {
        int c = threadIdx.x + i * 256;
        float y = (v[i] - mu) * rs * gam[c] + bet[c];
        o[c] = y;
        orr[c] = tf32r(y);
    }
}

// ---------------------------------------------------------------------------
// TF32 mma.sync GEMM v4: 128x128 CTA tile, 128 threads (4 warps, 64x64 each),
// BK=32, 2-stage cp.async. Operands pre-rounded in gmem.
// ---------------------------------------------------------------------------
#define BKT    32
#define ASPAD  36
#define BSPAD  132
#define A_STAGE (128 * ASPAD)
#define B_STAGE (BKT * BSPAD)
#define STAGE_F (A_STAGE + B_STAGE)
#define GEMM_SMEM_BYTES (2 * STAGE_F * 4)

__global__ __launch_bounds__(128) void gemm_mma(
    const float* __restrict__ A, const float* __restrict__ W,
    const float* __restrict__ bias, const float* __restrict__ res,
    float* __restrict__ C, int M, int N, int K, int gelu, int round_out) {
    extern __shared__ float sm[];
    float* Af[2] = { sm,           sm + STAGE_F };
    float* Bf[2] = { sm + A_STAGE, sm + STAGE_F + A_STAGE };
    uint32_t aU[2] = { smem_u32(Af[0]), smem_u32(Af[1]) };
    uint32_t bU[2] = { smem_u32(Bf[0]), smem_u32(Bf[1]) };

    int tid  = threadIdx.x;
    int wid  = tid >> 5, lane = tid & 31;
    int gid  = lane >> 2, tig = lane & 3;
    int m_off = (wid >> 1) * 64;
    int n_off = (wid & 1) * 64;
    int bm = blockIdx.y * 128, bn = blockIdx.x * 128;

    float acc[4][8][4];
#pragma unroll
    for (int i = 0; i < 4; i++)
#pragma unroll
        for (int j = 0; j < 8; j++)
#pragma unroll
            for (int k = 0; k < 4; k++) acc[i][j][k] = 0.f;

    const int T = K / BKT;

    {
#pragma unroll
        for (int i = 0; i < 8; i++) {
            int idx = tid + i * 128;
            int r = idx >> 3, c4 = idx & 7;
            cp16(aU[0] + (uint32_t)(r * ASPAD + c4 * 4) * 4,
                 A + (size_t)(bm + r) * K + c4 * 4);
        }
#pragma unroll
        for (int i = 0; i < 8; i++) {
            int idx = tid + i * 128;
            int r = idx >> 5, c4 = idx & 31;
            cp16(bU[0] + (uint32_t)(r * BSPAD + c4 * 4) * 4,
                 W + (size_t)r * N + bn + c4 * 4);
        }
        CP_COMMIT();
    }

    for (int t = 0; t < T; t++) {
        int cur = t & 1;
        if (t + 1 < T) {
            int nxt = cur ^ 1;
            int k0 = (t + 1) * BKT;
#pragma unroll
            for (int i = 0; i < 8; i++) {
                int idx = tid + i * 128;
                int r = idx >> 3, c4 = idx & 7;
                cp16(aU[nxt] + (uint32_t)(r * ASPAD + c4 * 4) * 4,
                     A + (size_t)(bm + r) * K + k0 + c4 * 4);
            }
#pragma unroll
            for (int i = 0; i < 8; i++) {
                int idx = tid + i * 128;
                int r = idx >> 5, c4 = idx & 31;
                cp16(bU[nxt] + (uint32_t)(r * BSPAD + c4 * 4) * 4,
                     W + (size_t)(k0 + r) * N + bn + c4 * 4);
            }
            CP_COMMIT();
            CP_WAIT(1);
        } else {
            CP_WAIT(0);
        }
        __syncthreads();

        const uint32_t* Ac = (const uint32_t*)Af[cur];
        const uint32_t* Bc = (const uint32_t*)Bf[cur];
#pragma unroll
        for (int ks = 0; ks < 4; ks++) {
            int k = ks * 8;
            uint32_t a[4][4], b[8][2];
#pragma unroll
            for (int mf = 0; mf < 4; mf++) {
                const uint32_t* p = Ac + (m_off + mf * 16 + gid) * ASPAD + k + tig;
                a[mf][0] = p[0];
                a[mf][1] = p[8 * ASPAD];
                a[mf][2] = p[4];
                a[mf][3] = p[8 * ASPAD + 4];
            }
#pragma unroll
            for (int nf = 0; nf < 8; nf++) {
                const uint32_t* p = Bc + (k + tig) * BSPAD + n_off + nf * 8 + gid;
                b[nf][0] = p[0];
                b[nf][1] = p[4 * BSPAD];
            }
#pragma unroll
            for (int mf = 0; mf < 4; mf++)
#pragma unroll
                for (int nf = 0; nf < 8; nf++)
                    mma_tf32(acc[mf][nf], a[mf], b[nf]);
        }
        __syncthreads();
    }

#pragma unroll
    for (int mf = 0; mf < 4; mf++) {
        int row0 = bm + m_off + mf * 16 + gid;
        int row1 = row0 + 8;
#pragma unroll
        for (int nf = 0; nf < 8; nf++) {
            int col = bn + n_off + nf * 8 + 2 * tig;
            float b0 = bias[col], b1 = bias[col + 1];
            float v0 = acc[mf][nf][0] + b0;
            float v1 = acc[mf][nf][1] + b1;
            float v2 = acc[mf][nf][2] + b0;
            float v3 = acc[mf][nf][3] + b1;
            if (res) {
                v0 += res[(size_t)row0 * N + col];
                v1 += res[(size_t)row0 * N + col + 1];
                v2 += res[(size_t)row1 * N + col];
                v3 += res[(size_t)row1 * N + col + 1];
            }
            if (gelu) {
                v0 = 0.5f * v0 * (1.0f + erff(v0 * 0.70710678118654752f));
                v1 = 0.5f * v1 * (1.0f + erff(v1 * 0.70710678118654752f));
                v2 = 0.5f * v2 * (1.0f + erff(v2 * 0.70710678118654752f));
                v3 = 0.5f * v3 * (1.0f + erff(v3 * 0.70710678118654752f));
            }
            if (round_out) {
                v0 = tf32r(v0); v1 = tf32r(v1);
                v2 = tf32r(v2); v3 = tf32r(v3);
            }
            *(float2*)(C + (size_t)row0 * N + col) = make_float2(v0, v1);
            *(float2*)(C + (size_t)row1 * N + col) = make_float2(v2, v3);
        }
    }
}

// ---------------------------------------------------------------------------
// Tensor-core flash attention (tf32). Inputs pre-rounded.
// stq / stkv: row strides of Q and K/V buffers (packed layouts supported).
// ---------------------------------------------------------------------------
#define APAD 68
#define ATTN_SMEM_BYTES ((3 * 64 * APAD + 64) * 4)

__global__ __launch_bounds__(128) void attn_tc(
    const float* __restrict__ Q, const float* __restrict__ Kb,
    const float* __restrict__ Vb, const int* __restrict__ ids,
    float* __restrict__ O, int causal, int stq, int stkv) {
    extern __shared__ float sm[];
    float* Ks = sm;
    float* Vt = sm + 64 * APAD;
    float* Ps = sm + 2 * 64 * APAD;
    float* pm = sm + 3 * 64 * APAD;

    int b   = blockIdx.y >> 4;
    int h   = blockIdx.y & 15;
    int q0  = blockIdx.x * 64;
    int tid = threadIdx.x;
    int wid = tid >> 5, lane = tid & 31;
    int gid = lane >> 2, tig = lane & 3;
    int lrow = wid * 16 + gid;
    int grow = q0 + lrow;

    float qf[8][4];
    const float* qb0 = Q + ((size_t)(b * SS + grow)) * stq + h * DHD;
    const float* qb8 = qb0 + (size_t)8 * stq;
#pragma unroll
    for (int ks = 0; ks < 8; ks++) {
        qf[ks][0] = qb0[ks * 8 + tig];
        qf[ks][1] = qb8[ks * 8 + tig];
        qf[ks][2] = qb0[ks * 8 + tig + 4];
        qf[ks][3] = qb8[ks * 8 + tig + 4];
    }

    float of[8][4];
#pragma unroll
    for (int i = 0; i < 8; i++)
#pragma unroll
        for (int j = 0; j < 4; j++) of[i][j] = 0.f;
    float m0 = -1e30f, m1 = -1e30f, l0 = 0.f, l1 = 0.f;

    int ntiles = causal ? (blockIdx.x + 1) : (SS / 64);
    for (int t = 0; t < ntiles; t++) {
        int kbase = t * 64;
#pragma unroll
        for (int i = 0; i < 8; i++) {
            int e  = tid + i * 128;
            int r  = e >> 4, c4 = (e & 15) * 4;
            size_t goff = ((size_t)(b * SS + kbase + r)) * stkv + h * DHD + c4;
            float4 kv = *(const float4*)(Kb + goff);
            float4 vv = *(const float4*)(Vb + goff);
            *(float4*)(Ks + r * APAD + c4) = kv;
            Vt[(c4 + 0) * APAD + r] = vv.x;
            Vt[(c4 + 1) * APAD + r] = vv.y;
            Vt[(c4 + 2) * APAD + r] = vv.z;
            Vt[(c4 + 3) * APAD + r] = vv.w;
        }
        if (tid < 64)
            pm[tid] = (ids[b * SS + kbase + tid] == 0) ? NEGBIG : 0.f;
        __syncthreads();

        float sf[8][4];
#pragma unroll
        for (int nf = 0; nf < 8; nf++) {
            sf[nf][0] = 0.f; sf[nf][1] = 0.f; sf[nf][2] = 0.f; sf[nf][3] = 0.f;
#pragma unroll
            for (int ks = 0; ks < 8; ks++) {
                uint32_t bf[2];
                const float* p = Ks + (nf * 8 + gid) * APAD + ks * 8 + tig;
                bf[0] = __float_as_uint(p[0]);
                bf[1] = __float_as_uint(p[4]);
                mma_tf32(sf[nf], (const uint32_t*)qf[ks], bf);
            }
        }

        float tmax0 = -1e30f, tmax1 = -1e30f;
#pragma unroll
        for (int nf = 0; nf < 8; nf++) {
            int lc0 = nf * 8 + 2 * tig, lc1 = lc0 + 1;
            float s0 = sf[nf][0] * 0.125f + pm[lc0];
            float s1 = sf[nf][1] * 0.125f + pm[lc1];
            float s2 = sf[nf][2] * 0.125f + pm[lc0];
            float s3 = sf[nf][3] * 0.125f + pm[lc1];
            if (causal) {
                int g0 = kbase + lc0, g1 = kbase + lc1;
                if (g0 > grow)     s0 = -1e30f;
                if (g1 > grow)     s1 = -1e30f;
                if (g0 > grow + 8) s2 = -1e30f;
                if (g1 > grow + 8) s3 = -1e30f;
            }
            sf[nf][0] = s0; sf[nf][1] = s1; sf[nf][2] = s2; sf[nf][3] = s3;
            tmax0 = fmaxf(tmax0, fmaxf(s0, s1));
            tmax1 = fmaxf(tmax1, fmaxf(s2, s3));
        }
        tmax0 = fmaxf(tmax0, __shfl_xor_sync(0xffffffffu, tmax0, 1));
        tmax0 = fmaxf(tmax0, __shfl_xor_sync(0xffffffffu, tmax0, 2));
        tmax1 = fmaxf(tmax1, __shfl_xor_sync(0xffffffffu, tmax1, 1));
        tmax1 = fmaxf(tmax1, __shfl_xor_sync(0xffffffffu, tmax1, 2));

        float nm0 = fmaxf(m0, tmax0), nm1 = fmaxf(m1, tmax1);
        float sc0 = __expf(m0 - nm0), sc1 = __expf(m1 - nm1);
        m0 = nm0; m1 = nm1;

        float ts0 = 0.f, ts1 = 0.f;
        float* pr0 = Ps + lrow * APAD;
        float* pr1 = Ps + (lrow + 8) * APAD;
#pragma unroll
        for (int nf = 0; nf < 8; nf++) {
            int lc0 = nf * 8 + 2 * tig;
            float p0 = __expf(sf[nf][0] - nm0);
            float p1 = __expf(sf[nf][1] - nm0);
            float p2 = __expf(sf[nf][2] - nm1);
            float p3 = __expf(sf[nf][3] - nm1);
            ts0 += p0 + p1; ts1 += p2 + p3;
            pr0[lc0]     = tf32r(p0);
            pr0[lc0 + 1] = tf32r(p1);
            pr1[lc0]     = tf32r(p2);
            pr1[lc0 + 1] = tf32r(p3);
            of[nf][0] *= sc0; of[nf][1] *= sc0;
            of[nf][2] *= sc1; of[nf][3] *= sc1;
        }
        ts0 += __shfl_xor_sync(0xffffffffu, ts0, 1);
        ts0 += __shfl_xor_sync(0xffffffffu, ts0, 2);
        ts1 += __shfl_xor_sync(0xffffffffu, ts1, 1);
        ts1 += __shfl_xor_sync(0xffffffffu, ts1, 2);
        l0 = l0 * sc0 + ts0;
        l1 = l1 * sc1 + ts1;
        __syncwarp();

#pragma unroll
        for (int ks = 0; ks < 8; ks++) {
            uint32_t af[4];
            af[0] = __float_as_uint(pr0[ks * 8 + tig]);
            af[1] = __float_as_uint(pr1[ks * 8 + tig]);
            af[2] = __float_as_uint(pr0[ks * 8 + tig + 4]);
            af[3] = __float_as_uint(pr1[ks * 8 + tig + 4]);
#pragma unroll
            for (int nf = 0; nf < 8; nf++) {
                uint32_t bf[2];
                const float* p = Vt + (nf * 8 + gid) * APAD + ks * 8 + tig;
                bf[0] = __float_as_uint(p[0]);
                bf[1] = __float_as_uint(p[4]);
                mma_tf32(of[nf], af, bf);
            }
        }
        __syncthreads();
    }

    float inv0 = 1.f / l0, inv1 = 1.f / l1;
    float* ob0 = O + ((size_t)(b * SS + grow)) * DM + h * DHD;
    float* ob8 = ob0 + 8 * DM;
#pragma unroll
    for (int nf = 0; nf < 8; nf++) {
        int col = nf * 8 + 2 * tig;
        *(float2*)(ob0 + col) = make_float2(tf32r(of[nf][0] * inv0),
                                            tf32r(of[nf][1] * inv0));
        *(float2*)(ob8 + col) = make_float2(tf32r(of[nf][2] * inv1),
                                            tf32r(of[nf][3] * inv1));
    }
}

// ---------------------------------------------------------------------------
// Launch
// ---------------------------------------------------------------------------
extern "C" void kernel_launch(void* const* d_in, const int* in_sizes, int n_in,
                              void* d_out, int out_size) {
    const float* input_embedding = (const float*)d_in[0];
    const int*   input_ids       = (const int*)d_in[1];
    const int*   target_ids      = (const int*)d_in[2];
    const float* tok_emb = (const float*)d_in[3];
    const float* pos_emb = (const float*)d_in[4];
    const float* ln1_g = (const float*)d_in[5];
    const float* ln1_b = (const float*)d_in[6];
    const float* q1_w = (const float*)d_in[7];
    const float* q1_b = (const float*)d_in[8];
    const float* k1_w = (const float*)d_in[9];
    const float* k1_b = (const float*)d_in[10];
    const float* v1_w = (const float*)d_in[11];
    const float* v1_b = (const float*)d_in[12];
    const float* out1_w = (const float*)d_in[13];
    const float* out1_b = (const float*)d_in[14];
    const float* ln2_g = (const float*)d_in[15];
    const float* ln2_b = (const float*)d_in[16];
    const float* q2_w = (const float*)d_in[17];
    const float* q2_b = (const float*)d_in[18];
    const float* k2_w = (const float*)d_in[19];
    const float* k2_b = (const float*)d_in[20];
    const float* v2_w = (const float*)d_in[21];
    const float* v2_b = (const float*)d_in[22];
    const float* out2_w = (const float*)d_in[23];
    const float* out2_b = (const float*)d_in[24];
    const float* ln3_g = (const float*)d_in[25];
    const float* ln3_b = (const float*)d_in[26];
    const float* mlp_w1 = (const float*)d_in[27];
    const float* mlp_b1 = (const float*)d_in[28];
    const float* mlp_w2 = (const float*)d_in[29];
    const float* mlp_b2 = (const float*)d_in[30];
    float* out = (float*)d_out;

    static float *X = nullptr, *XR = nullptr, *ER = nullptr,
                 *QKV = nullptr, *KV = nullptr, *Qb = nullptr,
                 *ATT = nullptr, *H = nullptr, *HID = nullptr,
                 *WT = nullptr, *BI = nullptr;
    static bool attr_done = false;
    if (!X) {
        cudaGetSymbolAddress((void**)&X,   g_X);
        cudaGetSymbolAddress((void**)&XR,  g_XR);
        cudaGetSymbolAddress((void**)&ER,  g_ER);
        cudaGetSymbolAddress((void**)&QKV, g_QKV);
        cudaGetSymbolAddress((void**)&KV,  g_KV);
        cudaGetSymbolAddress((void**)&Qb,  g_Q);
        cudaGetSymbolAddress((void**)&ATT, g_ATT);
        cudaGetSymbolAddress((void**)&H,   g_H);
        cudaGetSymbolAddress((void**)&HID, g_HID);
        cudaGetSymbolAddress((void**)&WT,  g_WT);
        cudaGetSymbolAddress((void**)&BI,  g_BI);
    }
    if (!attr_done) {
        cudaFuncSetAttribute(gemm_mma, cudaFuncAttributeMaxDynamicSharedMemorySize,
                             GEMM_SMEM_BYTES);
        cudaFuncSetAttribute(attn_tc, cudaFuncAttributeMaxDynamicSharedMemorySize,
                             ATTN_SMEM_BYTES);
        attr_done = true;
    }

    const size_t MW = 1024 * 1024;
    float* wr_qkv = WT + 0 * MW;    // [DM][3*DM]
    float* wr_kv2 = WT + 3 * MW;    // [DM][2*DM]
    float* wr_q2  = WT + 5 * MW;
    float* wr_o1  = WT + 6 * MW;
    float* wr_o2  = WT + 7 * MW;
    float* wr_m1  = WT + 8 * MW;
    float* wr_m2  = WT + 12 * MW;
    float* bqkv   = BI;
    float* bkv2   = BI + 3 * DM;

    const int N4 = (int)(MW / 4);
    const int GB = N4 / 256;
    // packed QKV1 weights
    round_concat<<<GB, 256>>>(q1_w, wr_qkv, N4, DM, 3 * DM, 0);
    round_concat<<<GB, 256>>>(k1_w, wr_qkv, N4, DM, 3 * DM, DM);
    round_concat<<<GB, 256>>>(v1_w, wr_qkv, N4, DM, 3 * DM, 2 * DM);
    // packed KV2 weights
    round_concat<<<GB, 256>>>(k2_w, wr_kv2, N4, DM, 2 * DM, 0);
    round_concat<<<GB, 256>>>(v2_w, wr_kv2, N4, DM, 2 * DM, DM);
    // plain rounded weights
    round_concat<<<GB, 256>>>(q2_w,  wr_q2, N4, DM, DM, 0);
    round_concat<<<GB, 256>>>(out1_w, wr_o1, N4, DM, DM, 0);
    round_concat<<<GB, 256>>>(out2_w, wr_o2, N4, DM, DM, 0);
    round_concat<<<4 * GB, 256>>>(mlp_w1, wr_m1, 4 * N4, DFF, DFF, 0);
    round_concat<<<4 * GB, 256>>>(mlp_w2, wr_m2, 4 * N4, DM, DM, 0);
    round_concat<<<4 * GB, 256>>>(input_embedding, ER, 4 * N4, DM, DM, 0);
    bias_concat<<<20, 256>>>(q1_b, k1_b, v1_b, k2_b, v2_b, BI);

    dim3 gQKV(3 * DM / 128, MTOK / 128);   // (24, 32)
    dim3 gKV (2 * DM / 128, MTOK / 128);   // (16, 32)
    dim3 gProj(DM / 128, MTOK / 128);      // (8, 32)
    dim3 gMlp1(DFF / 128, MTOK / 128);     // (32, 32)
    dim3 gAttn(SS / 64, BB * HH);          // (32, 32)
    const int SB = GEMM_SMEM_BYTES;
    const int AB = ATTN_SMEM_BYTES;

    // 1. embedding + LN1 -> X, XR
    embed_ln_kernel<<<MTOK, 256>>>(target_ids, tok_emb, pos_emb, ln1_g, ln1_b, X, XR);
    // 2. fused QKV projection (rounded out)
    gemm_mma<<<gQKV, 128, SB>>>(XR, wr_qkv, bqkv, nullptr, QKV, MTOK, 3 * DM, DM, 0, 1);
    // 3. causal self-attention (packed QKV, stride 3*DM)
    attn_tc<<<gAttn, 128, AB>>>(QKV, QKV + DM, QKV + 2 * DM, target_ids, ATT, 1,
                                3 * DM, 3 * DM);
    // 4. out projection + residual (X) -> H
    gemm_mma<<<gProj, 128, SB>>>(ATT, wr_o1, out1_b, X, H, MTOK, DM, DM, 0, 0);
    // 5. LN2 -> X, XR
    ln_kernel<<<MTOK, 256>>>(H, ln2_g, ln2_b, X, XR);
    // 6. cross-attn projections: Q2 (from XR), fused KV2 (from ER)
    gemm_mma<<<gProj, 128, SB>>>(XR, wr_q2, q2_b, nullptr, Qb, MTOK, DM, DM, 0, 1);
    gemm_mma<<<gKV, 128, SB>>>(ER, wr_kv2, bkv2, nullptr, KV, MTOK, 2 * DM, DM, 0, 1);
    // 7. cross-attention (Q stride DM, KV stride 2*DM)
    attn_tc<<<gAttn, 128, AB>>>(Qb, KV, KV + DM, input_ids, ATT, 0, DM, 2 * DM);
    // 8. out projection + residual (X = LN2 out) -> H
    gemm_mma<<<gProj, 128, SB>>>(ATT, wr_o2, out2_b, X, H, MTOK, DM, DM, 0, 0);
    // 9. LN3 -> X, XR
    ln_kernel<<<MTOK, 256>>>(H, ln3_g, ln3_b, X, XR);
    // 10. MLP up + GELU -> HID (rounded)
    gemm_mma<<<gMlp1, 128, SB>>>(XR, wr_m1, mlp_b1, nullptr, HID, MTOK, DFF, DM, 1, 1);
    // 11. MLP down + bias + residual (H) -> out
    gemm_mma<<<gProj, 128, SB>>>(HID, wr_m2, mlp_b2, H, out, MTOK, DM, DFF, 0, 0);
}

// round 11
// speedup vs baseline: 3.4963x; 1.0464x over previous
#include <cuda_runtime.h>
#include <math.h>
#include <stdint.h>

// ---------------------------------------------------------------------------
// Problem constants
// ---------------------------------------------------------------------------
#define BB    2
#define SS    2048
#define DM    1024
#define HH    16
#define DHD   64
#define MTOK  (BB*SS)          // 4096 token rows
#define DFF   4096
#define NEGBIG (-1000000000.0f)

// ---------------------------------------------------------------------------
// Scratch (static device globals; no allocations allowed)
// ---------------------------------------------------------------------------
__device__ float g_X  [MTOK*DM];            // LN out, exact
__device__ float g_XR [MTOK*DM];            // LN out, tf32-rounded
__device__ float g_ER [MTOK*DM];            // input_embedding, rounded
__device__ float g_QKV[(size_t)MTOK*3*DM];  // packed Q|K|V (self-attn)
__device__ float g_KV [(size_t)MTOK*2*DM];  // packed K|V (cross-attn)
__device__ float g_Q  [MTOK*DM];            // Q2
__device__ float g_ATT[MTOK*DM];
__device__ float g_H  [MTOK*DM];
__device__ float g_HID[(size_t)MTOK*DFF];
__device__ float g_WT [16*1024*1024];       // rounded weights (packed)
__device__ float g_BI [3*DM + 2*DM];        // concat biases qkv1, kv2

// ---------------------------------------------------------------------------
// Helpers
// ---------------------------------------------------------------------------
__device__ __forceinline__ float tf32r(float x) {
    float y;
    asm("cvt.rna.tf32.f32 %0, %1;" : "=f"(y) : "f"(x));
    return y;
}

__device__ __forceinline__ void mma_tf32(float* d, const uint32_t* a,
                                         const uint32_t* b) {
    asm volatile(
        "mma.sync.aligned.m16n8k8.row.col.f32.tf32.tf32.f32 "
        "{%0,%1,%2,%3}, {%4,%5,%6,%7}, {%8,%9}, {%0,%1,%2,%3};"
        : "+f"(d[0]), "+f"(d[1]), "+f"(d[2]), "+f"(d[3])
        : "r"(a[0]), "r"(a[1]), "r"(a[2]), "r"(a[3]), "r"(b[0]), "r"(b[1]));
}

__device__ __forceinline__ uint32_t smem_u32(const void* p) {
    uint32_t a;
    asm("{ .reg .u64 t; cvta.to.shared.u64 t, %1; cvt.u32.u64 %0, t; }"
        : "=r"(a) : "l"(p));
    return a;
}
__device__ __forceinline__ void cp16(uint32_t dst, const void* src) {
    asm volatile("cp.async.cg.shared.global [%0], [%1], 16;"
                 :: "r"(dst), "l"(src));
}
#define CP_COMMIT() asm volatile("cp.async.commit_group;" ::: "memory")
#define CP_WAIT(n)  asm volatile("cp.async.wait_group %0;" :: "n"(n) : "memory")

// ---------------------------------------------------------------------------
// tf32 rounding with optional column-concat relayout.
// ---------------------------------------------------------------------------
__global__ void round_concat(const float* __restrict__ in,
                             float* __restrict__ out,
                             int n4, int srcN, int dstN, int base) {
    int i = blockIdx.x * 256 + threadIdx.x;
    if (i < n4) {
        float4 v = ((const float4*)in)[i];
        v.x = tf32r(v.x); v.y = tf32r(v.y);
        v.z = tf32r(v.z); v.w = tf32r(v.w);
        int e = i * 4;
        int r = e / srcN, c = e - r * srcN;
        *(float4*)(out + (size_t)r * dstN + base + c) = v;
    }
}

// concat biases: out[0:3D) = q1_b|k1_b|v1_b ; out[3D:5D) = k2_b|v2_b
__global__ void bias_concat(const float* q1b, const float* k1b, const float* v1b,
                            const float* k2b, const float* v2b, float* out) {
    int i = blockIdx.x * 256 + threadIdx.x;
    if (i < DM)            out[i] = q1b[i];
    else if (i < 2 * DM)   out[i] = k1b[i - DM];
    else if (i < 3 * DM)   out[i] = v1b[i - 2 * DM];
    else if (i < 4 * DM)   out[i] = k2b[i - 3 * DM];
    else if (i < 5 * DM)   out[i] = v2b[i - 4 * DM];
}

// ---------------------------------------------------------------------------
// Block reduction for (sum, sumsq), blockDim.x == 256
// ---------------------------------------------------------------------------
__device__ __forceinline__ void block_reduce_2(float& s, float& q) {
    __shared__ float sh_s[8], sh_q[8];
    int lane = threadIdx.x & 31, w = threadIdx.x >> 5;
#pragma unroll
    for (int o = 16; o > 0; o >>= 1) {
        s += __shfl_down_sync(0xffffffffu, s, o);
        q += __shfl_down_sync(0xffffffffu, q, o);
    }
    if (lane == 0) { sh_s[w] = s; sh_q[w] = q; }
    __syncthreads();
    if (w == 0) {
        s = (lane < 8) ? sh_s[lane] : 0.f;
        q = (lane < 8) ? sh_q[lane] : 0.f;
#pragma unroll
        for (int o = 4; o > 0; o >>= 1) {
            s += __shfl_down_sync(0xffffffffu, s, o);
            q += __shfl_down_sync(0xffffffffu, q, o);
        }
        if (lane == 0) { sh_s[0] = s; sh_q[0] = q; }
    }
    __syncthreads();
    s = sh_s[0]; q = sh_q[0];
}

// ---------------------------------------------------------------------------
// Embedding gather + positional + LayerNorm; exact + rounded outputs
// ---------------------------------------------------------------------------
__global__ void embed_ln_kernel(const int* __restrict__ tgt_ids,
                                const float* __restrict__ tok_emb,
                                const float* __restrict__ pos_emb,
                                const float* __restrict__ gam,
                                const float* __restrict__ bet,
                                float* __restrict__ out,
                                float* __restrict__ out_r) {
    int row = blockIdx.x;
    int s   = row & (SS - 1);
    int tok = tgt_ids[row];
    const float* te = tok_emb + (size_t)tok * DM;
    const float* pe = pos_emb + (size_t)s   * DM;
    float v[4]; float sum = 0.f, sq = 0.f;
#pragma unroll
    for (int i = 0; i < 4; i++) {
        int c = threadIdx.x + i * 256;
        float x = te[c] + pe[c];
        v[i] = x; sum += x; sq += x * x;
    }
    block_reduce_2(sum, sq);
    float mu  = sum * (1.f / DM);
    float var = sq * (1.f / DM) - mu * mu;
    float rs  = rsqrtf(var + 1e-5f);
    float* o   = out   + (size_t)row * DM;
    float* orr = out_r + (size_t)row * DM;
#pragma unroll
    for (int i = 0; i < 4; i++) {
        int c = threadIdx.x + i * 256;
        float y = (v[i] - mu) * rs * gam[c] + bet[c];
        o[c] = y;
        orr[c] = tf32r(y);
    }
}

// ---------------------------------------------------------------------------
// LayerNorm; exact + rounded outputs
// ---------------------------------------------------------------------------
__global__ void ln_kernel(const float* __restrict__ in,
                          const float* __restrict__ gam,
                          const float* __restrict__ bet,
                          float* __restrict__ out,
                          float* __restrict__ out_r) {
    int row = blockIdx.x;
    const float* ip = in + (size_t)row * DM;
    float v[4]; float sum = 0.f, sq = 0.f;
#pragma unroll
    for (int i = 0; i < 4; i++) {
        int c = threadIdx.x + i * 256;
        float x = ip[c];
        v[i] = x; sum += x; sq += x * x;
    }
    block_reduce_2(sum, sq);
    float mu  = sum * (1.f / DM);
    float var = sq * (1.f / DM) - mu * mu;
    float rs  = rsqrtf(var + 1e-5f);
    float* o   = out   + (size_t)row * DM;
    float* orr = out_r + (size_t)row * DM;
#pragma unroll
    for (int i = 0; i < 4; i++) {
        int c = threadIdx.x + i * 256;
        float y = (v[i] - mu) * rs * gam[c] + bet[c];
        o[c] = y;
        orr[c] = tf32r(y);
    }
}

// ---------------------------------------------------------------------------
// TF32 mma.sync GEMM v5: 128x128 CTA tile, 128 threads (4 warps, 64x64 each),
// BK=32, 3-stage cp.async pipeline, ONE __syncthreads per iteration.
// Operands pre-rounded in gmem.
// ---------------------------------------------------------------------------
#define BKT    32
#define NSTG   3
#define ASPAD  36
#define BSPAD  132
#define A_STAGE (128 * ASPAD)
#define B_STAGE (BKT * BSPAD)
#define STAGE_F (A_STAGE + B_STAGE)
#define GEMM_SMEM_BYTES (NSTG * STAGE_F * 4)   // ~106 KB

__global__ __launch_bounds__(128) void gemm_mma(
    const float* __restrict__ A, const float* __restrict__ W,
    const float* __restrict__ bias, const float* __restrict__ res,
    float* __restrict__ C, int M, int N, int K, int gelu, int round_out) {
    extern __shared__ float sm[];
    uint32_t sbase = smem_u32(sm);

    int tid  = threadIdx.x;
    int wid  = tid >> 5, lane = tid & 31;
    int gid  = lane >> 2, tig = lane & 3;
    int m_off = (wid >> 1) * 64;
    int n_off = (wid & 1) * 64;
    int bm = blockIdx.y * 128, bn = blockIdx.x * 128;

    // per-thread load coordinates
    int ar = tid >> 3, ac4 = (tid & 7) * 4;      // A: 16 rows per pass? (128 th: r=tid/8 0..15? no)
    // A: 128 rows x 8 float4-cols = 1024 float4s, 128 threads x 8 iters
    // B: 32 rows x 32 float4-cols = 1024 float4s

    float acc[4][8][4];
#pragma unroll
    for (int i = 0; i < 4; i++)
#pragma unroll
        for (int j = 0; j < 8; j++)
#pragma unroll
            for (int k = 0; k < 4; k++) acc[i][j][k] = 0.f;

    const int T = K / BKT;

    // issue loads for stage s (k-tile kt)
    auto issue = [&](int s, int kt) {
        uint32_t aU = sbase + (uint32_t)(s * STAGE_F) * 4;
        uint32_t bU = aU + (uint32_t)A_STAGE * 4;
        int k0 = kt * BKT;
#pragma unroll
        for (int i = 0; i < 8; i++) {
            int idx = tid + i * 128;
            int r = idx >> 3, c4 = idx & 7;
            cp16(aU + (uint32_t)(r * ASPAD + c4 * 4) * 4,
                 A + (size_t)(bm + r) * K + k0 + c4 * 4);
        }
#pragma unroll
        for (int i = 0; i < 8; i++) {
            int idx = tid + i * 128;
            int r = idx >> 5, c4 = idx & 31;
            cp16(bU + (uint32_t)(r * BSPAD + c4 * 4) * 4,
                 W + (size_t)(k0 + r) * N + bn + c4 * 4);
        }
        CP_COMMIT();
    };

    // prologue: stages 0..NSTG-2
    issue(0, 0);
    issue(1, 1);

    for (int t = 0; t < T; t++) {
        int cur = t % NSTG;
        CP_WAIT(NSTG - 2);         // stage t's group complete (this thread)
        __syncthreads();           // make it visible to all warps
        if (t + NSTG - 1 < T)
            issue((t + NSTG - 1) % NSTG, t + NSTG - 1);

        const uint32_t* Ac = (const uint32_t*)(sm + cur * STAGE_F);
        const uint32_t* Bc = Ac + A_STAGE;
#pragma unroll
        for (int ks = 0; ks < 4; ks++) {
            int k = ks * 8;
            uint32_t a[4][4], b[8][2];
#pragma unroll
            for (int mf = 0; mf < 4; mf++) {
                const uint32_t* p = Ac + (m_off + mf * 16 + gid) * ASPAD + k + tig;
                a[mf][0] = p[0];
                a[mf][1] = p[8 * ASPAD];
                a[mf][2] = p[4];
                a[mf][3] = p[8 * ASPAD + 4];
            }
#pragma unroll
            for (int nf = 0; nf < 8; nf++) {
                const uint32_t* p = Bc + (k + tig) * BSPAD + n_off + nf * 8 + gid;
                b[nf][0] = p[0];
                b[nf][1] = p[4 * BSPAD];
            }
#pragma unroll
            for (int mf = 0; mf < 4; mf++)
#pragma unroll
                for (int nf = 0; nf < 8; nf++)
                    mma_tf32(acc[mf][nf], a[mf], b[nf]);
        }
        // no trailing barrier: next iteration's barrier protects buffer reuse
    }

#pragma unroll
    for (int mf = 0; mf < 4; mf++) {
        int row0 = bm + m_off + mf * 16 + gid;
        int row1 = row0 + 8;
#pragma unroll
        for (int nf = 0; nf < 8; nf++) {
            int col = bn + n_off + nf * 8 + 2 * tig;
            float b0 = bias[col], b1 = bias[col + 1];
            float v0 = acc[mf][nf][0] + b0;
            float v1 = acc[mf][nf][1] + b1;
            float v2 = acc[mf][nf][2] + b0;
            float v3 = acc[mf][nf][3] + b1;
            if (res) {
                v0 += res[(size_t)row0 * N + col];
                v1 += res[(size_t)row0 * N + col + 1];
                v2 += res[(size_t)row1 * N + col];
                v3 += res[(size_t)row1 * N + col + 1];
            }
            if (gelu) {
                v0 = 0.5f * v0 * (1.0f + erff(v0 * 0.70710678118654752f));
                v1 = 0.5f * v1 * (1.0f + erff(v1 * 0.70710678118654752f));
                v2 = 0.5f * v2 * (1.0f + erff(v2 * 0.70710678118654752f));
                v3 = 0.5f * v3 * (1.0f + erff(v3 * 0.70710678118654752f));
            }
            if (round_out) {
                v0 = tf32r(v0); v1 = tf32r(v1);
                v2 = tf32r(v2); v3 = tf32r(v3);
            }
            *(float2*)(C + (size_t)row0 * N + col) = make_float2(v0, v1);
            *(float2*)(C + (size_t)row1 * N + col) = make_float2(v2, v3);
        }
    }
}

// ---------------------------------------------------------------------------
// Tensor-core flash attention (tf32). Inputs pre-rounded.
// stq / stkv: row strides of Q and K/V buffers (packed layouts supported).
// ---------------------------------------------------------------------------
#define APAD 68
#define ATTN_SMEM_BYTES ((3 * 64 * APAD + 64) * 4)

__global__ __launch_bounds__(128) void attn_tc(
    const float* __restrict__ Q, const float* __restrict__ Kb,
    const float* __restrict__ Vb, const int* __restrict__ ids,
    float* __restrict__ O, int causal, int stq, int stkv) {
    extern __shared__ float sm[];
    float* Ks = sm;
    float* Vt = sm + 64 * APAD;
    float* Ps = sm + 2 * 64 * APAD;
    float* pm = sm + 3 * 64 * APAD;

    int b   = blockIdx.y >> 4;
    int h   = blockIdx.y & 15;
    int q0  = blockIdx.x * 64;
    int tid = threadIdx.x;
    int wid = tid >> 5, lane = tid & 31;
    int gid = lane >> 2, tig = lane & 3;
    int lrow = wid * 16 + gid;
    int grow = q0 + lrow;

    float qf[8][4];
    const float* qb0 = Q + ((size_t)(b * SS + grow)) * stq + h * DHD;
    const float* qb8 = qb0 + (size_t)8 * stq;
#pragma unroll
    for (int ks = 0; ks < 8; ks++) {
        qf[ks][0] = qb0[ks * 8 + tig];
        qf[ks][1] = qb8[ks * 8 + tig];
        qf[ks][2] = qb0[ks * 8 + tig + 4];
        qf[ks][3] = qb8[ks * 8 + tig + 4];
    }

    float of[8][4];
#pragma unroll
    for (int i = 0; i < 8; i++)
#pragma unroll
        for (int j = 0; j < 4; j++) of[i][j] = 0.f;
    float m0 = -1e30f, m1 = -1e30f, l0 = 0.f, l1 = 0.f;

    int ntiles = causal ? (blockIdx.x + 1) : (SS / 64);
    for (int t = 0; t < ntiles; t++) {
        int kbase = t * 64;
#pragma unroll
        for (int i = 0; i < 8; i++) {
            int e  = tid + i * 128;
            int r  = e >> 4, c4 = (e & 15) * 4;
            size_t goff = ((size_t)(b * SS + kbase + r)) * stkv + h * DHD + c4;
            float4 kv = *(const float4*)(Kb + goff);
            float4 vv = *(const float4*)(Vb + goff);
            *(float4*)(Ks + r * APAD + c4) = kv;
            Vt[(c4 + 0) * APAD + r] = vv.x;
            Vt[(c4 + 1) * APAD + r] = vv.y;
            Vt[(c4 + 2) * APAD + r] = vv.z;
            Vt[(c4 + 3) * APAD + r] = vv.w;
        }
        if (tid < 64)
            pm[tid] = (ids[b * SS + kbase + tid] == 0) ? NEGBIG : 0.f;
        __syncthreads();

        float sf[8][4];
#pragma unroll
        for (int nf = 0; nf < 8; nf++) {
            sf[nf][0] = 0.f; sf[nf][1] = 0.f; sf[nf][2] = 0.f; sf[nf][3] = 0.f;
#pragma unroll
            for (int ks = 0; ks < 8; ks++) {
                uint32_t bf[2];
                const float* p = Ks + (nf * 8 + gid) * APAD + ks * 8 + tig;
                bf[0] = __float_as_uint(p[0]);
                bf[1] = __float_as_uint(p[4]);
                mma_tf32(sf[nf], (const uint32_t*)qf[ks], bf);
            }
        }

        float tmax0 = -1e30f, tmax1 = -1e30f;
#pragma unroll
        for (int nf = 0; nf < 8; nf++) {
            int lc0 = nf * 8 + 2 * tig, lc1 = lc0 + 1;
            float s0 = sf[nf][0] * 0.125f + pm[lc0];
            float s1 = sf[nf][1] * 0.125f + pm[lc1];
            float s2 = sf[nf][2] * 0.125f + pm[lc0];
            float s3 = sf[nf][3] * 0.125f + pm[lc1];
            if (causal) {
                int g0 = kbase + lc0, g1 = kbase + lc1;
                if (g0 > grow)     s0 = -1e30f;
                if (g1 > grow)     s1 = -1e30f;
                if (g0 > grow + 8) s2 = -1e30f;
                if (g1 > grow + 8) s3 = -1e30f;
            }
            sf[nf][0] = s0; sf[nf][1] = s1; sf[nf][2] = s2; sf[nf][3] = s3;
            tmax0 = fmaxf(tmax0, fmaxf(s0, s1));
            tmax1 = fmaxf(tmax1, fmaxf(s2, s3));
        }
        tmax0 = fmaxf(tmax0, __shfl_xor_sync(0xffffffffu, tmax0, 1));
        tmax0 = fmaxf(tmax0, __shfl_xor_sync(0xffffffffu, tmax0, 2));
        tmax1 = fmaxf(tmax1, __shfl_xor_sync(0xffffffffu, tmax1, 1));
        tmax1 = fmaxf(tmax1, __shfl_xor_sync(0xffffffffu, tmax1, 2));

        float nm0 = fmaxf(m0, tmax0), nm1 = fmaxf(m1, tmax1);
        float sc0 = __expf(m0 - nm0), sc1 = __expf(m1 - nm1);
        m0 = nm0; m1 = nm1;

        float ts0 = 0.f, ts1 = 0.f;
        float* pr0 = Ps + lrow * APAD;
        float* pr1 = Ps + (lrow + 8) * APAD;
#pragma unroll
        for (int nf = 0; nf < 8; nf++) {
            int lc0 = nf * 8 + 2 * tig;
            float p0 = __expf(sf[nf][0] - nm0);
            float p1 = __expf(sf[nf][1] - nm0);
            float p2 = __expf(sf[nf][2] - nm1);
            float p3 = __expf(sf[nf][3] - nm1);
            ts0 += p0 + p1; ts1 += p2 + p3;
            pr0[lc0]     = tf32r(p0);
            pr0[lc0 + 1] = tf32r(p1);
            pr1[lc0]     = tf32r(p2);
            pr1[lc0 + 1] = tf32r(p3);
            of[nf][0] *= sc0; of[nf][1] *= sc0;
            of[nf][2] *= sc1; of[nf][3] *= sc1;
        }
        ts0 += __shfl_xor_sync(0xffffffffu, ts0, 1);
        ts0 += __shfl_xor_sync(0xffffffffu, ts0, 2);
        ts1 += __shfl_xor_sync(0xffffffffu, ts1, 1);
        ts1 += __shfl_xor_sync(0xffffffffu, ts1, 2);
        l0 = l0 * sc0 + ts0;
        l1 = l1 * sc1 + ts1;
        __syncwarp();

#pragma unroll
        for (int ks = 0; ks < 8; ks++) {
            uint32_t af[4];
            af[0] = __float_as_uint(pr0[ks * 8 + tig]);
            af[1] = __float_as_uint(pr1[ks * 8 + tig]);
            af[2] = __float_as_uint(pr0[ks * 8 + tig + 4]);
            af[3] = __float_as_uint(pr1[ks * 8 + tig + 4]);
#pragma unroll
            for (int nf = 0; nf < 8; nf++) {
                uint32_t bf[2];
                const float* p = Vt + (nf * 8 + gid) * APAD + ks * 8 + tig;
                bf[0] = __float_as_uint(p[0]);
                bf[1] = __float_as_uint(p[4]);
                mma_tf32(of[nf], af, bf);
            }
        }
        __syncthreads();
    }

    float inv0 = 1.f / l0, inv1 = 1.f / l1;
    float* ob0 = O + ((size_t)(b * SS + grow)) * DM + h * DHD;
    float* ob8 = ob0 + 8 * DM;
#pragma unroll
    for (int nf = 0; nf < 8; nf++) {
        int col = nf * 8 + 2 * tig;
        *(float2*)(ob0 + col) = make_float2(tf32r(of[nf][0] * inv0),
                                            tf32r(of[nf][1] * inv0));
        *(float2*)(ob8 + col) = make_float2(tf32r(of[nf][2] * inv1),
                                            tf32r(of[nf][3] * inv1));
    }
}

// ---------------------------------------------------------------------------
// Launch
// ---------------------------------------------------------------------------
extern "C" void kernel_launch(void* const* d_in, const int* in_sizes, int n_in,
                              void* d_out, int out_size) {
    const float* input_embedding = (const float*)d_in[0];
    const int*   input_ids       = (const int*)d_in[1];
    const int*   target_ids      = (const int*)d_in[2];
    const float* tok_emb = (const float*)d_in[3];
    const float* pos_emb = (const float*)d_in[4];
    const float* ln1_g = (const float*)d_in[5];
    const float* ln1_b = (const float*)d_in[6];
    const float* q1_w = (const float*)d_in[7];
    const float* q1_b = (const float*)d_in[8];
    const float* k1_w = (const float*)d_in[9];
    const float* k1_b = (const float*)d_in[10];
    const float* v1_w = (const float*)d_in[11];
    const float* v1_b = (const float*)d_in[12];
    const float* out1_w = (const float*)d_in[13];
    const float* out1_b = (const float*)d_in[14];
    const float* ln2_g = (const float*)d_in[15];
    const float* ln2_b = (const float*)d_in[16];
    const float* q2_w = (const float*)d_in[17];
    const float* q2_b = (const float*)d_in[18];
    const float* k2_w = (const float*)d_in[19];
    const float* k2_b = (const float*)d_in[20];
    const float* v2_w = (const float*)d_in[21];
    const float* v2_b = (const float*)d_in[22];
    const float* out2_w = (const float*)d_in[23];
    const float* out2_b = (const float*)d_in[24];
    const float* ln3_g = (const float*)d_in[25];
    const float* ln3_b = (const float*)d_in[26];
    const float* mlp_w1 = (const float*)d_in[27];
    const float* mlp_b1 = (const float*)d_in[28];
    const float* mlp_w2 = (const float*)d_in[29];
    const float* mlp_b2 = (const float*)d_in[30];
    float* out = (float*)d_out;

    static float *X = nullptr, *XR = nullptr, *ER = nullptr,
                 *QKV = nullptr, *KV = nullptr, *Qb = nullptr,
                 *ATT = nullptr, *H = nullptr, *HID = nullptr,
                 *WT = nullptr, *BI = nullptr;
    static bool attr_done = false;
    if (!X) {
        cudaGetSymbolAddress((void**)&X,   g_X);
        cudaGetSymbolAddress((void**)&XR,  g_XR);
        cudaGetSymbolAddress((void**)&ER,  g_ER);
        cudaGetSymbolAddress((void**)&QKV, g_QKV);
        cudaGetSymbolAddress((void**)&KV,  g_KV);
        cudaGetSymbolAddress((void**)&Qb,  g_Q);
        cudaGetSymbolAddress((void**)&ATT, g_ATT);
        cudaGetSymbolAddress((void**)&H,   g_H);
        cudaGetSymbolAddress((void**)&HID, g_HID);
        cudaGetSymbolAddress((void**)&WT,  g_WT);
        cudaGetSymbolAddress((void**)&BI,  g_BI);
    }
    if (!attr_done) {
        cudaFuncSetAttribute(gemm_mma, cudaFuncAttributeMaxDynamicSharedMemorySize,
                             GEMM_SMEM_BYTES);
        cudaFuncSetAttribute(attn_tc, cudaFuncAttributeMaxDynamicSharedMemorySize,
                             ATTN_SMEM_BYTES);
        attr_done = true;
    }

    const size_t MW = 1024 * 1024;
    float* wr_qkv = WT + 0 * MW;    // [DM][3*DM]
    float* wr_kv2 = WT + 3 * MW;    // [DM][2*DM]
    float* wr_q2  = WT + 5 * MW;
    float* wr_o1  = WT + 6 * MW;
    float* wr_o2  = WT + 7 * MW;
    float* wr_m1  = WT + 8 * MW;
    float* wr_m2  = WT + 12 * MW;
    float* bqkv   = BI;
    float* bkv2   = BI + 3 * DM;

    const int N4 = (int)(MW / 4);
    const int GB = N4 / 256;
    round_concat<<<GB, 256>>>(q1_w, wr_qkv, N4, DM, 3 * DM, 0);
    round_concat<<<GB, 256>>>(k1_w, wr_qkv, N4, DM, 3 * DM, DM);
    round_concat<<<GB, 256>>>(v1_w, wr_qkv, N4, DM, 3 * DM, 2 * DM);
    round_concat<<<GB, 256>>>(k2_w, wr_kv2, N4, DM, 2 * DM, 0);
    round_concat<<<GB, 256>>>(v2_w, wr_kv2, N4, DM, 2 * DM, DM);
    round_concat<<<GB, 256>>>(q2_w,  wr_q2, N4, DM, DM, 0);
    round_concat<<<GB, 256>>>(out1_w, wr_o1, N4, DM, DM, 0);
    round_concat<<<GB, 256>>>(out2_w, wr_o2, N4, DM, DM, 0);
    round_concat<<<4 * GB, 256>>>(mlp_w1, wr_m1, 4 * N4, DFF, DFF, 0);
    round_concat<<<4 * GB, 256>>>(mlp_w2, wr_m2, 4 * N4, DM, DM, 0);
    round_concat<<<4 * GB, 256>>>(input_embedding, ER, 4 * N4, DM, DM, 0);
    bias_concat<<<20, 256>>>(q1_b, k1_b, v1_b, k2_b, v2_b, BI);

    dim3 gQKV(3 * DM / 128, MTOK / 128);   // (24, 32)
    dim3 gKV (2 * DM / 128, MTOK / 128);   // (16, 32)
    dim3 gProj(DM / 128, MTOK / 128);      // (8, 32)
    dim3 gMlp1(DFF / 128, MTOK / 128);     // (32, 32)
    dim3 gAttn(SS / 64, BB * HH);          // (32, 32)
    const int SB = GEMM_SMEM_BYTES;
    const int AB = ATTN_SMEM_BYTES;

    // 1. embedding + LN1 -> X, XR
    embed_ln_kernel<<<MTOK, 256>>>(target_ids, tok_emb, pos_emb, ln1_g, ln1_b, X, XR);
    // 2. fused QKV projection (rounded out)
    gemm_mma<<<gQKV, 128, SB>>>(XR, wr_qkv, bqkv, nullptr, QKV, MTOK, 3 * DM, DM, 0, 1);
    // 3. causal self-attention (packed QKV, stride 3*DM)
    attn_tc<<<gAttn, 128, AB>>>(QKV, QKV + DM, QKV + 2 * DM, target_ids, ATT, 1,
                                3 * DM, 3 * DM);
    // 4. out projection + residual (X) -> H
    gemm_mma<<<gProj, 128, SB>>>(ATT, wr_o1, out1_b, X, H, MTOK, DM, DM, 0, 0);
    // 5. LN2 -> X, XR
    ln_kernel<<<MTOK, 256>>>(H, ln2_g, ln2_b, X, XR);
    // 6. cross-attn projections: Q2 (from XR), fused KV2 (from ER)
    gemm_mma<<<gProj, 128, SB>>>(XR, wr_q2, q2_b, nullptr, Qb, MTOK, DM, DM, 0, 1);
    gemm_mma<<<gKV, 128, SB>>>(ER, wr_kv2, bkv2, nullptr, KV, MTOK, 2 * DM, DM, 0, 1);
    // 7. cross-attention (Q stride DM, KV stride 2*DM)
    attn_tc<<<gAttn, 128, AB>>>(Qb, KV, KV + DM, input_ids, ATT, 0, DM, 2 * DM);
    // 8. out projection + residual (X = LN2 out) -> H
    gemm_mma<<<gProj, 128, SB>>>(ATT, wr_o2, out2_b, X, H, MTOK, DM, DM, 0, 0);
    // 9. LN3 -> X, XR
    ln_kernel<<<MTOK, 256>>>(H, ln3_g, ln3_b, X, XR);
    // 10. MLP up + GELU -> HID (rounded)
    gemm_mma<<<gMlp1, 128, SB>>>(XR, wr_m1, mlp_b1, nullptr, HID, MTOK, DFF, DM, 1, 1);
    // 11. MLP down + bias + residual (H) -> out
    gemm_mma<<<gProj, 128, SB>>>(HID, wr_m2, mlp_b2, H, out, MTOK, DM, DFF, 0, 0);
}

// round 13
// speedup vs baseline: 5.8615x; 1.6765x over previous
#include <cuda_runtime.h>
#include <cuda_fp16.h>
#include <math.h>
#include <stdint.h>

// ---------------------------------------------------------------------------
// Problem constants
// ---------------------------------------------------------------------------
#define BB    2
#define SS    2048
#define DM    1024
#define HH    16
#define DHD   64
#define MTOK  (BB*SS)          // 4096 token rows
#define DFF   4096
#define NEGBIG (-1000000000.0f)

// ---------------------------------------------------------------------------
// Scratch (static device globals; no allocations allowed)
// ---------------------------------------------------------------------------
__device__ float  g_X  [MTOK*DM];             // LN out, exact (residuals)
__device__ __half g_XR [MTOK*DM];             // LN out, fp16 (GEMM A)
__device__ __half g_ER [MTOK*DM];             // input_embedding, fp16
__device__ __half g_QKV[(size_t)MTOK*3*DM];   // packed Q|K|V (self-attn)
__device__ __half g_KV [(size_t)MTOK*2*DM];   // packed K|V (cross-attn)
__device__ __half g_Q  [MTOK*DM];             // Q2
__device__ __half g_ATT[MTOK*DM];             // attention out (fp16)
__device__ float  g_H  [MTOK*DM];             // residual stream, exact
__device__ __half g_HID[(size_t)MTOK*DFF];    // MLP hidden (fp16)
__device__ __half g_WTh[16*1024*1024];        // fp16 weights, K-major [N][K]
__device__ float  g_BI [3*DM + 2*DM];         // concat biases qkv1, kv2

// ---------------------------------------------------------------------------
// Helpers
// ---------------------------------------------------------------------------
__device__ __forceinline__ uint32_t h2_u32(__half2 h) {
    return *(uint32_t*)&h;
}

__device__ __forceinline__ void mma_f16(float* d, const uint32_t* a,
                                        const uint32_t* b) {
    asm volatile(
        "mma.sync.aligned.m16n8k16.row.col.f32.f16.f16.f32 "
        "{%0,%1,%2,%3}, {%4,%5,%6,%7}, {%8,%9}, {%0,%1,%2,%3};"
        : "+f"(d[0]), "+f"(d[1]), "+f"(d[2]), "+f"(d[3])
        : "r"(a[0]), "r"(a[1]), "r"(a[2]), "r"(a[3]), "r"(b[0]), "r"(b[1]));
}

__device__ __forceinline__ uint32_t smem_u32(const void* p) {
    uint32_t a;
    asm("{ .reg .u64 t; cvta.to.shared.u64 t, %1; cvt.u32.u64 %0, t; }"
        : "=r"(a) : "l"(p));
    return a;
}
__device__ __forceinline__ void cp16(uint32_t dst, const void* src) {
    asm volatile("cp.async.cg.shared.global [%0], [%1], 16;"
                 :: "r"(dst), "l"(src));
}
#define CP_COMMIT() asm volatile("cp.async.commit_group;" ::: "memory")
#define CP_WAIT(n)  asm volatile("cp.async.wait_group %0;" :: "n"(n) : "memory")

// ---------------------------------------------------------------------------
// Weight transpose + fp16 convert: in fp32 [R][C] -> out half [C][R] (+obase)
// ---------------------------------------------------------------------------
__global__ void trans_h(const float* __restrict__ in, __half* __restrict__ out,
                        int R, int C, int obase) {
    __shared__ float tile[32][33];
    int cx = blockIdx.x * 32, ry = blockIdx.y * 32;
    int tx = threadIdx.x, ty = threadIdx.y;
#pragma unroll
    for (int i = 0; i < 32; i += 8)
        tile[ty + i][tx] = in[(size_t)(ry + ty + i) * C + cx + tx];
    __syncthreads();
#pragma unroll
    for (int i = 0; i < 32; i += 8)
        out[(size_t)(obase + cx + ty + i) * R + ry + tx] =
            __float2half_rn(tile[tx][ty + i]);
}

// elementwise fp32 -> fp16
__global__ void round_h(const float* __restrict__ in, __half* __restrict__ out,
                        int n4) {
    int i = blockIdx.x * 256 + threadIdx.x;
    if (i < n4) {
        float4 v = ((const float4*)in)[i];
        uint2 o;
        o.x = h2_u32(__floats2half2_rn(v.x, v.y));
        o.y = h2_u32(__floats2half2_rn(v.z, v.w));
        ((uint2*)out)[i] = o;
    }
}

// concat biases: out[0:3D) = q1_b|k1_b|v1_b ; out[3D:5D) = k2_b|v2_b
__global__ void bias_concat(const float* q1b, const float* k1b, const float* v1b,
                            const float* k2b, const float* v2b, float* out) {
    int i = blockIdx.x * 256 + threadIdx.x;
    if (i < DM)            out[i] = q1b[i];
    else if (i < 2 * DM)   out[i] = k1b[i - DM];
    else if (i < 3 * DM)   out[i] = v1b[i - 2 * DM];
    else if (i < 4 * DM)   out[i] = k2b[i - 3 * DM];
    else if (i < 5 * DM)   out[i] = v2b[i - 4 * DM];
}

// ---------------------------------------------------------------------------
// Block reduction for (sum, sumsq), blockDim.x == 256
// ---------------------------------------------------------------------------
__device__ __forceinline__ void block_reduce_2(float& s, float& q) {
    __shared__ float sh_s[8], sh_q[8];
    int lane = threadIdx.x & 31, w = threadIdx.x >> 5;
#pragma unroll
    for (int o = 16; o > 0; o >>= 1) {
        s += __shfl_down_sync(0xffffffffu, s, o);
        q += __shfl_down_sync(0xffffffffu, q, o);
    }
    if (lane == 0) { sh_s[w] = s; sh_q[w] = q; }
    __syncthreads();
    if (w == 0) {
        s = (lane < 8) ? sh_s[lane] : 0.f;
        q = (lane < 8) ? sh_q[lane] : 0.f;
#pragma unroll
        for (int o = 4; o > 0; o >>= 1) {
            s += __shfl_down_sync(0xffffffffu, s, o);
            q += __shfl_down_sync(0xffffffffu, q, o);
        }
        if (lane == 0) { sh_s[0] = s; sh_q[0] = q; }
    }
    __syncthreads();
    s = sh_s[0]; q = sh_q[0];
}

// ---------------------------------------------------------------------------
// Embedding gather + positional + LayerNorm; exact fp32 + fp16 outputs
// ---------------------------------------------------------------------------
__global__ void embed_ln_kernel(const int* __restrict__ tgt_ids,
                                const float* __restrict__ tok_emb,
                                const float* __restrict__ pos_emb,
                                const float* __restrict__ gam,
                                const float* __restrict__ bet,
                                float* __restrict__ out,
                                __half* __restrict__ out_r) {
    int row = blockIdx.x;
    int s   = row & (SS - 1);
    int tok = tgt_ids[row];
    const float* te = tok_emb + (size_t)tok * DM;
    const float* pe = pos_emb + (size_t)s   * DM;
    float v[4]; float sum = 0.f, sq = 0.f;
#pragma unroll
    for (int i = 0; i < 4; i++) {
        int c = threadIdx.x + i * 256;
        float x = te[c] + pe[c];
        v[i] = x; sum += x; sq += x * x;
    }
    block_reduce_2(sum, sq);
    float mu  = sum * (1.f / DM);
    float var = sq * (1.f / DM) - mu * mu;
    float rs  = rsqrtf(var + 1e-5f);
    float*  o   = out   + (size_t)row * DM;
    __half* orr = out_r + (size_t)row * DM;
#pragma unroll
    for (int i = 0; i < 4; i++) {
        int c = threadIdx.x + i * 256;
        float y = (v[i] - mu) * rs * gam[c] + bet[c];
        o[c] = y;
        orr[c] = __float2half_rn(y);
    }
}

// ---------------------------------------------------------------------------
// LayerNorm; exact fp32 + fp16 outputs
// ---------------------------------------------------------------------------
__global__ void ln_kernel(const float* __restrict__ in,
                          const float* __restrict__ gam,
                          const float* __restrict__ bet,
                          float* __restrict__ out,
                          __half* __restrict__ out_r) {
    int row = blockIdx.x;
    const float* ip = in + (size_t)row * DM;
    float v[4]; float sum = 0.f, sq = 0.f;
#pragma unroll
    for (int i = 0; i < 4; i++) {
        int c = threadIdx.x + i * 256;
        float x = ip[c];
        v[i] = x; sum += x; sq += x * x;
    }
    block_reduce_2(sum, sq);
    float mu  = sum * (1.f / DM);
    float var = sq * (1.f / DM) - mu * mu;
    float rs  = rsqrtf(var + 1e-5f);
    float*  o   = out   + (size_t)row * DM;
    __half* orr = out_r + (size_t)row * DM;
#pragma unroll
    for (int i = 0; i < 4; i++) {
        int c = threadIdx.x + i * 256;
        float y = (v[i] - mu) * rs * gam[c] + bet[c];
        o[c] = y;
        orr[c] = __float2half_rn(y);
    }
}

// ---------------------------------------------------------------------------
// FP16 mma.sync GEMM: C[M,N] = A[M,K] @ W^T (W stored [N][K] half) + bias
// (+res fp32) (gelu opt). 128x128 CTA tile, 128 threads (4 warps, 64x64),
// BK=64 (4 k-steps of m16n8k16), 3-stage cp.async pipeline.
// C written as half (out_half=1) or float.
// ---------------------------------------------------------------------------
#define BKH    64
#define PADH   72                              // halfs per smem row
#define TILE_H (128 * PADH)                    // halfs per operand
#define STAGE_H (2 * TILE_H)                   // halfs per stage
#define GEMM_SMEM_BYTES (3 * STAGE_H * 2)      // 110592 B

__global__ __launch_bounds__(128) void gemm_h(
    const __half* __restrict__ A, const __half* __restrict__ W,
    const float* __restrict__ bias, const float* __restrict__ res,
    void* __restrict__ Cout, int M, int N, int K, int gelu, int out_half) {
    extern __shared__ __half smh[];
    uint32_t sbase = smem_u32(smh);

    int tid  = threadIdx.x;
    int wid  = tid >> 5, lane = tid & 31;
    int gid  = lane >> 2, tig = lane & 3;
    int m_off = (wid >> 1) * 64;
    int n_off = (wid & 1) * 64;
    int bm = blockIdx.y * 128, bn = blockIdx.x * 128;

    float acc[4][8][4];
#pragma unroll
    for (int i = 0; i < 4; i++)
#pragma unroll
        for (int j = 0; j < 8; j++)
#pragma unroll
            for (int k = 0; k < 4; k++) acc[i][j][k] = 0.f;

    const int T = K / BKH;

    auto issue = [&](int s, int kt) {
        uint32_t aU = sbase + (uint32_t)(s * STAGE_H) * 2;
        uint32_t bU = aU + (uint32_t)TILE_H * 2;
        int k0 = kt * BKH;
#pragma unroll
        for (int i = 0; i < 8; i++) {
            int idx = tid + i * 128;
            int r = idx >> 3, c8 = (idx & 7) * 8;
            cp16(aU + (uint32_t)(r * PADH + c8) * 2,
                 A + (size_t)(bm + r) * K + k0 + c8);
        }
#pragma unroll
        for (int i = 0; i < 8; i++) {
            int idx = tid + i * 128;
            int r = idx >> 3, c8 = (idx & 7) * 8;
            cp16(bU + (uint32_t)(r * PADH + c8) * 2,
                 W + (size_t)(bn + r) * K + k0 + c8);
        }
        CP_COMMIT();
    };

    issue(0, 0);
    issue(1, 1);

    for (int t = 0; t < T; t++) {
        int cur = t % 3;
        CP_WAIT(1);
        __syncthreads();
        if (t + 2 < T) issue((t + 2) % 3, t + 2);

        const __half* Ah = smh + cur * STAGE_H;
        const __half* Bh = Ah + TILE_H;
#pragma unroll
        for (int ks = 0; ks < 4; ks++) {
            int k = ks * 16;
            uint32_t a[4][4], b[8][2];
#pragma unroll
            for (int mf = 0; mf < 4; mf++) {
                const __half* p = Ah + (m_off + mf * 16 + gid) * PADH + k + 2 * tig;
                a[mf][0] = *(const uint32_t*)(p);
                a[mf][1] = *(const uint32_t*)(p + 8 * PADH);
                a[mf][2] = *(const uint32_t*)(p + 8);
                a[mf][3] = *(const uint32_t*)(p + 8 * PADH + 8);
            }
#pragma unroll
            for (int nf = 0; nf < 8; nf++) {
                const __half* p = Bh + (n_off + nf * 8 + gid) * PADH + k + 2 * tig;
                b[nf][0] = *(const uint32_t*)(p);
                b[nf][1] = *(const uint32_t*)(p + 8);
            }
#pragma unroll
            for (int mf = 0; mf < 4; mf++)
#pragma unroll
                for (int nf = 0; nf < 8; nf++)
                    mma_f16(acc[mf][nf], a[mf], b[nf]);
        }
    }

#pragma unroll
    for (int mf = 0; mf < 4; mf++) {
        int row0 = bm + m_off + mf * 16 + gid;
        int row1 = row0 + 8;
#pragma unroll
        for (int nf = 0; nf < 8; nf++) {
            int col = bn + n_off + nf * 8 + 2 * tig;
            float b0 = bias[col], b1 = bias[col + 1];
            float v0 = acc[mf][nf][0] + b0;
            float v1 = acc[mf][nf][1] + b1;
            float v2 = acc[mf][nf][2] + b0;
            float v3 = acc[mf][nf][3] + b1;
            if (res) {
                v0 += res[(size_t)row0 * N + col];
                v1 += res[(size_t)row0 * N + col + 1];
                v2 += res[(size_t)row1 * N + col];
                v3 += res[(size_t)row1 * N + col + 1];
            }
            if (gelu) {
                v0 = 0.5f * v0 * (1.0f + erff(v0 * 0.70710678118654752f));
                v1 = 0.5f * v1 * (1.0f + erff(v1 * 0.70710678118654752f));
                v2 = 0.5f * v2 * (1.0f + erff(v2 * 0.70710678118654752f));
                v3 = 0.5f * v3 * (1.0f + erff(v3 * 0.70710678118654752f));
            }
            if (out_half) {
                __half* C = (__half*)Cout;
                *(__half2*)(C + (size_t)row0 * N + col) = __floats2half2_rn(v0, v1);
                *(__half2*)(C + (size_t)row1 * N + col) = __floats2half2_rn(v2, v3);
            } else {
                float* C = (float*)Cout;
                *(float2*)(C + (size_t)row0 * N + col) = make_float2(v0, v1);
                *(float2*)(C + (size_t)row1 * N + col) = make_float2(v2, v3);
            }
        }
    }
}

// ---------------------------------------------------------------------------
// FP16 tensor-core flash attention. Q/K/V half (packed strides), O half.
// Block = 128 threads (4 warps), 64 query rows, warp owns 16.
// ---------------------------------------------------------------------------
#define AP 72
#define ATTN_SMEM_BYTES (3 * 64 * AP * 2 + 64 * 4)

__global__ __launch_bounds__(128) void attn_h(
    const __half* __restrict__ Q, const __half* __restrict__ Kb,
    const __half* __restrict__ Vb, const int* __restrict__ ids,
    __half* __restrict__ O, int causal, int stq, int stkv) {
    extern __shared__ __half smh[];
    __half* Ks = smh;                  // [64][AP]  keys x dh
    __half* Vt = smh + 64 * AP;        // [64][AP]  dh x keys
    __half* Ps = smh + 2 * 64 * AP;    // [64][AP]  q x keys
    float*  pm = (float*)(smh + 3 * 64 * AP);

    int b   = blockIdx.y >> 4;
    int h   = blockIdx.y & 15;
    int q0  = blockIdx.x * 64;
    int tid = threadIdx.x;
    int wid = tid >> 5, lane = tid & 31;
    int gid = lane >> 2, tig = lane & 3;
    int lrow = wid * 16 + gid;
    int grow = q0 + lrow;

    // Q fragments (A operand), 4 k-steps of 16 dh
    uint32_t qf[4][4];
    const __half* qb0 = Q + ((size_t)(b * SS + grow)) * stq + h * DHD;
    const __half* qb8 = qb0 + (size_t)8 * stq;
#pragma unroll
    for (int ks = 0; ks < 4; ks++) {
        int k = ks * 16 + 2 * tig;
        qf[ks][0] = *(const uint32_t*)(qb0 + k);
        qf[ks][1] = *(const uint32_t*)(qb8 + k);
        qf[ks][2] = *(const uint32_t*)(qb0 + k + 8);
        qf[ks][3] = *(const uint32_t*)(qb8 + k + 8);
    }

    float of[8][4];
#pragma unroll
    for (int i = 0; i < 8; i++)
#pragma unroll
        for (int j = 0; j < 4; j++) of[i][j] = 0.f;
    float m0 = -1e30f, m1 = -1e30f, l0 = 0.f, l1 = 0.f;

    int ntiles = causal ? (blockIdx.x + 1) : (SS / 64);
    for (int t = 0; t < ntiles; t++) {
        int kbase = t * 64;
#pragma unroll
        for (int i = 0; i < 4; i++) {
            int e  = tid + i * 128;
            int r  = e >> 3, c8 = (e & 7) * 8;
            size_t goff = ((size_t)(b * SS + kbase + r)) * stkv + h * DHD + c8;
            uint4 kv = *(const uint4*)(Kb + goff);
            uint4 vv = *(const uint4*)(Vb + goff);
            *(uint4*)(Ks + r * AP + c8) = kv;
            const __half* vh = (const __half*)&vv;
#pragma unroll
            for (int j = 0; j < 8; j++)
                Vt[(c8 + j) * AP + r] = vh[j];
        }
        if (tid < 64)
            pm[tid] = (ids[b * SS + kbase + tid] == 0) ? NEGBIG : 0.f;
        __syncthreads();

        // S = Q @ K^T
        float sf[8][4];
#pragma unroll
        for (int nf = 0; nf < 8; nf++) {
            sf[nf][0] = 0.f; sf[nf][1] = 0.f; sf[nf][2] = 0.f; sf[nf][3] = 0.f;
#pragma unroll
            for (int ks = 0; ks < 4; ks++) {
                uint32_t bf[2];
                const __half* p = Ks + (nf * 8 + gid) * AP + ks * 16 + 2 * tig;
                bf[0] = *(const uint32_t*)(p);
                bf[1] = *(const uint32_t*)(p + 8);
                mma_f16(sf[nf], qf[ks], bf);
            }
        }

        float tmax0 = -1e30f, tmax1 = -1e30f;
#pragma unroll
        for (int nf = 0; nf < 8; nf++) {
            int lc0 = nf * 8 + 2 * tig, lc1 = lc0 + 1;
            float s0 = sf[nf][0] * 0.125f + pm[lc0];
            float s1 = sf[nf][1] * 0.125f + pm[lc1];
            float s2 = sf[nf][2] * 0.125f + pm[lc0];
            float s3 = sf[nf][3] * 0.125f + pm[lc1];
            if (causal) {
                int g0 = kbase + lc0, g1 = kbase + lc1;
                if (g0 > grow)     s0 = -1e30f;
                if (g1 > grow)     s1 = -1e30f;
                if (g0 > grow + 8) s2 = -1e30f;
                if (g1 > grow + 8) s3 = -1e30f;
            }
            sf[nf][0] = s0; sf[nf][1] = s1; sf[nf][2] = s2; sf[nf][3] = s3;
            tmax0 = fmaxf(tmax0, fmaxf(s0, s1));
            tmax1 = fmaxf(tmax1, fmaxf(s2, s3));
        }
        tmax0 = fmaxf(tmax0, __shfl_xor_sync(0xffffffffu, tmax0, 1));
        tmax0 = fmaxf(tmax0, __shfl_xor_sync(0xffffffffu, tmax0, 2));
        tmax1 = fmaxf(tmax1, __shfl_xor_sync(0xffffffffu, tmax1, 1));
        tmax1 = fmaxf(tmax1, __shfl_xor_sync(0xffffffffu, tmax1, 2));

        float nm0 = fmaxf(m0, tmax0), nm1 = fmaxf(m1, tmax1);
        float sc0 = __expf(m0 - nm0), sc1 = __expf(m1 - nm1);
        m0 = nm0; m1 = nm1;

        float ts0 = 0.f, ts1 = 0.f;
        __half* pr0 = Ps + lrow * AP;
        __half* pr1 = Ps + (lrow + 8) * AP;
#pragma unroll
        for (int nf = 0; nf < 8; nf++) {
            int lc0 = nf * 8 + 2 * tig;
            float p0 = __expf(sf[nf][0] - nm0);
            float p1 = __expf(sf[nf][1] - nm0);
            float p2 = __expf(sf[nf][2] - nm1);
            float p3 = __expf(sf[nf][3] - nm1);
            ts0 += p0 + p1; ts1 += p2 + p3;
            *(__half2*)(pr0 + lc0) = __floats2half2_rn(p0, p1);
            *(__half2*)(pr1 + lc0) = __floats2half2_rn(p2, p3);
            of[nf][0] *= sc0; of[nf][1] *= sc0;
            of[nf][2] *= sc1; of[nf][3] *= sc1;
        }
        ts0 += __shfl_xor_sync(0xffffffffu, ts0, 1);
        ts0 += __shfl_xor_sync(0xffffffffu, ts0, 2);
        ts1 += __shfl_xor_sync(0xffffffffu, ts1, 1);
        ts1 += __shfl_xor_sync(0xffffffffu, ts1, 2);
        l0 = l0 * sc0 + ts0;
        l1 = l1 * sc1 + ts1;
        __syncwarp();

        // O += P @ V
#pragma unroll
        for (int ks = 0; ks < 4; ks++) {
            int kk = ks * 16 + 2 * tig;
            uint32_t af[4];
            af[0] = *(const uint32_t*)(pr0 + kk);
            af[1] = *(const uint32_t*)(pr1 + kk);
            af[2] = *(const uint32_t*)(pr0 + kk + 8);
            af[3] = *(const uint32_t*)(pr1 + kk + 8);
#pragma unroll
            for (int nf = 0; nf < 8; nf++) {
                uint32_t bf[2];
                const __half* p = Vt + (nf * 8 + gid) * AP + ks * 16 + 2 * tig;
                bf[0] = *(const uint32_t*)(p);
                bf[1] = *(const uint32_t*)(p + 8);
                mma_f16(of[nf], af, bf);
            }
        }
        __syncthreads();
    }

    float inv0 = 1.f / l0, inv1 = 1.f / l1;
    __half* ob0 = O + ((size_t)(b * SS + grow)) * DM + h * DHD;
    __half* ob8 = ob0 + (size_t)8 * DM;
#pragma unroll
    for (int nf = 0; nf < 8; nf++) {
        int col = nf * 8 + 2 * tig;
        *(__half2*)(ob0 + col) = __floats2half2_rn(of[nf][0] * inv0, of[nf][1] * inv0);
        *(__half2*)(ob8 + col) = __floats2half2_rn(of[nf][2] * inv1, of[nf][3] * inv1);
    }
}

// ---------------------------------------------------------------------------
// Launch
// ---------------------------------------------------------------------------
extern "C" void kernel_launch(void* const* d_in, const int* in_sizes, int n_in,
                              void* d_out, int out_size) {
    const float* input_embedding = (const float*)d_in[0];
    const int*   input_ids       = (const int*)d_in[1];
    const int*   target_ids      = (const int*)d_in[2];
    const float* tok_emb = (const float*)d_in[3];
    const float* pos_emb = (const float*)d_in[4];
    const float* ln1_g = (const float*)d_in[5];
    const float* ln1_b = (const float*)d_in[6];
    const float* q1_w = (const float*)d_in[7];
    const float* q1_b = (const float*)d_in[8];
    const float* k1_w = (const float*)d_in[9];
    const float* k1_b = (const float*)d_in[10];
    const float* v1_w = (const float*)d_in[11];
    const float* v1_b = (const float*)d_in[12];
    const float* out1_w = (const float*)d_in[13];
    const float* out1_b = (const float*)d_in[14];
    const float* ln2_g = (const float*)d_in[15];
    const float* ln2_b = (const float*)d_in[16];
    const float* q2_w = (const float*)d_in[17];
    const float* q2_b = (const float*)d_in[18];
    const float* k2_w = (const float*)d_in[19];
    const float* k2_b = (const float*)d_in[20];
    const float* v2_w = (const float*)d_in[21];
    const float* v2_b = (const float*)d_in[22];
    const float* out2_w = (const float*)d_in[23];
    const float* out2_b = (const float*)d_in[24];
    const float* ln3_g = (const float*)d_in[25];
    const float* ln3_b = (const float*)d_in[26];
    const float* mlp_w1 = (const float*)d_in[27];
    const float* mlp_b1 = (const float*)d_in[28];
    const float* mlp_w2 = (const float*)d_in[29];
    const float* mlp_b2 = (const float*)d_in[30];
    float* out = (float*)d_out;

    static float  *X = nullptr, *H = nullptr, *BI = nullptr;
    static __half *XR = nullptr, *ER = nullptr, *QKV = nullptr, *KV = nullptr,
                  *Qh = nullptr, *ATT = nullptr, *HID = nullptr, *WTh = nullptr;
    static bool attr_done = false;
    if (!X) {
        cudaGetSymbolAddress((void**)&X,   g_X);
        cudaGetSymbolAddress((void**)&XR,  g_XR);
        cudaGetSymbolAddress((void**)&ER,  g_ER);
        cudaGetSymbolAddress((void**)&QKV, g_QKV);
        cudaGetSymbolAddress((void**)&KV,  g_KV);
        cudaGetSymbolAddress((void**)&Qh,  g_Q);
        cudaGetSymbolAddress((void**)&ATT, g_ATT);
        cudaGetSymbolAddress((void**)&H,   g_H);
        cudaGetSymbolAddress((void**)&HID, g_HID);
        cudaGetSymbolAddress((void**)&WTh, g_WTh);
        cudaGetSymbolAddress((void**)&BI,  g_BI);
    }
    if (!attr_done) {
        cudaFuncSetAttribute(gemm_h, cudaFuncAttributeMaxDynamicSharedMemorySize,
                             GEMM_SMEM_BYTES);
        cudaFuncSetAttribute(attn_h, cudaFuncAttributeMaxDynamicSharedMemorySize,
                             ATTN_SMEM_BYTES);
        attr_done = true;
    }

    const size_t MH = 1024 * 1024;
    __half* wr_qkv = WTh + 0 * MH;    // [3072][1024]
    __half* wr_kv2 = WTh + 3 * MH;    // [2048][1024]
    __half* wr_q2  = WTh + 5 * MH;    // [1024][1024]
    __half* wr_o1  = WTh + 6 * MH;
    __half* wr_o2  = WTh + 7 * MH;
    __half* wr_m1  = WTh + 8 * MH;    // [4096][1024]
    __half* wr_m2  = WTh + 12 * MH;   // [1024][4096]
    float* bqkv = BI;
    float* bkv2 = BI + 3 * DM;

    dim3 tb(32, 8);
    dim3 tg(DM / 32, DM / 32);               // [1024][1024] weights
    trans_h<<<tg, tb>>>(q1_w,  wr_qkv, DM, DM, 0);
    trans_h<<<tg, tb>>>(k1_w,  wr_qkv, DM, DM, DM);
    trans_h<<<tg, tb>>>(v1_w,  wr_qkv, DM, DM, 2 * DM);
    trans_h<<<tg, tb>>>(k2_w,  wr_kv2, DM, DM, 0);
    trans_h<<<tg, tb>>>(v2_w,  wr_kv2, DM, DM, DM);
    trans_h<<<tg, tb>>>(q2_w,  wr_q2,  DM, DM, 0);
    trans_h<<<tg, tb>>>(out1_w, wr_o1, DM, DM, 0);
    trans_h<<<tg, tb>>>(out2_w, wr_o2, DM, DM, 0);
    dim3 tgm1(DFF / 32, DM / 32);            // mlp_w1 [1024][4096]
    trans_h<<<tgm1, tb>>>(mlp_w1, wr_m1, DM, DFF, 0);
    dim3 tgm2(DM / 32, DFF / 32);            // mlp_w2 [4096][1024]
    trans_h<<<tgm2, tb>>>(mlp_w2, wr_m2, DFF, DM, 0);
    round_h<<<(MTOK * DM / 4) / 256, 256>>>(input_embedding, ER, MTOK * DM / 4);
    bias_concat<<<20, 256>>>(q1_b, k1_b, v1_b, k2_b, v2_b, BI);

    dim3 gQKV(3 * DM / 128, MTOK / 128);   // (24, 32)
    dim3 gKV (2 * DM / 128, MTOK / 128);   // (16, 32)
    dim3 gProj(DM / 128, MTOK / 128);      // (8, 32)
    dim3 gMlp1(DFF / 128, MTOK / 128);     // (32, 32)
    dim3 gAttn(SS / 64, BB * HH);          // (32, 32)
    const int SB = GEMM_SMEM_BYTES;
    const int AB = ATTN_SMEM_BYTES;

    // 1. embedding + LN1 -> X (fp32), XR (fp16)
    embed_ln_kernel<<<MTOK, 256>>>(target_ids, tok_emb, pos_emb, ln1_g, ln1_b, X, XR);
    // 2. fused QKV projection -> QKV (fp16)
    gemm_h<<<gQKV, 128, SB>>>(XR, wr_qkv, bqkv, nullptr, QKV, MTOK, 3 * DM, DM, 0, 1);
    // 3. causal self-attention (packed QKV, stride 3*DM) -> ATT (fp16)
    attn_h<<<gAttn, 128, AB>>>(QKV, QKV + DM, QKV + 2 * DM, target_ids, ATT, 1,
                               3 * DM, 3 * DM);
    // 4. out projection + residual (X) -> H (fp32)
    gemm_h<<<gProj, 128, SB>>>(ATT, wr_o1, out1_b, X, H, MTOK, DM, DM, 0, 0);
    // 5. LN2 -> X, XR
    ln_kernel<<<MTOK, 256>>>(H, ln2_g, ln2_b, X, XR);
    // 6. cross-attn projections: Q2 (from XR), fused KV2 (from ER)
    gemm_h<<<gProj, 128, SB>>>(XR, wr_q2, q2_b, nullptr, Qh, MTOK, DM, DM, 0, 1);
    gemm_h<<<gKV, 128, SB>>>(ER, wr_kv2, bkv2, nullptr, KV, MTOK, 2 * DM, DM, 0, 1);
    // 7. cross-attention (Q stride DM, KV stride 2*DM) -> ATT (fp16)
    attn_h<<<gAttn, 128, AB>>>(Qh, KV, KV + DM, input_ids, ATT, 0, DM, 2 * DM);
    // 8. out projection + residual (X = LN2 out) -> H (fp32, "r")
    gemm_h<<<gProj, 128, SB>>>(ATT, wr_o2, out2_b, X, H, MTOK, DM, DM, 0, 0);
    // 9. LN3 -> X, XR
    ln_kernel<<<MTOK, 256>>>(H, ln3_g, ln3_b, X, XR);
    // 10. MLP up + GELU -> HID (fp16)
    gemm_h<<<gMlp1, 128, SB>>>(XR, wr_m1, mlp_b1, nullptr, HID, MTOK, DFF, DM, 1, 1);
    // 11. MLP down + bias + residual (H) -> out (fp32)
    gemm_h<<<gProj, 128, SB>>>(HID, wr_m2, mlp_b2, H, out, MTOK, DM, DFF, 0, 0);
}